// round 4
// baseline (speedup 1.0000x reference)
#include <cuda_runtime.h>
#include <cstdint>

#define S_    2048
#define HID_  2048
#define H_    16
#define D_    256
#define R_    64
#define RH_   32          // R/2
#define NOPE_ 192
#define QL_   1024
#define OR_   512
#define G_    4
#define EPS_  1e-6f
#define SCALE_ 0.0625f    // 256^-0.5

#define BM 128
#define BN 128
#define BK 32
#define GEMM_SMEM 65536   // 2 buf * (128*32 A + 128*32 B) * 4B

// ---------------- scratch (static device memory; allocation-free) ----------------
__device__ float g_cos[S_ * RH_];
__device__ float g_sin[S_ * RH_];
__device__ float g_qa[(size_t)S_ * QL_];          //  8 MB
__device__ float g_q[(size_t)S_ * H_ * D_];       // 32 MB
__device__ float g_kv[(size_t)S_ * D_];           //  2 MB
__device__ float g_kvT[(size_t)D_ * S_];          //  2 MB
__device__ float g_scores[(size_t)H_ * S_ * S_];  // 256 MB
__device__ float g_o[(size_t)S_ * H_ * D_];       // 32 MB
__device__ float g_or[(size_t)S_ * G_ * OR_];     // 16 MB

// ---------------- helpers ----------------
__device__ __forceinline__ uint32_t f2tf(float x) {
    uint32_t r;
    asm("cvt.rna.tf32.f32 %0, %1;" : "=r"(r) : "f"(x));
    return r;
}

__device__ __forceinline__ void mma_tf32(float4& c, const uint32_t a[4], const uint32_t b[2]) {
    asm volatile(
        "mma.sync.aligned.m16n8k8.row.col.f32.tf32.tf32.f32 "
        "{%0,%1,%2,%3}, {%4,%5,%6,%7}, {%8,%9}, {%0,%1,%2,%3};\n"
        : "+f"(c.x), "+f"(c.y), "+f"(c.z), "+f"(c.w)
        : "r"(a[0]), "r"(a[1]), "r"(a[2]), "r"(a[3]), "r"(b[0]), "r"(b[1]));
}

__device__ __forceinline__ void ldsm4(uint32_t* d, uint32_t addr) {
    asm volatile("ldmatrix.sync.aligned.m8n8.x4.shared.b16 {%0,%1,%2,%3}, [%4];"
        : "=r"(d[0]), "=r"(d[1]), "=r"(d[2]), "=r"(d[3]) : "r"(addr));
}

__device__ __forceinline__ float block_reduce(float v, bool is_max) {
    __shared__ float warp_res[8];
    __shared__ float result;
    __syncthreads();
    #pragma unroll
    for (int o = 16; o; o >>= 1) {
        float other = __shfl_xor_sync(0xffffffffu, v, o);
        v = is_max ? fmaxf(v, other) : (v + other);
    }
    if ((threadIdx.x & 31) == 0) warp_res[threadIdx.x >> 5] = v;
    __syncthreads();
    if (threadIdx.x == 0) {
        int nw = (blockDim.x + 31) >> 5;
        float r = warp_res[0];
        for (int i = 1; i < nw; i++) r = is_max ? fmaxf(r, warp_res[i]) : (r + warp_res[i]);
        result = r;
    }
    __syncthreads();
    return result;
}

// ============================================================================
// TF32 tensor-core GEMM, TN:  C[M,N] = A[M,K] @ B[N,K]^T
// 128x128x32 tile, 256 threads (2x4 warps, 64x32 warp tile),
// double-buffered smem, ldmatrix fragment loads, XOR-swizzled float4 layout.
//   smem float4 index for (row, k): row*8 + ((k>>2) ^ (row&7))
// ============================================================================
__global__ __launch_bounds__(256, 2) void gemm_tn_tc(
    const float* __restrict__ A, const float* __restrict__ B, float* __restrict__ C,
    int K, int lda, int ldb, int ldc,
    long sA, long sB, long sC, int causal_skip, int kcap)
{
    int row0 = blockIdx.y * BM, col0 = blockIdx.x * BN;
    if (causal_skip && col0 > row0) return;
    A += (long)blockIdx.z * sA;
    B += (long)blockIdx.z * sB;
    C += (long)blockIdx.z * sC;
    int Keff = kcap ? min(K, row0 + BM) : K;

    extern __shared__ uint32_t smem[];
    uint32_t smem_b = (uint32_t)__cvta_generic_to_shared(smem);
    // byte offsets: A buf0 = 0, A buf1 = 16384, B buf0 = 32768, B buf1 = 49152

    int tid = threadIdx.x, lane = tid & 31, warp = tid >> 5;
    int wm = warp >> 2, wn = warp & 3;

    float4 pa[4], pb[4];
    float4 c[4][4];
    #pragma unroll
    for (int i = 0; i < 4; i++)
        #pragma unroll
        for (int j = 0; j < 4; j++) c[i][j] = make_float4(0.f, 0.f, 0.f, 0.f);

    int ldr = tid >> 3;        // base row 0..31 (+32*i)
    int ldk = tid & 7;         // float4 k-index 0..7

    // prologue: load k=0 tile
    #pragma unroll
    for (int i = 0; i < 4; i++) {
        int r = ldr + i * 32;
        pa[i] = *(const float4*)(A + (long)(row0 + r) * lda + (ldk << 2));
        pb[i] = *(const float4*)(B + (long)(col0 + r) * ldb + (ldk << 2));
    }
    // store stage 0
    #pragma unroll
    for (int i = 0; i < 4; i++) {
        int r = ldr + i * 32;
        int c4 = ldk ^ (r & 7);
        uint32_t* pA = smem + ((r << 3) + c4) * 4;
        uint32_t* pB = smem + 8192 + ((r << 3) + c4) * 4;
        pA[0] = f2tf(pa[i].x); pA[1] = f2tf(pa[i].y); pA[2] = f2tf(pa[i].z); pA[3] = f2tf(pa[i].w);
        pB[0] = f2tf(pb[i].x); pB[1] = f2tf(pb[i].y); pB[2] = f2tf(pb[i].z); pB[3] = f2tf(pb[i].w);
    }
    __syncthreads();

    int jr = ((lane >> 3) & 1) << 3;   // 0/8 row offset within fragment
    int jk = lane >> 4;                // 0/1 -> float4 column offset
    int rr = lane & 7;

    int cur = 0;
    for (int k0 = 0; k0 < Keff; k0 += BK) {
        bool more = (k0 + BK) < Keff;
        if (more) {
            #pragma unroll
            for (int i = 0; i < 4; i++) {
                int r = ldr + i * 32;
                pa[i] = *(const float4*)(A + (long)(row0 + r) * lda + k0 + BK + (ldk << 2));
                pb[i] = *(const float4*)(B + (long)(col0 + r) * ldb + k0 + BK + (ldk << 2));
            }
        }
        uint32_t abase = smem_b + cur * 16384;
        uint32_t bbase = smem_b + 32768 + cur * 16384;
        #pragma unroll
        for (int ks = 0; ks < 4; ks++) {
            uint32_t af[4][4];
            #pragma unroll
            for (int mt = 0; mt < 4; mt++) {
                int arow = wm * 64 + mt * 16 + jr + rr;
                uint32_t ad = abase + (((arow << 3) + ((ks * 2 + jk) ^ (arow & 7))) << 4);
                ldsm4(af[mt], ad);
            }
            uint32_t bf[4][2];
            #pragma unroll
            for (int ntp = 0; ntp < 2; ntp++) {
                int nrow = wn * 32 + ntp * 16 + jr + rr;
                uint32_t bd = bbase + (((nrow << 3) + ((ks * 2 + jk) ^ (nrow & 7))) << 4);
                uint32_t t[4];
                ldsm4(t, bd);
                bf[ntp * 2][0] = t[0]; bf[ntp * 2 + 1][0] = t[1];
                bf[ntp * 2][1] = t[2]; bf[ntp * 2 + 1][1] = t[3];
            }
            #pragma unroll
            for (int mt = 0; mt < 4; mt++)
                #pragma unroll
                for (int nt = 0; nt < 4; nt++)
                    mma_tf32(c[mt][nt], af[mt], bf[nt]);
        }
        if (more) {
            int nxt = cur ^ 1;
            uint32_t* sA = smem + nxt * 4096;
            uint32_t* sB = smem + 8192 + nxt * 4096;
            #pragma unroll
            for (int i = 0; i < 4; i++) {
                int r = ldr + i * 32;
                int c4 = ldk ^ (r & 7);
                uint32_t* pA = sA + ((r << 3) + c4) * 4;
                uint32_t* pB = sB + ((r << 3) + c4) * 4;
                pA[0] = f2tf(pa[i].x); pA[1] = f2tf(pa[i].y); pA[2] = f2tf(pa[i].z); pA[3] = f2tf(pa[i].w);
                pB[0] = f2tf(pb[i].x); pB[1] = f2tf(pb[i].y); pB[2] = f2tf(pb[i].z); pB[3] = f2tf(pb[i].w);
            }
            __syncthreads();
            cur = nxt;
        }
    }

    // epilogue
    #pragma unroll
    for (int mt = 0; mt < 4; mt++) {
        int m = row0 + wm * 64 + mt * 16 + (lane >> 2);
        #pragma unroll
        for (int nt = 0; nt < 4; nt++) {
            int n = col0 + wn * 32 + nt * 8 + ((lane & 3) << 1);
            *(float2*)(C + (long)m * ldc + n)       = make_float2(c[mt][nt].x, c[mt][nt].y);
            *(float2*)(C + (long)(m + 8) * ldc + n) = make_float2(c[mt][nt].z, c[mt][nt].w);
        }
    }
}

// ---------------- elementwise / norm kernels ----------------
__global__ void cos_sin_k(const float* __restrict__ freqs) {
    int i = blockIdx.x * blockDim.x + threadIdx.x;
    if (i < S_ * RH_) {
        float f = freqs[i];
        g_cos[i] = cosf(f);
        g_sin[i] = sinf(f);
    }
}

__global__ __launch_bounds__(256) void rms_qa(const float* __restrict__ w) {
    int s = blockIdx.x;
    float* row = g_qa + (long)s * QL_;
    float ss = 0.f;
    for (int i = threadIdx.x; i < QL_; i += 256) { float v = row[i]; ss += v * v; }
    ss = block_reduce(ss, false);
    float sc = rsqrtf(ss / QL_ + EPS_);
    for (int i = threadIdx.x; i < QL_; i += 256) row[i] = row[i] * sc * w[i];
}

__global__ __launch_bounds__(256) void q_post() {
    int s = blockIdx.x, h = blockIdx.y;
    float* row = g_q + (size_t)s * (H_ * D_) + (size_t)h * D_;
    int d = threadIdx.x;
    float v = row[d];
    float ss = block_reduce(v * v, false);
    float sc = rsqrtf(ss / D_ + EPS_);
    __shared__ float sh[D_];
    sh[d] = v * sc;
    __syncthreads();
    float out;
    if (d < NOPE_) out = sh[d];
    else {
        int p = d - NOPE_, i = p >> 1;
        float cc = g_cos[s * RH_ + i], sn = g_sin[s * RH_ + i];
        float x1 = sh[NOPE_ + (i << 1)], x2 = sh[NOPE_ + (i << 1) + 1];
        out = (p & 1) ? (x1 * sn + x2 * cc) : (x1 * cc - x2 * sn);
    }
    row[d] = out;
}

__global__ __launch_bounds__(256) void kv_post(const float* __restrict__ w) {
    int s = blockIdx.x;
    float* row = g_kv + (long)s * D_;
    int d = threadIdx.x;
    float v = row[d];
    float ss = block_reduce(v * v, false);
    float sc = rsqrtf(ss / D_ + EPS_);
    __shared__ float sh[D_];
    sh[d] = v * sc * w[d];
    __syncthreads();
    float out;
    if (d < NOPE_) out = sh[d];
    else {
        int p = d - NOPE_, i = p >> 1;
        float cc = g_cos[s * RH_ + i], sn = g_sin[s * RH_ + i];
        float x1 = sh[NOPE_ + (i << 1)], x2 = sh[NOPE_ + (i << 1) + 1];
        out = (p & 1) ? (x1 * sn + x2 * cc) : (x1 * cc - x2 * sn);
    }
    row[d] = out;
}

// kvT[d][t] = kv[t][d]
__global__ __launch_bounds__(256) void transpose_kv() {
    __shared__ float t[32][33];
    int x = threadIdx.x & 31, y = threadIdx.x >> 5;  // 8 rows per pass
    #pragma unroll
    for (int i = 0; i < 4; i++) {
        int trow = blockIdx.x * 32 + y + i * 8;
        t[y + i * 8][x] = g_kv[(size_t)trow * D_ + blockIdx.y * 32 + x];
    }
    __syncthreads();
    #pragma unroll
    for (int i = 0; i < 4; i++) {
        int drow = blockIdx.y * 32 + y + i * 8;
        g_kvT[(size_t)drow * S_ + blockIdx.x * 32 + x] = t[x][y + i * 8];
    }
}

// causal softmax with sink, register-resident (single read + single write).
// Zero-fill up to the 128-boundary for the K-capped PV GEMM.
__global__ __launch_bounds__(256) void softmax_k(const float* __restrict__ sink) {
    int s = blockIdx.x, h = blockIdx.y;
    float* row = g_scores + ((size_t)h * S_ + s) * S_;
    int L = s + 1;
    float snk = sink[h];
    float v[8];
    float m = -3.4e38f;
    #pragma unroll
    for (int i = 0; i < 8; i++) {
        int t = threadIdx.x + i * 256;
        v[i] = (t < L) ? row[t] * SCALE_ : -3.4e38f;
        m = fmaxf(m, v[i]);
    }
    m = block_reduce(m, true);
    m = fmaxf(m, snk);
    float sum = 0.f;
    #pragma unroll
    for (int i = 0; i < 8; i++) {
        v[i] = __expf(v[i] - m);
        sum += v[i];
    }
    sum = block_reduce(sum, false);
    sum += __expf(snk - m);
    float inv = 1.f / sum;
    int zend = min(S_, ((s >> 7) + 1) << 7);
    #pragma unroll
    for (int i = 0; i < 8; i++) {
        int t = threadIdx.x + i * 256;
        if (t < L) row[t] = v[i] * inv;
        else if (t < zend) row[t] = 0.f;
    }
}

__global__ __launch_bounds__(64) void o_post() {
    int s = blockIdx.x, h = blockIdx.y;
    float* row = g_o + (size_t)s * (H_ * D_) + (size_t)h * D_ + NOPE_;
    __shared__ float sh[R_];
    int p = threadIdx.x;
    sh[p] = row[p];
    __syncthreads();
    int i = p >> 1;
    float cc = g_cos[s * RH_ + i], sn = g_sin[s * RH_ + i];
    float x1 = sh[i << 1], x2 = sh[(i << 1) + 1];
    row[p] = (p & 1) ? (x2 * cc - x1 * sn) : (x1 * cc + x2 * sn);
}

// ---------------- launch ----------------
extern "C" void kernel_launch(void* const* d_in, const int* in_sizes, int n_in,
                              void* d_out, int out_size) {
    const float* x        = (const float*)d_in[0];
    const float* freqs    = (const float*)d_in[1];
    const float* wq_a     = (const float*)d_in[2];
    const float* q_norm_w = (const float*)d_in[3];
    const float* wq_b     = (const float*)d_in[4];
    const float* wkv      = (const float*)d_in[5];
    const float* kv_norm_w= (const float*)d_in[6];
    const float* wo_a_w   = (const float*)d_in[7];
    const float* wo_b     = (const float*)d_in[8];
    const float* sink     = (const float*)d_in[9];
    float* out = (float*)d_out;

    float *p_qa, *p_q, *p_kv, *p_kvT, *p_sc, *p_o, *p_or;
    cudaGetSymbolAddress((void**)&p_qa,  g_qa);
    cudaGetSymbolAddress((void**)&p_q,   g_q);
    cudaGetSymbolAddress((void**)&p_kv,  g_kv);
    cudaGetSymbolAddress((void**)&p_kvT, g_kvT);
    cudaGetSymbolAddress((void**)&p_sc,  g_scores);
    cudaGetSymbolAddress((void**)&p_o,   g_o);
    cudaGetSymbolAddress((void**)&p_or,  g_or);

    cudaFuncSetAttribute(gemm_tn_tc, cudaFuncAttributeMaxDynamicSharedMemorySize, GEMM_SMEM);

    cos_sin_k<<<(S_ * RH_ + 255) / 256, 256>>>(freqs);

    // q_a = x @ wq_a^T   (2048 x 1024, K=2048)
    gemm_tn_tc<<<dim3(QL_ / BN, S_ / BM, 1), 256, GEMM_SMEM>>>(x, wq_a, p_qa,
        HID_, HID_, HID_, QL_, 0, 0, 0, 0, 0);
    rms_qa<<<S_, 256>>>(q_norm_w);

    // q = qa @ wq_b^T    (2048 x 4096, K=1024)
    gemm_tn_tc<<<dim3((H_ * D_) / BN, S_ / BM, 1), 256, GEMM_SMEM>>>(p_qa, wq_b, p_q,
        QL_, QL_, QL_, H_ * D_, 0, 0, 0, 0, 0);
    q_post<<<dim3(S_, H_), 256>>>();

    // kv = x @ wkv^T     (2048 x 256, K=2048)
    gemm_tn_tc<<<dim3(D_ / BN, S_ / BM, 1), 256, GEMM_SMEM>>>(x, wkv, p_kv,
        HID_, HID_, HID_, D_, 0, 0, 0, 0, 0);
    kv_post<<<S_, 256>>>(kv_norm_w);
    transpose_kv<<<dim3(S_ / 32, D_ / 32), 256>>>();

    // scores[h] = q_h @ kv^T  (batched over heads, causal block skip)
    gemm_tn_tc<<<dim3(S_ / BN, S_ / BM, H_), 256, GEMM_SMEM>>>(p_q, p_kv, p_sc,
        D_, H_ * D_, D_, S_, (long)D_, 0, (long)S_ * S_, 1, 0);

    softmax_k<<<dim3(S_, H_), 256>>>(sink);

    // o[h] = probs[h] @ kvT^T  (TN with pre-transposed kv, K capped causally)
    gemm_tn_tc<<<dim3(D_ / BN, S_ / BM, H_), 256, GEMM_SMEM>>>(p_sc, p_kvT, p_o,
        S_, S_, S_, H_ * D_, (long)S_ * S_, 0, (long)D_, 0, 1);

    o_post<<<dim3(S_, H_), 64>>>();

    // grouped wo_a: batch G
    gemm_tn_tc<<<dim3(OR_ / BN, S_ / BM, G_), 256, GEMM_SMEM>>>(p_o, wo_a_w, p_or,
        (H_ / G_) * D_, H_ * D_, (H_ / G_) * D_, G_ * OR_,
        (long)(H_ / G_) * D_, (long)OR_ * (H_ / G_) * D_, (long)OR_, 0, 0);

    // out = o_r @ wo_b^T  (2048 x 2048, K=2048)
    gemm_tn_tc<<<dim3(HID_ / BN, S_ / BM, 1), 256, GEMM_SMEM>>>(p_or, wo_b, out,
        G_ * OR_, G_ * OR_, G_ * OR_, HID_, 0, 0, 0, 0, 0);
}

// round 5
// speedup vs baseline: 1.7953x; 1.7953x over previous
#include <cuda_runtime.h>
#include <cstdint>

#define S_    2048
#define HID_  2048
#define H_    16
#define D_    256
#define R_    64
#define RH_   32          // R/2
#define NOPE_ 192
#define QL_   1024
#define OR_   512
#define G_    4
#define EPS_  1e-6f
#define SCALE_ 0.0625f    // 256^-0.5

#define BM 128
#define BN 128
#define BK 32
#define STAGE_BYTES 32768            // A 16KB + B 16KB per stage (fp32)
#define GEMM_SMEM (3 * STAGE_BYTES)  // 96 KB, 3-stage pipeline

// ---------------- scratch (static device memory; allocation-free) ----------------
__device__ float g_cos[S_ * RH_];
__device__ float g_sin[S_ * RH_];
__device__ float g_qa[(size_t)S_ * QL_];          //  8 MB
__device__ float g_q[(size_t)S_ * H_ * D_];       // 32 MB
__device__ float g_kv[(size_t)S_ * D_];           //  2 MB
__device__ float g_kvT[(size_t)D_ * S_];          //  2 MB
__device__ float g_scores[(size_t)H_ * S_ * S_];  // 256 MB
__device__ float g_o[(size_t)S_ * H_ * D_];       // 32 MB
__device__ float g_or[(size_t)S_ * G_ * OR_];     // 16 MB

// ---------------- helpers ----------------
__device__ __forceinline__ uint32_t f2tf_bits(uint32_t x) {
    float xf = __uint_as_float(x);
    uint32_t r;
    asm("cvt.rna.tf32.f32 %0, %1;" : "=r"(r) : "f"(xf));
    return r;
}

__device__ __forceinline__ void mma_tf32(float4& c, const uint32_t a[4], const uint32_t b[2]) {
    asm volatile(
        "mma.sync.aligned.m16n8k8.row.col.f32.tf32.tf32.f32 "
        "{%0,%1,%2,%3}, {%4,%5,%6,%7}, {%8,%9}, {%0,%1,%2,%3};\n"
        : "+f"(c.x), "+f"(c.y), "+f"(c.z), "+f"(c.w)
        : "r"(a[0]), "r"(a[1]), "r"(a[2]), "r"(a[3]), "r"(b[0]), "r"(b[1]));
}

__device__ __forceinline__ void ldsm4(uint32_t* d, uint32_t addr) {
    asm volatile("ldmatrix.sync.aligned.m8n8.x4.shared.b16 {%0,%1,%2,%3}, [%4];"
        : "=r"(d[0]), "=r"(d[1]), "=r"(d[2]), "=r"(d[3]) : "r"(addr));
}

#define CP16(dst, src) \
    asm volatile("cp.async.cg.shared.global [%0], [%1], 16;\n" :: "r"(dst), "l"(src))
#define CP_COMMIT() asm volatile("cp.async.commit_group;\n")
#define CP_WAIT1()  asm volatile("cp.async.wait_group 1;\n")

__device__ __forceinline__ float block_reduce(float v, bool is_max) {
    __shared__ float warp_res[8];
    __shared__ float result;
    __syncthreads();
    #pragma unroll
    for (int o = 16; o; o >>= 1) {
        float other = __shfl_xor_sync(0xffffffffu, v, o);
        v = is_max ? fmaxf(v, other) : (v + other);
    }
    if ((threadIdx.x & 31) == 0) warp_res[threadIdx.x >> 5] = v;
    __syncthreads();
    if (threadIdx.x == 0) {
        int nw = (blockDim.x + 31) >> 5;
        float r = warp_res[0];
        for (int i = 1; i < nw; i++) r = is_max ? fmaxf(r, warp_res[i]) : (r + warp_res[i]);
        result = r;
    }
    __syncthreads();
    return result;
}

// ============================================================================
// TF32 tensor-core GEMM, TN:  C[M,N] = A[M,K] @ B[N,K]^T
// 128x128x32 tile, 256 threads (2x4 warps, 64x32 warp tile).
// 3-stage cp.async pipeline (fp32 in smem, cvt->tf32 at fragment load),
// ldmatrix.x4 fragment loads, XOR-swizzled float4 layout:
//   float4 index for (row, k4): row*8 + (k4 ^ (row&7))
// ============================================================================
__global__ __launch_bounds__(256, 2) void gemm_tn_tc(
    const float* __restrict__ A, const float* __restrict__ B, float* __restrict__ C,
    int K, int lda, int ldb, int ldc,
    long sA, long sB, long sC, int causal_skip, int kcap)
{
    int row0 = blockIdx.y * BM, col0 = blockIdx.x * BN;
    if (causal_skip && col0 > row0) return;
    A += (long)blockIdx.z * sA;
    B += (long)blockIdx.z * sB;
    C += (long)blockIdx.z * sC;
    int Keff = kcap ? min(K, row0 + BM) : K;
    int niter = Keff / BK;

    extern __shared__ uint32_t smem[];
    uint32_t smem_b = (uint32_t)__cvta_generic_to_shared(smem);

    int tid = threadIdx.x, lane = tid & 31, warp = tid >> 5;
    int wm = warp >> 2, wn = warp & 3;

    // ---- loader setup (cp.async) ----
    int ldr = tid >> 3;        // base row 0..31 (+32*i)
    int ldk = tid & 7;         // float4 k-index 0..7
    uint32_t dstA[4];
    const float* srcA[4];
    const float* srcB[4];
    #pragma unroll
    for (int i = 0; i < 4; i++) {
        int r = ldr + i * 32;
        dstA[i] = smem_b + ((((r << 3) + (ldk ^ (r & 7)))) << 4);
        srcA[i] = A + (long)(row0 + r) * lda + (ldk << 2);
        srcB[i] = B + (long)(col0 + r) * ldb + (ldk << 2);
    }

    // ---- fragment base addresses (stage 0) ----
    int jr = ((lane >> 3) & 1) << 3;
    int jk = lane >> 4;
    int rr = lane & 7;
    uint32_t a_ad[4], b_ad[2];
    #pragma unroll
    for (int mt = 0; mt < 4; mt++) {
        int ar = wm * 64 + mt * 16 + jr + rr;
        a_ad[mt] = smem_b + (((ar << 3) + (jk ^ (ar & 7))) << 4);
    }
    #pragma unroll
    for (int ntp = 0; ntp < 2; ntp++) {
        int br = wn * 32 + ntp * 16 + jr + rr;
        b_ad[ntp] = smem_b + 16384 + (((br << 3) + (jk ^ (br & 7))) << 4);
    }

    float4 c[4][4];
    #pragma unroll
    for (int i = 0; i < 4; i++)
        #pragma unroll
        for (int j = 0; j < 4; j++) c[i][j] = make_float4(0.f, 0.f, 0.f, 0.f);

    // ---- prologue: stages 0,1 ----
    {
        #pragma unroll
        for (int i = 0; i < 4; i++) CP16(dstA[i], srcA[i]);
        #pragma unroll
        for (int i = 0; i < 4; i++) CP16(dstA[i] + 16384, srcB[i]);
        CP_COMMIT();
        if (niter > 1) {
            #pragma unroll
            for (int i = 0; i < 4; i++) CP16(dstA[i] + STAGE_BYTES, srcA[i] + BK);
            #pragma unroll
            for (int i = 0; i < 4; i++) CP16(dstA[i] + STAGE_BYTES + 16384, srcB[i] + BK);
        }
        CP_COMMIT();
    }

    int stage = 0;
    for (int k = 0; k < niter; k++) {
        CP_WAIT1();
        __syncthreads();

        // issue stage k+2
        if (k + 2 < niter) {
            int s2 = stage + 2; if (s2 >= 3) s2 -= 3;
            uint32_t so = (uint32_t)s2 * STAGE_BYTES;
            int koff = (k + 2) * BK;
            #pragma unroll
            for (int i = 0; i < 4; i++) CP16(dstA[i] + so, srcA[i] + koff);
            #pragma unroll
            for (int i = 0; i < 4; i++) CP16(dstA[i] + so + 16384, srcB[i] + koff);
        }
        CP_COMMIT();

        // compute stage k
        uint32_t so = (uint32_t)stage * STAGE_BYTES;
        #pragma unroll
        for (int ks = 0; ks < 4; ks++) {
            uint32_t af[4][4];
            #pragma unroll
            for (int mt = 0; mt < 4; mt++) {
                ldsm4(af[mt], (a_ad[mt] + so) ^ (ks << 5));
                af[mt][0] = f2tf_bits(af[mt][0]); af[mt][1] = f2tf_bits(af[mt][1]);
                af[mt][2] = f2tf_bits(af[mt][2]); af[mt][3] = f2tf_bits(af[mt][3]);
            }
            uint32_t bf[4][2];
            #pragma unroll
            for (int ntp = 0; ntp < 2; ntp++) {
                uint32_t t[4];
                ldsm4(t, (b_ad[ntp] + so) ^ (ks << 5));
                bf[ntp * 2][0]     = f2tf_bits(t[0]);
                bf[ntp * 2 + 1][0] = f2tf_bits(t[1]);
                bf[ntp * 2][1]     = f2tf_bits(t[2]);
                bf[ntp * 2 + 1][1] = f2tf_bits(t[3]);
            }
            #pragma unroll
            for (int mt = 0; mt < 4; mt++)
                #pragma unroll
                for (int nt = 0; nt < 4; nt++)
                    mma_tf32(c[mt][nt], af[mt], bf[nt]);
        }
        stage++; if (stage >= 3) stage -= 3;
    }

    // epilogue
    #pragma unroll
    for (int mt = 0; mt < 4; mt++) {
        int m = row0 + wm * 64 + mt * 16 + (lane >> 2);
        #pragma unroll
        for (int nt = 0; nt < 4; nt++) {
            int n = col0 + wn * 32 + nt * 8 + ((lane & 3) << 1);
            *(float2*)(C + (long)m * ldc + n)       = make_float2(c[mt][nt].x, c[mt][nt].y);
            *(float2*)(C + (long)(m + 8) * ldc + n) = make_float2(c[mt][nt].z, c[mt][nt].w);
        }
    }
}

// ---------------- elementwise / norm kernels ----------------
__global__ void cos_sin_k(const float* __restrict__ freqs) {
    int i = blockIdx.x * blockDim.x + threadIdx.x;
    if (i < S_ * RH_) {
        float f = freqs[i];
        g_cos[i] = cosf(f);
        g_sin[i] = sinf(f);
    }
}

__global__ __launch_bounds__(256) void rms_qa(const float* __restrict__ w) {
    int s = blockIdx.x;
    float* row = g_qa + (long)s * QL_;
    float ss = 0.f;
    for (int i = threadIdx.x; i < QL_; i += 256) { float v = row[i]; ss += v * v; }
    ss = block_reduce(ss, false);
    float sc = rsqrtf(ss / QL_ + EPS_);
    for (int i = threadIdx.x; i < QL_; i += 256) row[i] = row[i] * sc * w[i];
}

__global__ __launch_bounds__(256) void q_post() {
    int s = blockIdx.x, h = blockIdx.y;
    float* row = g_q + (size_t)s * (H_ * D_) + (size_t)h * D_;
    int d = threadIdx.x;
    float v = row[d];
    float ss = block_reduce(v * v, false);
    float sc = rsqrtf(ss / D_ + EPS_);
    __shared__ float sh[D_];
    sh[d] = v * sc;
    __syncthreads();
    float out;
    if (d < NOPE_) out = sh[d];
    else {
        int p = d - NOPE_, i = p >> 1;
        float cc = g_cos[s * RH_ + i], sn = g_sin[s * RH_ + i];
        float x1 = sh[NOPE_ + (i << 1)], x2 = sh[NOPE_ + (i << 1) + 1];
        out = (p & 1) ? (x1 * sn + x2 * cc) : (x1 * cc - x2 * sn);
    }
    row[d] = out;
}

__global__ __launch_bounds__(256) void kv_post(const float* __restrict__ w) {
    int s = blockIdx.x;
    float* row = g_kv + (long)s * D_;
    int d = threadIdx.x;
    float v = row[d];
    float ss = block_reduce(v * v, false);
    float sc = rsqrtf(ss / D_ + EPS_);
    __shared__ float sh[D_];
    sh[d] = v * sc * w[d];
    __syncthreads();
    float out;
    if (d < NOPE_) out = sh[d];
    else {
        int p = d - NOPE_, i = p >> 1;
        float cc = g_cos[s * RH_ + i], sn = g_sin[s * RH_ + i];
        float x1 = sh[NOPE_ + (i << 1)], x2 = sh[NOPE_ + (i << 1) + 1];
        out = (p & 1) ? (x1 * sn + x2 * cc) : (x1 * cc - x2 * sn);
    }
    row[d] = out;
}

// kvT[d][t] = kv[t][d]
__global__ __launch_bounds__(256) void transpose_kv() {
    __shared__ float t[32][33];
    int x = threadIdx.x & 31, y = threadIdx.x >> 5;
    #pragma unroll
    for (int i = 0; i < 4; i++) {
        int trow = blockIdx.x * 32 + y + i * 8;
        t[y + i * 8][x] = g_kv[(size_t)trow * D_ + blockIdx.y * 32 + x];
    }
    __syncthreads();
    #pragma unroll
    for (int i = 0; i < 4; i++) {
        int drow = blockIdx.y * 32 + y + i * 8;
        g_kvT[(size_t)drow * S_ + blockIdx.x * 32 + x] = t[x][y + i * 8];
    }
}

// causal softmax with sink, register-resident.
// Zero-fill up to the 128-boundary for the K-capped PV GEMM.
__global__ __launch_bounds__(256) void softmax_k(const float* __restrict__ sink) {
    int s = blockIdx.x, h = blockIdx.y;
    float* row = g_scores + ((size_t)h * S_ + s) * S_;
    int L = s + 1;
    float snk = sink[h];
    float v[8];
    float m = -3.4e38f;
    #pragma unroll
    for (int i = 0; i < 8; i++) {
        int t = threadIdx.x + i * 256;
        v[i] = (t < L) ? row[t] * SCALE_ : -3.4e38f;
        m = fmaxf(m, v[i]);
    }
    m = block_reduce(m, true);
    m = fmaxf(m, snk);
    float sum = 0.f;
    #pragma unroll
    for (int i = 0; i < 8; i++) {
        v[i] = __expf(v[i] - m);
        sum += v[i];
    }
    sum = block_reduce(sum, false);
    sum += __expf(snk - m);
    float inv = 1.f / sum;
    int zend = min(S_, ((s >> 7) + 1) << 7);
    #pragma unroll
    for (int i = 0; i < 8; i++) {
        int t = threadIdx.x + i * 256;
        if (t < L) row[t] = v[i] * inv;
        else if (t < zend) row[t] = 0.f;
    }
}

__global__ __launch_bounds__(64) void o_post() {
    int s = blockIdx.x, h = blockIdx.y;
    float* row = g_o + (size_t)s * (H_ * D_) + (size_t)h * D_ + NOPE_;
    __shared__ float sh[R_];
    int p = threadIdx.x;
    sh[p] = row[p];
    __syncthreads();
    int i = p >> 1;
    float cc = g_cos[s * RH_ + i], sn = g_sin[s * RH_ + i];
    float x1 = sh[i << 1], x2 = sh[(i << 1) + 1];
    row[p] = (p & 1) ? (x2 * cc - x1 * sn) : (x1 * cc + x2 * sn);
}

// ---------------- launch ----------------
extern "C" void kernel_launch(void* const* d_in, const int* in_sizes, int n_in,
                              void* d_out, int out_size) {
    const float* x        = (const float*)d_in[0];
    const float* freqs    = (const float*)d_in[1];
    const float* wq_a     = (const float*)d_in[2];
    const float* q_norm_w = (const float*)d_in[3];
    const float* wq_b     = (const float*)d_in[4];
    const float* wkv      = (const float*)d_in[5];
    const float* kv_norm_w= (const float*)d_in[6];
    const float* wo_a_w   = (const float*)d_in[7];
    const float* wo_b     = (const float*)d_in[8];
    const float* sink     = (const float*)d_in[9];
    float* out = (float*)d_out;

    float *p_qa, *p_q, *p_kv, *p_kvT, *p_sc, *p_o, *p_or;
    cudaGetSymbolAddress((void**)&p_qa,  g_qa);
    cudaGetSymbolAddress((void**)&p_q,   g_q);
    cudaGetSymbolAddress((void**)&p_kv,  g_kv);
    cudaGetSymbolAddress((void**)&p_kvT, g_kvT);
    cudaGetSymbolAddress((void**)&p_sc,  g_scores);
    cudaGetSymbolAddress((void**)&p_o,   g_o);
    cudaGetSymbolAddress((void**)&p_or,  g_or);

    cudaFuncSetAttribute(gemm_tn_tc, cudaFuncAttributeMaxDynamicSharedMemorySize, GEMM_SMEM);

    cos_sin_k<<<(S_ * RH_ + 255) / 256, 256>>>(freqs);

    // q_a = x @ wq_a^T   (2048 x 1024, K=2048)
    gemm_tn_tc<<<dim3(QL_ / BN, S_ / BM, 1), 256, GEMM_SMEM>>>(x, wq_a, p_qa,
        HID_, HID_, HID_, QL_, 0, 0, 0, 0, 0);
    rms_qa<<<S_, 256>>>(q_norm_w);

    // q = qa @ wq_b^T    (2048 x 4096, K=1024)
    gemm_tn_tc<<<dim3((H_ * D_) / BN, S_ / BM, 1), 256, GEMM_SMEM>>>(p_qa, wq_b, p_q,
        QL_, QL_, QL_, H_ * D_, 0, 0, 0, 0, 0);
    q_post<<<dim3(S_, H_), 256>>>();

    // kv = x @ wkv^T     (2048 x 256, K=2048)
    gemm_tn_tc<<<dim3(D_ / BN, S_ / BM, 1), 256, GEMM_SMEM>>>(x, wkv, p_kv,
        HID_, HID_, HID_, D_, 0, 0, 0, 0, 0);
    kv_post<<<S_, 256>>>(kv_norm_w);
    transpose_kv<<<dim3(S_ / 32, D_ / 32), 256>>>();

    // scores[h] = q_h @ kv^T  (batched over heads, causal block skip)
    gemm_tn_tc<<<dim3(S_ / BN, S_ / BM, H_), 256, GEMM_SMEM>>>(p_q, p_kv, p_sc,
        D_, H_ * D_, D_, S_, (long)D_, 0, (long)S_ * S_, 1, 0);

    softmax_k<<<dim3(S_, H_), 256>>>(sink);

    // o[h] = probs[h] @ kvT^T  (TN with pre-transposed kv, K capped causally)
    gemm_tn_tc<<<dim3(D_ / BN, S_ / BM, H_), 256, GEMM_SMEM>>>(p_sc, p_kvT, p_o,
        S_, S_, S_, H_ * D_, (long)S_ * S_, 0, (long)D_, 0, 1);

    o_post<<<dim3(S_, H_), 64>>>();

    // grouped wo_a: batch G
    gemm_tn_tc<<<dim3(OR_ / BN, S_ / BM, G_), 256, GEMM_SMEM>>>(p_o, wo_a_w, p_or,
        (H_ / G_) * D_, H_ * D_, (H_ / G_) * D_, G_ * OR_,
        (long)(H_ / G_) * D_, (long)OR_ * (H_ / G_) * D_, (long)OR_, 0, 0);

    // out = o_r @ wo_b^T  (2048 x 2048, K=2048)
    gemm_tn_tc<<<dim3(HID_ / BN, S_ / BM, 1), 256, GEMM_SMEM>>>(p_or, wo_b, out,
        G_ * OR_, G_ * OR_, G_ * OR_, HID_, 0, 0, 0, 0, 0);
}

// round 6
// speedup vs baseline: 1.8294x; 1.0190x over previous
#include <cuda_runtime.h>
#include <cstdint>

#define S_    2048
#define HID_  2048
#define H_    16
#define D_    256
#define R_    64
#define RH_   32          // R/2
#define NOPE_ 192
#define QL_   1024
#define OR_   512
#define G_    4
#define EPS_  1e-6f
#define SCALE_ 0.0625f    // 256^-0.5

#define BM 128
#define BN 128
#define BK 32
#define STAGE_BYTES 32768            // A 16KB + B 16KB per stage
#define GEMM_SMEM (3 * STAGE_BYTES)  // 96 KB, 3-stage pipeline

// ---------------- scratch (static device memory; allocation-free) ----------------
__device__ float g_cos[S_ * RH_];
__device__ float g_sin[S_ * RH_];
__device__ float g_x[(size_t)S_ * HID_];          // 16 MB (tf32-rounded x)
__device__ float g_wqa[(size_t)QL_ * HID_];       //  8 MB
__device__ float g_wqb[(size_t)H_ * D_ * QL_];    // 16 MB
__device__ float g_wkv[(size_t)D_ * HID_];        //  2 MB
__device__ float g_woa[(size_t)G_ * OR_ * 1024];  //  8 MB
__device__ float g_wob[(size_t)HID_ * G_ * OR_];  // 16 MB
__device__ float g_qa[(size_t)S_ * QL_];          //  8 MB
__device__ float g_q[(size_t)S_ * H_ * D_];       // 32 MB
__device__ float g_kv[(size_t)S_ * D_];           //  2 MB
__device__ float g_kvT[(size_t)D_ * S_];          //  2 MB
__device__ float g_scores[(size_t)H_ * S_ * S_];  // 256 MB
__device__ float g_o[(size_t)S_ * H_ * D_];       // 32 MB
__device__ float g_or[(size_t)S_ * G_ * OR_];     // 16 MB

// ---------------- helpers ----------------
__device__ __forceinline__ uint32_t f2tf(float x) {
    uint32_t r;
    asm("cvt.rna.tf32.f32 %0, %1;" : "=r"(r) : "f"(x));
    return r;
}
__device__ __forceinline__ float f2tf_f(float x) { return __uint_as_float(f2tf(x)); }

__device__ __forceinline__ void mma_tf32(float4& c, const uint32_t a[4], const uint32_t b[2]) {
    asm volatile(
        "mma.sync.aligned.m16n8k8.row.col.f32.tf32.tf32.f32 "
        "{%0,%1,%2,%3}, {%4,%5,%6,%7}, {%8,%9}, {%0,%1,%2,%3};\n"
        : "+f"(c.x), "+f"(c.y), "+f"(c.z), "+f"(c.w)
        : "r"(a[0]), "r"(a[1]), "r"(a[2]), "r"(a[3]), "r"(b[0]), "r"(b[1]));
}

__device__ __forceinline__ void ldsm4(uint32_t* d, uint32_t addr) {
    asm volatile("ldmatrix.sync.aligned.m8n8.x4.shared.b16 {%0,%1,%2,%3}, [%4];"
        : "=r"(d[0]), "=r"(d[1]), "=r"(d[2]), "=r"(d[3]) : "r"(addr));
}

#define CP16(dst, src) \
    asm volatile("cp.async.cg.shared.global [%0], [%1], 16;\n" :: "r"(dst), "l"(src))
#define CP_COMMIT() asm volatile("cp.async.commit_group;\n")
#define CP_WAIT1()  asm volatile("cp.async.wait_group 1;\n")

__device__ __forceinline__ float block_reduce(float v, bool is_max) {
    __shared__ float warp_res[8];
    __shared__ float result;
    __syncthreads();
    #pragma unroll
    for (int o = 16; o; o >>= 1) {
        float other = __shfl_xor_sync(0xffffffffu, v, o);
        v = is_max ? fmaxf(v, other) : (v + other);
    }
    if ((threadIdx.x & 31) == 0) warp_res[threadIdx.x >> 5] = v;
    __syncthreads();
    if (threadIdx.x == 0) {
        int nw = (blockDim.x + 31) >> 5;
        float r = warp_res[0];
        for (int i = 1; i < nw; i++) r = is_max ? fmaxf(r, warp_res[i]) : (r + warp_res[i]);
        result = r;
    }
    __syncthreads();
    return result;
}

// elementwise tf32 rounding: dst[i] = round_tf32(src[i]); n must be /4
__global__ __launch_bounds__(256) void round_tf32_k(const float* __restrict__ src,
                                                    float* __restrict__ dst, int n4) {
    int i = blockIdx.x * 256 + threadIdx.x;
    if (i < n4) {
        float4 v = ((const float4*)src)[i];
        v.x = f2tf_f(v.x); v.y = f2tf_f(v.y); v.z = f2tf_f(v.z); v.w = f2tf_f(v.w);
        ((float4*)dst)[i] = v;
    }
}

// ============================================================================
// TF32 tensor-core GEMM, TN:  C[M,N] = A[M,K] @ B[N,K]^T
// Inputs MUST already be tf32-rounded bits (no cvt in the loop).
// 128x128x32 tile, 256 threads (2x4 warps, 64x32 warp tile),
// 3-stage cp.async pipeline, ldmatrix.x4, XOR-swizzled float4 layout.
// ============================================================================
__global__ __launch_bounds__(256, 2) void gemm_tn_tc(
    const float* __restrict__ A, const float* __restrict__ B, float* __restrict__ C,
    int K, int lda, int ldb, int ldc,
    long sA, long sB, long sC, int causal_skip, int kcap)
{
    int row0 = blockIdx.y * BM, col0 = blockIdx.x * BN;
    if (causal_skip && col0 > row0) return;
    A += (long)blockIdx.z * sA;
    B += (long)blockIdx.z * sB;
    C += (long)blockIdx.z * sC;
    int Keff = kcap ? min(K, row0 + BM) : K;
    int niter = Keff / BK;

    extern __shared__ uint32_t smem[];
    uint32_t smem_b = (uint32_t)__cvta_generic_to_shared(smem);

    int tid = threadIdx.x, lane = tid & 31, warp = tid >> 5;
    int wm = warp >> 2, wn = warp & 3;

    // ---- loader setup ----
    int ldr = tid >> 3;
    int ldk = tid & 7;
    uint32_t dstA[4];
    const float* srcA[4];
    const float* srcB[4];
    #pragma unroll
    for (int i = 0; i < 4; i++) {
        int r = ldr + i * 32;
        dstA[i] = smem_b + ((((r << 3) + (ldk ^ (r & 7)))) << 4);
        srcA[i] = A + (long)(row0 + r) * lda + (ldk << 2);
        srcB[i] = B + (long)(col0 + r) * ldb + (ldk << 2);
    }

    // ---- fragment base addresses (stage 0) ----
    int jr = ((lane >> 3) & 1) << 3;
    int jk = lane >> 4;
    int rr = lane & 7;
    uint32_t a_ad[4], b_ad[2];
    #pragma unroll
    for (int mt = 0; mt < 4; mt++) {
        int ar = wm * 64 + mt * 16 + jr + rr;
        a_ad[mt] = smem_b + (((ar << 3) + (jk ^ (ar & 7))) << 4);
    }
    #pragma unroll
    for (int ntp = 0; ntp < 2; ntp++) {
        int br = wn * 32 + ntp * 16 + jr + rr;
        b_ad[ntp] = smem_b + 16384 + (((br << 3) + (jk ^ (br & 7))) << 4);
    }

    float4 c[4][4];
    #pragma unroll
    for (int i = 0; i < 4; i++)
        #pragma unroll
        for (int j = 0; j < 4; j++) c[i][j] = make_float4(0.f, 0.f, 0.f, 0.f);

    // ---- prologue: stages 0,1 ----
    #pragma unroll
    for (int i = 0; i < 4; i++) CP16(dstA[i], srcA[i]);
    #pragma unroll
    for (int i = 0; i < 4; i++) CP16(dstA[i] + 16384, srcB[i]);
    CP_COMMIT();
    if (niter > 1) {
        #pragma unroll
        for (int i = 0; i < 4; i++) CP16(dstA[i] + STAGE_BYTES, srcA[i] + BK);
        #pragma unroll
        for (int i = 0; i < 4; i++) CP16(dstA[i] + STAGE_BYTES + 16384, srcB[i] + BK);
    }
    CP_COMMIT();
    #pragma unroll
    for (int i = 0; i < 4; i++) { srcA[i] += 2 * BK; srcB[i] += 2 * BK; }

    int stage = 0;
    for (int k = 0; k < niter; k++) {
        CP_WAIT1();
        __syncthreads();

        if (k + 2 < niter) {
            int s2 = stage + 2; if (s2 >= 3) s2 -= 3;
            uint32_t so2 = (uint32_t)s2 * STAGE_BYTES;
            #pragma unroll
            for (int i = 0; i < 4; i++) CP16(dstA[i] + so2, srcA[i]);
            #pragma unroll
            for (int i = 0; i < 4; i++) CP16(dstA[i] + so2 + 16384, srcB[i]);
        }
        CP_COMMIT();
        #pragma unroll
        for (int i = 0; i < 4; i++) { srcA[i] += BK; srcB[i] += BK; }

        uint32_t so = (uint32_t)stage * STAGE_BYTES;
        uint32_t aa[4], bb[2];
        #pragma unroll
        for (int mt = 0; mt < 4; mt++) aa[mt] = a_ad[mt] + so;
        #pragma unroll
        for (int ntp = 0; ntp < 2; ntp++) bb[ntp] = b_ad[ntp] + so;

        #pragma unroll
        for (int ks = 0; ks < 4; ks++) {
            uint32_t af[4][4];
            #pragma unroll
            for (int mt = 0; mt < 4; mt++) ldsm4(af[mt], aa[mt] ^ (ks << 5));
            uint32_t bf[4][2];
            #pragma unroll
            for (int ntp = 0; ntp < 2; ntp++) {
                uint32_t t[4];
                ldsm4(t, bb[ntp] ^ (ks << 5));
                bf[ntp * 2][0]     = t[0];
                bf[ntp * 2 + 1][0] = t[1];
                bf[ntp * 2][1]     = t[2];
                bf[ntp * 2 + 1][1] = t[3];
            }
            #pragma unroll
            for (int mt = 0; mt < 4; mt++)
                #pragma unroll
                for (int nt = 0; nt < 4; nt++)
                    mma_tf32(c[mt][nt], af[mt], bf[nt]);
        }
        stage++; if (stage >= 3) stage -= 3;
    }

    // epilogue
    #pragma unroll
    for (int mt = 0; mt < 4; mt++) {
        int m = row0 + wm * 64 + mt * 16 + (lane >> 2);
        #pragma unroll
        for (int nt = 0; nt < 4; nt++) {
            int n = col0 + wn * 32 + nt * 8 + ((lane & 3) << 1);
            *(float2*)(C + (long)m * ldc + n)       = make_float2(c[mt][nt].x, c[mt][nt].y);
            *(float2*)(C + (long)(m + 8) * ldc + n) = make_float2(c[mt][nt].z, c[mt][nt].w);
        }
    }
}

// ---------------- elementwise / norm kernels ----------------
__global__ void cos_sin_k(const float* __restrict__ freqs) {
    int i = blockIdx.x * blockDim.x + threadIdx.x;
    if (i < S_ * RH_) {
        float f = freqs[i];
        g_cos[i] = cosf(f);
        g_sin[i] = sinf(f);
    }
}

// RMS-norm rows of g_qa, tf32-rounded store
__global__ __launch_bounds__(256) void rms_qa(const float* __restrict__ w) {
    int s = blockIdx.x;
    float* row = g_qa + (long)s * QL_;
    float ss = 0.f;
    for (int i = threadIdx.x; i < QL_; i += 256) { float v = row[i]; ss += v * v; }
    ss = block_reduce(ss, false);
    float sc = rsqrtf(ss / QL_ + EPS_);
    for (int i = threadIdx.x; i < QL_; i += 256) row[i] = f2tf_f(row[i] * sc * w[i]);
}

// per (s,h): normalize over D, RoPE last R dims, tf32-rounded store
__global__ __launch_bounds__(256) void q_post() {
    int s = blockIdx.x, h = blockIdx.y;
    float* row = g_q + (size_t)s * (H_ * D_) + (size_t)h * D_;
    int d = threadIdx.x;
    float v = row[d];
    float ss = block_reduce(v * v, false);
    float sc = rsqrtf(ss / D_ + EPS_);
    __shared__ float sh[D_];
    sh[d] = v * sc;
    __syncthreads();
    float out;
    if (d < NOPE_) out = sh[d];
    else {
        int p = d - NOPE_, i = p >> 1;
        float cc = g_cos[s * RH_ + i], sn = g_sin[s * RH_ + i];
        float x1 = sh[NOPE_ + (i << 1)], x2 = sh[NOPE_ + (i << 1) + 1];
        out = (p & 1) ? (x1 * sn + x2 * cc) : (x1 * cc - x2 * sn);
    }
    row[d] = f2tf_f(out);
}

__global__ __launch_bounds__(256) void kv_post(const float* __restrict__ w) {
    int s = blockIdx.x;
    float* row = g_kv + (long)s * D_;
    int d = threadIdx.x;
    float v = row[d];
    float ss = block_reduce(v * v, false);
    float sc = rsqrtf(ss / D_ + EPS_);
    __shared__ float sh[D_];
    sh[d] = v * sc * w[d];
    __syncthreads();
    float out;
    if (d < NOPE_) out = sh[d];
    else {
        int p = d - NOPE_, i = p >> 1;
        float cc = g_cos[s * RH_ + i], sn = g_sin[s * RH_ + i];
        float x1 = sh[NOPE_ + (i << 1)], x2 = sh[NOPE_ + (i << 1) + 1];
        out = (p & 1) ? (x1 * sn + x2 * cc) : (x1 * cc - x2 * sn);
    }
    row[d] = f2tf_f(out);
}

// kvT[d][t] = kv[t][d]  (kv already rounded)
__global__ __launch_bounds__(256) void transpose_kv() {
    __shared__ float t[32][33];
    int x = threadIdx.x & 31, y = threadIdx.x >> 5;
    #pragma unroll
    for (int i = 0; i < 4; i++) {
        int trow = blockIdx.x * 32 + y + i * 8;
        t[y + i * 8][x] = g_kv[(size_t)trow * D_ + blockIdx.y * 32 + x];
    }
    __syncthreads();
    #pragma unroll
    for (int i = 0; i < 4; i++) {
        int drow = blockIdx.y * 32 + y + i * 8;
        g_kvT[(size_t)drow * S_ + blockIdx.x * 32 + x] = t[x][y + i * 8];
    }
}

// causal softmax with sink, register-resident, tf32-rounded probs.
// Zero-fill up to the 128-boundary for the K-capped PV GEMM.
__global__ __launch_bounds__(256) void softmax_k(const float* __restrict__ sink) {
    int s = blockIdx.x, h = blockIdx.y;
    float* row = g_scores + ((size_t)h * S_ + s) * S_;
    int L = s + 1;
    float snk = sink[h];
    float v[8];
    float m = -3.4e38f;
    #pragma unroll
    for (int i = 0; i < 8; i++) {
        int t = threadIdx.x + i * 256;
        v[i] = (t < L) ? row[t] * SCALE_ : -3.4e38f;
        m = fmaxf(m, v[i]);
    }
    m = block_reduce(m, true);
    m = fmaxf(m, snk);
    float sum = 0.f;
    #pragma unroll
    for (int i = 0; i < 8; i++) {
        v[i] = __expf(v[i] - m);
        sum += v[i];
    }
    sum = block_reduce(sum, false);
    sum += __expf(snk - m);
    float inv = 1.f / sum;
    int zend = min(S_, ((s >> 7) + 1) << 7);
    #pragma unroll
    for (int i = 0; i < 8; i++) {
        int t = threadIdx.x + i * 256;
        if (t < L) row[t] = f2tf_f(v[i] * inv);
        else if (t < zend) row[t] = 0.f;
    }
}

// inverse RoPE on last R dims of o + tf32 round on full row
__global__ __launch_bounds__(256) void o_post() {
    int s = blockIdx.x, h = blockIdx.y;
    float* row = g_o + (size_t)s * (H_ * D_) + (size_t)h * D_;
    int d = threadIdx.x;
    __shared__ float sh[R_];
    float v = row[d];
    if (d >= NOPE_) sh[d - NOPE_] = v;
    __syncthreads();
    float out;
    if (d < NOPE_) out = v;
    else {
        int p = d - NOPE_, i = p >> 1;
        float cc = g_cos[s * RH_ + i], sn = g_sin[s * RH_ + i];
        float x1 = sh[i << 1], x2 = sh[(i << 1) + 1];
        out = (p & 1) ? (x2 * cc - x1 * sn) : (x1 * cc + x2 * sn);
    }
    row[d] = f2tf_f(out);
}

// wo_a output needs rounding before the final GEMM
__global__ __launch_bounds__(256) void round_or_k() {
    int i = blockIdx.x * 256 + threadIdx.x;
    float4 v = ((const float4*)g_or)[i];
    v.x = f2tf_f(v.x); v.y = f2tf_f(v.y); v.z = f2tf_f(v.z); v.w = f2tf_f(v.w);
    ((float4*)g_or)[i] = v;
}

// ---------------- launch ----------------
extern "C" void kernel_launch(void* const* d_in, const int* in_sizes, int n_in,
                              void* d_out, int out_size) {
    const float* x        = (const float*)d_in[0];
    const float* freqs    = (const float*)d_in[1];
    const float* wq_a     = (const float*)d_in[2];
    const float* q_norm_w = (const float*)d_in[3];
    const float* wq_b     = (const float*)d_in[4];
    const float* wkv      = (const float*)d_in[5];
    const float* kv_norm_w= (const float*)d_in[6];
    const float* wo_a_w   = (const float*)d_in[7];
    const float* wo_b     = (const float*)d_in[8];
    const float* sink     = (const float*)d_in[9];
    float* out = (float*)d_out;

    float *p_x, *p_wqa, *p_wqb, *p_wkv, *p_woa, *p_wob;
    float *p_qa, *p_q, *p_kv, *p_kvT, *p_sc, *p_o, *p_or;
    cudaGetSymbolAddress((void**)&p_x,   g_x);
    cudaGetSymbolAddress((void**)&p_wqa, g_wqa);
    cudaGetSymbolAddress((void**)&p_wqb, g_wqb);
    cudaGetSymbolAddress((void**)&p_wkv, g_wkv);
    cudaGetSymbolAddress((void**)&p_woa, g_woa);
    cudaGetSymbolAddress((void**)&p_wob, g_wob);
    cudaGetSymbolAddress((void**)&p_qa,  g_qa);
    cudaGetSymbolAddress((void**)&p_q,   g_q);
    cudaGetSymbolAddress((void**)&p_kv,  g_kv);
    cudaGetSymbolAddress((void**)&p_kvT, g_kvT);
    cudaGetSymbolAddress((void**)&p_sc,  g_scores);
    cudaGetSymbolAddress((void**)&p_o,   g_o);
    cudaGetSymbolAddress((void**)&p_or,  g_or);

    cudaFuncSetAttribute(gemm_tn_tc, cudaFuncAttributeMaxDynamicSharedMemorySize, GEMM_SMEM);

    cos_sin_k<<<(S_ * RH_ + 255) / 256, 256>>>(freqs);

    // pre-round operands to tf32 bits
    round_tf32_k<<<(S_ * HID_ / 4 + 255) / 256, 256>>>(x, p_x, S_ * HID_ / 4);
    round_tf32_k<<<(QL_ * HID_ / 4 + 255) / 256, 256>>>(wq_a, p_wqa, QL_ * HID_ / 4);
    round_tf32_k<<<(H_ * D_ * QL_ / 4 + 255) / 256, 256>>>(wq_b, p_wqb, H_ * D_ * QL_ / 4);
    round_tf32_k<<<(D_ * HID_ / 4 + 255) / 256, 256>>>(wkv, p_wkv, D_ * HID_ / 4);
    round_tf32_k<<<(G_ * OR_ * 1024 / 4 + 255) / 256, 256>>>(wo_a_w, p_woa, G_ * OR_ * 1024 / 4);
    round_tf32_k<<<(HID_ * G_ * OR_ / 4 + 255) / 256, 256>>>(wo_b, p_wob, HID_ * G_ * OR_ / 4);

    // q_a = x @ wq_a^T   (2048 x 1024, K=2048)
    gemm_tn_tc<<<dim3(QL_ / BN, S_ / BM, 1), 256, GEMM_SMEM>>>(p_x, p_wqa, p_qa,
        HID_, HID_, HID_, QL_, 0, 0, 0, 0, 0);
    rms_qa<<<S_, 256>>>(q_norm_w);

    // q = qa @ wq_b^T    (2048 x 4096, K=1024)
    gemm_tn_tc<<<dim3((H_ * D_) / BN, S_ / BM, 1), 256, GEMM_SMEM>>>(p_qa, p_wqb, p_q,
        QL_, QL_, QL_, H_ * D_, 0, 0, 0, 0, 0);
    q_post<<<dim3(S_, H_), 256>>>();

    // kv = x @ wkv^T     (2048 x 256, K=2048)
    gemm_tn_tc<<<dim3(D_ / BN, S_ / BM, 1), 256, GEMM_SMEM>>>(p_x, p_wkv, p_kv,
        HID_, HID_, HID_, D_, 0, 0, 0, 0, 0);
    kv_post<<<S_, 256>>>(kv_norm_w);
    transpose_kv<<<dim3(S_ / 32, D_ / 32), 256>>>();

    // scores[h] = q_h @ kv^T  (batched over heads, causal block skip)
    gemm_tn_tc<<<dim3(S_ / BN, S_ / BM, H_), 256, GEMM_SMEM>>>(p_q, p_kv, p_sc,
        D_, H_ * D_, D_, S_, (long)D_, 0, (long)S_ * S_, 1, 0);

    softmax_k<<<dim3(S_, H_), 256>>>(sink);

    // o[h] = probs[h] @ kvT^T  (TN with pre-transposed kv, K capped causally)
    gemm_tn_tc<<<dim3(D_ / BN, S_ / BM, H_), 256, GEMM_SMEM>>>(p_sc, p_kvT, p_o,
        S_, S_, S_, H_ * D_, (long)S_ * S_, 0, (long)D_, 0, 1);

    o_post<<<dim3(S_, H_), 256>>>();

    // grouped wo_a: batch G
    gemm_tn_tc<<<dim3(OR_ / BN, S_ / BM, G_), 256, GEMM_SMEM>>>(p_o, p_woa, p_or,
        (H_ / G_) * D_, H_ * D_, (H_ / G_) * D_, G_ * OR_,
        (long)(H_ / G_) * D_, (long)OR_ * (H_ / G_) * D_, (long)OR_, 0, 0);
    round_or_k<<<(S_ * G_ * OR_ / 4) / 256, 256>>>();

    // out = o_r @ wo_b^T  (2048 x 2048, K=2048)
    gemm_tn_tc<<<dim3(HID_ / BN, S_ / BM, 1), 256, GEMM_SMEM>>>(p_or, p_wob, out,
        G_ * OR_, G_ * OR_, G_ * OR_, HID_, 0, 0, 0, 0, 0);
}

// round 7
// speedup vs baseline: 2.0827x; 1.1385x over previous
#include <cuda_runtime.h>
#include <cstdint>

#define S_    2048
#define HID_  2048
#define H_    16
#define D_    256
#define R_    64
#define RH_   32          // R/2
#define NOPE_ 192
#define QL_   1024
#define OR_   512
#define G_    4
#define EPS_  1e-6f
#define SCALE_ 0.0625f    // 256^-0.5

#define BM 128
#define BN 128
#define BK 32
#define STAGE_BYTES 32768
#define GEMM_SMEM (3 * STAGE_BYTES)

// flash smem (floats): Q 16384 | KV 16384 | KVT 16384 | P 4096 | RED 512
#define F_Q   0
#define F_KV  16384
#define F_KVT 32768
#define F_P   49152
#define F_RED 53248
#define FLASH_SMEM ((53248 + 512) * 4)

// ---------------- scratch ----------------
__device__ float g_cos[S_ * RH_];
__device__ float g_sin[S_ * RH_];
__device__ float g_x[(size_t)S_ * HID_];
__device__ float g_wqa[(size_t)QL_ * HID_];
__device__ float g_wqb[(size_t)H_ * D_ * QL_];
__device__ float g_wkv[(size_t)D_ * HID_];
__device__ float g_woa[(size_t)G_ * OR_ * 1024];
__device__ float g_wob[(size_t)HID_ * G_ * OR_];
__device__ float g_qa[(size_t)S_ * QL_];
__device__ float g_q[(size_t)S_ * H_ * D_];
__device__ float g_kv[(size_t)S_ * D_];
__device__ float g_kvT[(size_t)D_ * S_];
__device__ float g_o[(size_t)S_ * H_ * D_];
__device__ float g_or[(size_t)S_ * G_ * OR_];

// ---------------- helpers ----------------
__device__ __forceinline__ uint32_t f2tf(float x) {
    uint32_t r;
    asm("cvt.rna.tf32.f32 %0, %1;" : "=r"(r) : "f"(x));
    return r;
}
__device__ __forceinline__ float f2tf_f(float x) { return __uint_as_float(f2tf(x)); }

__device__ __forceinline__ void mma_tf32(float4& c, const uint32_t a[4], const uint32_t b[2]) {
    asm volatile(
        "mma.sync.aligned.m16n8k8.row.col.f32.tf32.tf32.f32 "
        "{%0,%1,%2,%3}, {%4,%5,%6,%7}, {%8,%9}, {%0,%1,%2,%3};\n"
        : "+f"(c.x), "+f"(c.y), "+f"(c.z), "+f"(c.w)
        : "r"(a[0]), "r"(a[1]), "r"(a[2]), "r"(a[3]), "r"(b[0]), "r"(b[1]));
}
__device__ __forceinline__ void ldsm4(uint32_t* d, uint32_t addr) {
    asm volatile("ldmatrix.sync.aligned.m8n8.x4.shared.b16 {%0,%1,%2,%3}, [%4];"
        : "=r"(d[0]), "=r"(d[1]), "=r"(d[2]), "=r"(d[3]) : "r"(addr));
}
#define CP16(dst, src) \
    asm volatile("cp.async.cg.shared.global [%0], [%1], 16;\n" :: "r"(dst), "l"(src))
#define CP_COMMIT() asm volatile("cp.async.commit_group;\n")
#define CP_WAIT1()  asm volatile("cp.async.wait_group 1;\n")

__device__ __forceinline__ float block_reduce(float v, bool is_max) {
    __shared__ float warp_res[8];
    __shared__ float result;
    __syncthreads();
    #pragma unroll
    for (int o = 16; o; o >>= 1) {
        float other = __shfl_xor_sync(0xffffffffu, v, o);
        v = is_max ? fmaxf(v, other) : (v + other);
    }
    if ((threadIdx.x & 31) == 0) warp_res[threadIdx.x >> 5] = v;
    __syncthreads();
    if (threadIdx.x == 0) {
        int nw = (blockDim.x + 31) >> 5;
        float r = warp_res[0];
        for (int i = 1; i < nw; i++) r = is_max ? fmaxf(r, warp_res[i]) : (r + warp_res[i]);
        result = r;
    }
    __syncthreads();
    return result;
}

__global__ __launch_bounds__(256) void round_tf32_k(const float* __restrict__ src,
                                                    float* __restrict__ dst, int n4) {
    int i = blockIdx.x * 256 + threadIdx.x;
    if (i < n4) {
        float4 v = ((const float4*)src)[i];
        v.x = f2tf_f(v.x); v.y = f2tf_f(v.y); v.z = f2tf_f(v.z); v.w = f2tf_f(v.w);
        ((float4*)dst)[i] = v;
    }
}

// ============================================================================
// TF32 GEMM TN (projections): C[M,N] = A[M,K] @ B[N,K]^T. Inputs pre-rounded.
// ============================================================================
__global__ __launch_bounds__(256, 2) void gemm_tn_tc(
    const float* __restrict__ A, const float* __restrict__ B, float* __restrict__ C,
    int K, int lda, int ldb, int ldc,
    long sA, long sB, long sC)
{
    int row0 = blockIdx.y * BM, col0 = blockIdx.x * BN;
    A += (long)blockIdx.z * sA;
    B += (long)blockIdx.z * sB;
    C += (long)blockIdx.z * sC;
    int niter = K / BK;

    extern __shared__ uint32_t smem[];
    uint32_t smem_b = (uint32_t)__cvta_generic_to_shared(smem);

    int tid = threadIdx.x, lane = tid & 31, warp = tid >> 5;
    int wm = warp >> 2, wn = warp & 3;

    int ldr = tid >> 3;
    int ldk = tid & 7;
    uint32_t dstA[4];
    const float* srcA[4];
    const float* srcB[4];
    #pragma unroll
    for (int i = 0; i < 4; i++) {
        int r = ldr + i * 32;
        dstA[i] = smem_b + ((((r << 3) + (ldk ^ (r & 7)))) << 4);
        srcA[i] = A + (long)(row0 + r) * lda + (ldk << 2);
        srcB[i] = B + (long)(col0 + r) * ldb + (ldk << 2);
    }

    int jr = ((lane >> 3) & 1) << 3;
    int jk = lane >> 4;
    int rr = lane & 7;
    uint32_t a_ad[4], b_ad[2];
    #pragma unroll
    for (int mt = 0; mt < 4; mt++) {
        int ar = wm * 64 + mt * 16 + jr + rr;
        a_ad[mt] = smem_b + (((ar << 3) + (jk ^ (ar & 7))) << 4);
    }
    #pragma unroll
    for (int ntp = 0; ntp < 2; ntp++) {
        int br = wn * 32 + ntp * 16 + jr + rr;
        b_ad[ntp] = smem_b + 16384 + (((br << 3) + (jk ^ (br & 7))) << 4);
    }

    float4 c[4][4];
    #pragma unroll
    for (int i = 0; i < 4; i++)
        #pragma unroll
        for (int j = 0; j < 4; j++) c[i][j] = make_float4(0.f, 0.f, 0.f, 0.f);

    #pragma unroll
    for (int i = 0; i < 4; i++) CP16(dstA[i], srcA[i]);
    #pragma unroll
    for (int i = 0; i < 4; i++) CP16(dstA[i] + 16384, srcB[i]);
    CP_COMMIT();
    if (niter > 1) {
        #pragma unroll
        for (int i = 0; i < 4; i++) CP16(dstA[i] + STAGE_BYTES, srcA[i] + BK);
        #pragma unroll
        for (int i = 0; i < 4; i++) CP16(dstA[i] + STAGE_BYTES + 16384, srcB[i] + BK);
    }
    CP_COMMIT();
    #pragma unroll
    for (int i = 0; i < 4; i++) { srcA[i] += 2 * BK; srcB[i] += 2 * BK; }

    int stage = 0;
    for (int k = 0; k < niter; k++) {
        CP_WAIT1();
        __syncthreads();

        if (k + 2 < niter) {
            int s2 = stage + 2; if (s2 >= 3) s2 -= 3;
            uint32_t so2 = (uint32_t)s2 * STAGE_BYTES;
            #pragma unroll
            for (int i = 0; i < 4; i++) CP16(dstA[i] + so2, srcA[i]);
            #pragma unroll
            for (int i = 0; i < 4; i++) CP16(dstA[i] + so2 + 16384, srcB[i]);
        }
        CP_COMMIT();
        #pragma unroll
        for (int i = 0; i < 4; i++) { srcA[i] += BK; srcB[i] += BK; }

        uint32_t so = (uint32_t)stage * STAGE_BYTES;
        uint32_t aa[4], bb[2];
        #pragma unroll
        for (int mt = 0; mt < 4; mt++) aa[mt] = a_ad[mt] + so;
        #pragma unroll
        for (int ntp = 0; ntp < 2; ntp++) bb[ntp] = b_ad[ntp] + so;

        #pragma unroll
        for (int ks = 0; ks < 4; ks++) {
            uint32_t af[4][4];
            #pragma unroll
            for (int mt = 0; mt < 4; mt++) ldsm4(af[mt], aa[mt] ^ (ks << 5));
            uint32_t bf[4][2];
            #pragma unroll
            for (int ntp = 0; ntp < 2; ntp++) {
                uint32_t t[4];
                ldsm4(t, bb[ntp] ^ (ks << 5));
                bf[ntp * 2][0]     = t[0];
                bf[ntp * 2 + 1][0] = t[1];
                bf[ntp * 2][1]     = t[2];
                bf[ntp * 2 + 1][1] = t[3];
            }
            #pragma unroll
            for (int mt = 0; mt < 4; mt++)
                #pragma unroll
                for (int nt = 0; nt < 4; nt++)
                    mma_tf32(c[mt][nt], af[mt], bf[nt]);
        }
        stage++; if (stage >= 3) stage -= 3;
    }

    #pragma unroll
    for (int mt = 0; mt < 4; mt++) {
        int m = row0 + wm * 64 + mt * 16 + (lane >> 2);
        #pragma unroll
        for (int nt = 0; nt < 4; nt++) {
            int n = col0 + wn * 32 + nt * 8 + ((lane & 3) << 1);
            *(float2*)(C + (long)m * ldc + n)       = make_float2(c[mt][nt].x, c[mt][nt].y);
            *(float2*)(C + (long)(m + 8) * ldc + n) = make_float2(c[mt][nt].z, c[mt][nt].w);
        }
    }
}

// ============================================================================
// Fused flash attention: per CTA = (head h, 64-row q tile qi), online softmax.
// S = Q@KV^T (tf32 mma), P=softmax chunk, O += P@KV via kvT. Sink folded at end.
// ============================================================================
__global__ __launch_bounds__(256, 1) void flash_attn(const float* __restrict__ sink) {
    int bx = blockIdx.x;
    int h  = bx & 15;
    int qi = 31 - (bx >> 4);          // heavy tiles first
    int q0 = qi * 64;
    int jn = qi + 1;

    extern __shared__ float smf[];
    uint32_t smb = (uint32_t)__cvta_generic_to_shared(smf);
    uint32_t smQ = smb, smKV = smb + F_KV * 4, smKVT = smb + F_KVT * 4, smP = smb + F_P * 4;

    int tid = threadIdx.x, lane = tid & 31, warp = tid >> 5;
    int wm = warp >> 2, wn = warp & 3;
    int jr = ((lane >> 3) & 1) << 3;
    int jk = lane >> 4;
    int rr = lane & 7;
    int g  = lane >> 2;       // row group 0..7
    int e2 = (lane & 3) << 1; // col pair base

    // ---- loader: Q (once) + KV_0 (group0), KVT_0 (group1) ----
    const float4* q4   = (const float4*)g_q + (size_t)q0 * 1024 + (size_t)h * 64;
    const float4* kv4  = (const float4*)g_kv;
    const float4* kvT4 = (const float4*)g_kvT;

    #pragma unroll
    for (int i = 0; i < 16; i++) {
        int id = tid + i * 256, row = id >> 6, k4 = id & 63;
        uint32_t dst = smQ + (uint32_t)((row << 6) + (k4 & 56) + ((k4 ^ row) & 7)) * 16;
        CP16(dst, q4 + (size_t)row * 1024 + k4);
    }
    #pragma unroll
    for (int i = 0; i < 16; i++) {
        int id = tid + i * 256, row = id >> 6, k4 = id & 63;
        uint32_t dst = smKV + (uint32_t)((row << 6) + (k4 & 56) + ((k4 ^ row) & 7)) * 16;
        CP16(dst, kv4 + (size_t)row * 64 + k4);
    }
    CP_COMMIT();
    #pragma unroll
    for (int i = 0; i < 16; i++) {
        int id = tid + i * 256, rd = id >> 4, k4 = id & 15;
        uint32_t dst = smKVT + (uint32_t)((rd << 4) + (k4 & 8) + ((k4 ^ rd) & 7)) * 16;
        CP16(dst, kvT4 + (size_t)rd * 512 + k4);
    }
    CP_COMMIT();

    // ---- fragment base addresses ----
    uint32_t aSb[2], bSb, aPb[2], bPVb[4];
    #pragma unroll
    for (int mt = 0; mt < 2; mt++) {
        int ar = wm * 32 + mt * 16 + jr + rr;
        aSb[mt] = smQ + (uint32_t)((ar << 6) + (jk ^ (ar & 7))) * 16;
        aPb[mt] = smP + (uint32_t)((ar << 4) + (jk ^ (ar & 7))) * 16;
    }
    {
        int br = wn * 16 + jr + rr;
        bSb = smKV + (uint32_t)((br << 6) + (jk ^ (br & 7))) * 16;
    }
    #pragma unroll
    for (int ntp = 0; ntp < 4; ntp++) {
        int br = wn * 64 + ntp * 16 + jr + rr;
        bPVb[ntp] = smKVT + (uint32_t)((br << 4) + (jk ^ (br & 7))) * 16;
    }

    // ---- state ----
    float4 cO[2][8];
    #pragma unroll
    for (int mt = 0; mt < 2; mt++)
        #pragma unroll
        for (int nt = 0; nt < 8; nt++) cO[mt][nt] = make_float4(0.f, 0.f, 0.f, 0.f);
    float mrow[4] = {-3.0e38f, -3.0e38f, -3.0e38f, -3.0e38f};
    float lrow[4] = {0.f, 0.f, 0.f, 0.f};

    for (int j = 0; j < jn; j++) {
        CP_WAIT1();
        __syncthreads();

        // ---- S = Q @ KV^T (64x64, K=256) ----
        float4 sS[2][2];
        #pragma unroll
        for (int mt = 0; mt < 2; mt++)
            #pragma unroll
            for (int nt = 0; nt < 2; nt++) sS[mt][nt] = make_float4(0.f, 0.f, 0.f, 0.f);

        #pragma unroll
        for (int cc = 0; cc < 8; cc++) {
            uint32_t ao = (uint32_t)cc * 128;
            #pragma unroll
            for (int ks = 0; ks < 4; ks++) {
                uint32_t af[2][4];
                #pragma unroll
                for (int mt = 0; mt < 2; mt++) ldsm4(af[mt], (aSb[mt] + ao) ^ (ks << 5));
                uint32_t tb[4];
                ldsm4(tb, (bSb + ao) ^ (ks << 5));
                uint32_t b0[2] = {tb[0], tb[2]}, b1[2] = {tb[1], tb[3]};
                #pragma unroll
                for (int mt = 0; mt < 2; mt++) {
                    mma_tf32(sS[mt][0], af[mt], b0);
                    mma_tf32(sS[mt][1], af[mt], b1);
                }
            }
        }

        // ---- scale + causal mask (only diagonal tile) ----
        #pragma unroll
        for (int mt = 0; mt < 2; mt++)
            #pragma unroll
            for (int nt = 0; nt < 2; nt++) {
                sS[mt][nt].x *= SCALE_; sS[mt][nt].y *= SCALE_;
                sS[mt][nt].z *= SCALE_; sS[mt][nt].w *= SCALE_;
            }
        if (j == qi) {
            #pragma unroll
            for (int mt = 0; mt < 2; mt++) {
                int r0 = wm * 32 + mt * 16 + g;       // local q row (half 0)
                #pragma unroll
                for (int nt = 0; nt < 2; nt++) {
                    int c0 = wn * 16 + nt * 8 + e2;   // local kv col
                    if (c0 > r0)     sS[mt][nt].x = -3.0e38f;
                    if (c0 + 1 > r0) sS[mt][nt].y = -3.0e38f;
                    if (c0 > r0 + 8)     sS[mt][nt].z = -3.0e38f;
                    if (c0 + 1 > r0 + 8) sS[mt][nt].w = -3.0e38f;
                }
            }
        }

        // ---- row max (16 cols -> warp -> 64 cols via smem) ----
        float rm[4];
        #pragma unroll
        for (int mt = 0; mt < 2; mt++) {
            rm[mt * 2 + 0] = fmaxf(fmaxf(sS[mt][0].x, sS[mt][0].y), fmaxf(sS[mt][1].x, sS[mt][1].y));
            rm[mt * 2 + 1] = fmaxf(fmaxf(sS[mt][0].z, sS[mt][0].w), fmaxf(sS[mt][1].z, sS[mt][1].w));
        }
        #pragma unroll
        for (int i = 0; i < 4; i++) {
            rm[i] = fmaxf(rm[i], __shfl_xor_sync(0xffffffffu, rm[i], 1));
            rm[i] = fmaxf(rm[i], __shfl_xor_sync(0xffffffffu, rm[i], 2));
        }
        #pragma unroll
        for (int i = 0; i < 4; i++) {
            int row = wm * 32 + (i >> 1) * 16 + g + (i & 1) * 8;
            smf[F_RED + wn * 64 + row] = rm[i];
        }
        __syncthreads();   // (A)

        // issue KV_{j+1} (sKV free after S-mma; sync A guarantees all warps done)
        if (j + 1 < jn) {
            const float4* kvs = kv4 + (size_t)(j + 1) * 64 * 64;
            #pragma unroll
            for (int i = 0; i < 16; i++) {
                int id = tid + i * 256, row = id >> 6, k4 = id & 63;
                uint32_t dst = smKV + (uint32_t)((row << 6) + (k4 & 56) + ((k4 ^ row) & 7)) * 16;
                CP16(dst, kvs + (size_t)row * 64 + k4);
            }
        }
        CP_COMMIT();

        float mnew[4], alpha[4];
        #pragma unroll
        for (int i = 0; i < 4; i++) {
            int row = wm * 32 + (i >> 1) * 16 + g + (i & 1) * 8;
            float tm = fmaxf(fmaxf(smf[F_RED + row], smf[F_RED + 64 + row]),
                             fmaxf(smf[F_RED + 128 + row], smf[F_RED + 192 + row]));
            mnew[i] = fmaxf(mrow[i], tm);
            alpha[i] = __expf(mrow[i] - mnew[i]);
            mrow[i] = mnew[i];
        }

        // ---- p = exp(s - m), row sums ----
        float ls[4];
        #pragma unroll
        for (int mt = 0; mt < 2; mt++) {
            #pragma unroll
            for (int nt = 0; nt < 2; nt++) {
                sS[mt][nt].x = __expf(sS[mt][nt].x - mnew[mt * 2 + 0]);
                sS[mt][nt].y = __expf(sS[mt][nt].y - mnew[mt * 2 + 0]);
                sS[mt][nt].z = __expf(sS[mt][nt].z - mnew[mt * 2 + 1]);
                sS[mt][nt].w = __expf(sS[mt][nt].w - mnew[mt * 2 + 1]);
            }
            ls[mt * 2 + 0] = sS[mt][0].x + sS[mt][0].y + sS[mt][1].x + sS[mt][1].y;
            ls[mt * 2 + 1] = sS[mt][0].z + sS[mt][0].w + sS[mt][1].z + sS[mt][1].w;
        }
        #pragma unroll
        for (int i = 0; i < 4; i++) {
            ls[i] += __shfl_xor_sync(0xffffffffu, ls[i], 1);
            ls[i] += __shfl_xor_sync(0xffffffffu, ls[i], 2);
        }
        #pragma unroll
        for (int i = 0; i < 4; i++) {
            int row = wm * 32 + (i >> 1) * 16 + g + (i & 1) * 8;
            smf[F_RED + 256 + wn * 64 + row] = ls[i];
        }
        __syncthreads();   // (B)
        #pragma unroll
        for (int i = 0; i < 4; i++) {
            int row = wm * 32 + (i >> 1) * 16 + g + (i & 1) * 8;
            float tl = smf[F_RED + 256 + row] + smf[F_RED + 256 + 64 + row] +
                       smf[F_RED + 256 + 128 + row] + smf[F_RED + 256 + 192 + row];
            lrow[i] = lrow[i] * alpha[i] + tl;
        }

        // ---- rescale O ----
        #pragma unroll
        for (int mt = 0; mt < 2; mt++)
            #pragma unroll
            for (int nt = 0; nt < 8; nt++) {
                cO[mt][nt].x *= alpha[mt * 2 + 0];
                cO[mt][nt].y *= alpha[mt * 2 + 0];
                cO[mt][nt].z *= alpha[mt * 2 + 1];
                cO[mt][nt].w *= alpha[mt * 2 + 1];
            }

        // ---- store P (tf32) to sP ----
        #pragma unroll
        for (int mt = 0; mt < 2; mt++)
            #pragma unroll
            for (int nt = 0; nt < 2; nt++) {
                int c = wn * 16 + nt * 8 + e2;
                int k4 = c >> 2;
                {
                    int row = wm * 32 + mt * 16 + g;
                    int fi = F_P + (((row << 4) + (k4 & 8) + ((k4 ^ row) & 7)) << 2) + (c & 2);
                    *(float2*)(smf + fi) = make_float2(f2tf_f(sS[mt][nt].x), f2tf_f(sS[mt][nt].y));
                }
                {
                    int row = wm * 32 + mt * 16 + g + 8;
                    int fi = F_P + (((row << 4) + (k4 & 8) + ((k4 ^ row) & 7)) << 2) + (c & 2);
                    *(float2*)(smf + fi) = make_float2(f2tf_f(sS[mt][nt].z), f2tf_f(sS[mt][nt].w));
                }
            }

        CP_WAIT1();        // KVT_j complete (KV_{j+1} still in flight)
        __syncthreads();   // (C)

        // ---- O += P @ KV  (A=P[64x64], B=KVT[256x64], K=64) ----
        #pragma unroll
        for (int kk = 0; kk < 8; kk++) {
            uint32_t xo = (uint32_t)((kk & 3) << 5);
            uint32_t ad = (uint32_t)((kk >> 2) << 7);
            uint32_t af[2][4];
            #pragma unroll
            for (int mt = 0; mt < 2; mt++) ldsm4(af[mt], (aPb[mt] + ad) ^ xo);
            #pragma unroll
            for (int ntp = 0; ntp < 4; ntp++) {
                uint32_t tb[4];
                ldsm4(tb, (bPVb[ntp] + ad) ^ xo);
                uint32_t b0[2] = {tb[0], tb[2]}, b1[2] = {tb[1], tb[3]};
                #pragma unroll
                for (int mt = 0; mt < 2; mt++) {
                    mma_tf32(cO[mt][ntp * 2 + 0], af[mt], b0);
                    mma_tf32(cO[mt][ntp * 2 + 1], af[mt], b1);
                }
            }
        }
        __syncthreads();   // (D)

        // issue KVT_{j+1}
        if (j + 1 < jn) {
            const float4* kvts = kvT4 + (size_t)(j + 1) * 16;
            #pragma unroll
            for (int i = 0; i < 16; i++) {
                int id = tid + i * 256, rd = id >> 4, k4 = id & 15;
                uint32_t dst = smKVT + (uint32_t)((rd << 4) + (k4 & 8) + ((k4 ^ rd) & 7)) * 16;
                CP16(dst, kvts + (size_t)rd * 512 + k4);
            }
        }
        CP_COMMIT();
    }

    // ---- finalize: sink + normalize, write O ----
    float snk = sink[h];
    float fac[4];
    #pragma unroll
    for (int i = 0; i < 4; i++) {
        float mf = fmaxf(mrow[i], snk);
        float af = __expf(mrow[i] - mf);
        float lf = lrow[i] * af + __expf(snk - mf);
        fac[i] = af / lf;
    }
    #pragma unroll
    for (int mt = 0; mt < 2; mt++) {
        int r = q0 + wm * 32 + mt * 16 + g;
        #pragma unroll
        for (int nt = 0; nt < 8; nt++) {
            int c = wn * 64 + nt * 8 + e2;
            float* p0 = g_o + (size_t)r * (H_ * D_) + (size_t)h * D_ + c;
            *(float2*)p0 = make_float2(cO[mt][nt].x * fac[mt * 2 + 0], cO[mt][nt].y * fac[mt * 2 + 0]);
            *(float2*)(p0 + (size_t)8 * (H_ * D_)) =
                make_float2(cO[mt][nt].z * fac[mt * 2 + 1], cO[mt][nt].w * fac[mt * 2 + 1]);
        }
    }
}

// ---------------- elementwise / norm kernels ----------------
__global__ void cos_sin_k(const float* __restrict__ freqs) {
    int i = blockIdx.x * blockDim.x + threadIdx.x;
    if (i < S_ * RH_) {
        float f = freqs[i];
        g_cos[i] = cosf(f);
        g_sin[i] = sinf(f);
    }
}

__global__ __launch_bounds__(256) void rms_qa(const float* __restrict__ w) {
    int s = blockIdx.x;
    float* row = g_qa + (long)s * QL_;
    float ss = 0.f;
    for (int i = threadIdx.x; i < QL_; i += 256) { float v = row[i]; ss += v * v; }
    ss = block_reduce(ss, false);
    float sc = rsqrtf(ss / QL_ + EPS_);
    for (int i = threadIdx.x; i < QL_; i += 256) row[i] = f2tf_f(row[i] * sc * w[i]);
}

__global__ __launch_bounds__(256) void q_post() {
    int s = blockIdx.x, h = blockIdx.y;
    float* row = g_q + (size_t)s * (H_ * D_) + (size_t)h * D_;
    int d = threadIdx.x;
    float v = row[d];
    float ss = block_reduce(v * v, false);
    float sc = rsqrtf(ss / D_ + EPS_);
    __shared__ float sh[D_];
    sh[d] = v * sc;
    __syncthreads();
    float out;
    if (d < NOPE_) out = sh[d];
    else {
        int p = d - NOPE_, i = p >> 1;
        float cc = g_cos[s * RH_ + i], sn = g_sin[s * RH_ + i];
        float x1 = sh[NOPE_ + (i << 1)], x2 = sh[NOPE_ + (i << 1) + 1];
        out = (p & 1) ? (x1 * sn + x2 * cc) : (x1 * cc - x2 * sn);
    }
    row[d] = f2tf_f(out);
}

__global__ __launch_bounds__(256) void kv_post(const float* __restrict__ w) {
    int s = blockIdx.x;
    float* row = g_kv + (long)s * D_;
    int d = threadIdx.x;
    float v = row[d];
    float ss = block_reduce(v * v, false);
    float sc = rsqrtf(ss / D_ + EPS_);
    __shared__ float sh[D_];
    sh[d] = v * sc * w[d];
    __syncthreads();
    float out;
    if (d < NOPE_) out = sh[d];
    else {
        int p = d - NOPE_, i = p >> 1;
        float cc = g_cos[s * RH_ + i], sn = g_sin[s * RH_ + i];
        float x1 = sh[NOPE_ + (i << 1)], x2 = sh[NOPE_ + (i << 1) + 1];
        out = (p & 1) ? (x1 * sn + x2 * cc) : (x1 * cc - x2 * sn);
    }
    row[d] = f2tf_f(out);
}

__global__ __launch_bounds__(256) void transpose_kv() {
    __shared__ float t[32][33];
    int x = threadIdx.x & 31, y = threadIdx.x >> 5;
    #pragma unroll
    for (int i = 0; i < 4; i++) {
        int trow = blockIdx.x * 32 + y + i * 8;
        t[y + i * 8][x] = g_kv[(size_t)trow * D_ + blockIdx.y * 32 + x];
    }
    __syncthreads();
    #pragma unroll
    for (int i = 0; i < 4; i++) {
        int drow = blockIdx.y * 32 + y + i * 8;
        g_kvT[(size_t)drow * S_ + blockIdx.x * 32 + x] = t[x][y + i * 8];
    }
}

__global__ __launch_bounds__(256) void o_post() {
    int s = blockIdx.x, h = blockIdx.y;
    float* row = g_o + (size_t)s * (H_ * D_) + (size_t)h * D_;
    int d = threadIdx.x;
    __shared__ float sh[R_];
    float v = row[d];
    if (d >= NOPE_) sh[d - NOPE_] = v;
    __syncthreads();
    float out;
    if (d < NOPE_) out = v;
    else {
        int p = d - NOPE_, i = p >> 1;
        float cc = g_cos[s * RH_ + i], sn = g_sin[s * RH_ + i];
        float x1 = sh[i << 1], x2 = sh[(i << 1) + 1];
        out = (p & 1) ? (x2 * cc - x1 * sn) : (x1 * cc + x2 * sn);
    }
    row[d] = f2tf_f(out);
}

__global__ __launch_bounds__(256) void round_or_k() {
    int i = blockIdx.x * 256 + threadIdx.x;
    float4 v = ((const float4*)g_or)[i];
    v.x = f2tf_f(v.x); v.y = f2tf_f(v.y); v.z = f2tf_f(v.z); v.w = f2tf_f(v.w);
    ((float4*)g_or)[i] = v;
}

// ---------------- launch ----------------
extern "C" void kernel_launch(void* const* d_in, const int* in_sizes, int n_in,
                              void* d_out, int out_size) {
    const float* x        = (const float*)d_in[0];
    const float* freqs    = (const float*)d_in[1];
    const float* wq_a     = (const float*)d_in[2];
    const float* q_norm_w = (const float*)d_in[3];
    const float* wq_b     = (const float*)d_in[4];
    const float* wkv      = (const float*)d_in[5];
    const float* kv_norm_w= (const float*)d_in[6];
    const float* wo_a_w   = (const float*)d_in[7];
    const float* wo_b     = (const float*)d_in[8];
    const float* sink     = (const float*)d_in[9];
    float* out = (float*)d_out;

    float *p_x, *p_wqa, *p_wqb, *p_wkv, *p_woa, *p_wob;
    float *p_qa, *p_q, *p_o, *p_or;
    cudaGetSymbolAddress((void**)&p_x,   g_x);
    cudaGetSymbolAddress((void**)&p_wqa, g_wqa);
    cudaGetSymbolAddress((void**)&p_wqb, g_wqb);
    cudaGetSymbolAddress((void**)&p_wkv, g_wkv);
    cudaGetSymbolAddress((void**)&p_woa, g_woa);
    cudaGetSymbolAddress((void**)&p_wob, g_wob);
    cudaGetSymbolAddress((void**)&p_qa,  g_qa);
    cudaGetSymbolAddress((void**)&p_q,   g_q);
    cudaGetSymbolAddress((void**)&p_o,   g_o);
    cudaGetSymbolAddress((void**)&p_or,  g_or);

    float *p_kv;
    cudaGetSymbolAddress((void**)&p_kv, g_kv);

    cudaFuncSetAttribute(gemm_tn_tc, cudaFuncAttributeMaxDynamicSharedMemorySize, GEMM_SMEM);
    cudaFuncSetAttribute(flash_attn, cudaFuncAttributeMaxDynamicSharedMemorySize, FLASH_SMEM);

    cos_sin_k<<<(S_ * RH_ + 255) / 256, 256>>>(freqs);

    round_tf32_k<<<(S_ * HID_ / 4 + 255) / 256, 256>>>(x, p_x, S_ * HID_ / 4);
    round_tf32_k<<<(QL_ * HID_ / 4 + 255) / 256, 256>>>(wq_a, p_wqa, QL_ * HID_ / 4);
    round_tf32_k<<<(H_ * D_ * QL_ / 4 + 255) / 256, 256>>>(wq_b, p_wqb, H_ * D_ * QL_ / 4);
    round_tf32_k<<<(D_ * HID_ / 4 + 255) / 256, 256>>>(wkv, p_wkv, D_ * HID_ / 4);
    round_tf32_k<<<(G_ * OR_ * 1024 / 4 + 255) / 256, 256>>>(wo_a_w, p_woa, G_ * OR_ * 1024 / 4);
    round_tf32_k<<<(HID_ * G_ * OR_ / 4 + 255) / 256, 256>>>(wo_b, p_wob, HID_ * G_ * OR_ / 4);

    // q_a = x @ wq_a^T
    gemm_tn_tc<<<dim3(QL_ / BN, S_ / BM, 1), 256, GEMM_SMEM>>>(p_x, p_wqa, p_qa,
        HID_, HID_, HID_, QL_, 0, 0, 0);
    rms_qa<<<S_, 256>>>(q_norm_w);

    // q = qa @ wq_b^T
    gemm_tn_tc<<<dim3((H_ * D_) / BN, S_ / BM, 1), 256, GEMM_SMEM>>>(p_qa, p_wqb, p_q,
        QL_, QL_, QL_, H_ * D_, 0, 0, 0);
    q_post<<<dim3(S_, H_), 256>>>();

    // kv = x @ wkv^T
    gemm_tn_tc<<<dim3(D_ / BN, S_ / BM, 1), 256, GEMM_SMEM>>>(p_x, p_wkv, p_kv,
        HID_, HID_, HID_, D_, 0, 0, 0);
    kv_post<<<S_, 256>>>(kv_norm_w);
    transpose_kv<<<dim3(S_ / 32, D_ / 32), 256>>>();

    // fused attention (scores + softmax + PV)
    flash_attn<<<512, 256, FLASH_SMEM>>>(sink);

    o_post<<<dim3(S_, H_), 256>>>();

    // grouped wo_a
    gemm_tn_tc<<<dim3(OR_ / BN, S_ / BM, G_), 256, GEMM_SMEM>>>(p_o, p_woa, p_or,
        (H_ / G_) * D_, H_ * D_, (H_ / G_) * D_, G_ * OR_,
        (long)(H_ / G_) * D_, (long)OR_ * (H_ / G_) * D_, (long)OR_);
    round_or_k<<<(S_ * G_ * OR_ / 4) / 256, 256>>>();

    // out = o_r @ wo_b^T
    gemm_tn_tc<<<dim3(HID_ / BN, S_ / BM, 1), 256, GEMM_SMEM>>>(p_or, p_wob, out,
        G_ * OR_, G_ * OR_, G_ * OR_, HID_, 0, 0, 0);
}

// round 8
// speedup vs baseline: 2.1732x; 1.0434x over previous
#include <cuda_runtime.h>
#include <cstdint>

#define S_    2048
#define HID_  2048
#define H_    16
#define D_    256
#define R_    64
#define RH_   32          // R/2
#define NOPE_ 192
#define QL_   1024
#define OR_   512
#define G_    4
#define EPS_  1e-6f
#define SCALE_ 0.0625f    // 256^-0.5

#define BM 128
#define BN 128
#define BK 32
#define STAGE_BYTES 32768
#define GEMM_SMEM (3 * STAGE_BYTES)

// flash smem (floats): Q 16384 | KV 16384 | KVT 16384 | P 4096 | RED 512
#define F_Q   0
#define F_KV  16384
#define F_KVT 32768
#define F_P   49152
#define F_RED 53248
#define FLASH_SMEM ((53248 + 512) * 4)

// ---------------- scratch ----------------
__device__ float g_cos[S_ * RH_];
__device__ float g_sin[S_ * RH_];
__device__ float g_x[(size_t)S_ * HID_];
__device__ float g_wqa[(size_t)QL_ * HID_];
__device__ float g_wqb[(size_t)H_ * D_ * QL_];
__device__ float g_wkv[(size_t)D_ * HID_];
__device__ float g_woa[(size_t)G_ * OR_ * 1024];
__device__ float g_wob[(size_t)HID_ * G_ * OR_];
__device__ float g_qa[(size_t)S_ * QL_];
__device__ float g_q[(size_t)S_ * H_ * D_];
__device__ float g_kv[(size_t)S_ * D_];
__device__ float g_kvT[(size_t)D_ * S_];
__device__ float g_o[(size_t)S_ * H_ * D_];
__device__ float g_or[(size_t)S_ * G_ * OR_];
__device__ float g_part[(size_t)8 * 1024 * 1024];   // 32 MB split-K partials

// ---------------- helpers ----------------
__device__ __forceinline__ uint32_t f2tf(float x) {
    uint32_t r;
    asm("cvt.rna.tf32.f32 %0, %1;" : "=r"(r) : "f"(x));
    return r;
}
__device__ __forceinline__ float f2tf_f(float x) { return __uint_as_float(f2tf(x)); }

__device__ __forceinline__ void mma_tf32(float4& c, const uint32_t a[4], const uint32_t b[2]) {
    asm volatile(
        "mma.sync.aligned.m16n8k8.row.col.f32.tf32.tf32.f32 "
        "{%0,%1,%2,%3}, {%4,%5,%6,%7}, {%8,%9}, {%0,%1,%2,%3};\n"
        : "+f"(c.x), "+f"(c.y), "+f"(c.z), "+f"(c.w)
        : "r"(a[0]), "r"(a[1]), "r"(a[2]), "r"(a[3]), "r"(b[0]), "r"(b[1]));
}
__device__ __forceinline__ void ldsm4(uint32_t* d, uint32_t addr) {
    asm volatile("ldmatrix.sync.aligned.m8n8.x4.shared.b16 {%0,%1,%2,%3}, [%4];"
        : "=r"(d[0]), "=r"(d[1]), "=r"(d[2]), "=r"(d[3]) : "r"(addr));
}
#define CP16(dst, src) \
    asm volatile("cp.async.cg.shared.global [%0], [%1], 16;\n" :: "r"(dst), "l"(src))
#define CP_COMMIT() asm volatile("cp.async.commit_group;\n")
#define CP_WAIT1()  asm volatile("cp.async.wait_group 1;\n")

__device__ __forceinline__ float block_reduce(float v, bool is_max) {
    __shared__ float warp_res[8];
    __shared__ float result;
    __syncthreads();
    #pragma unroll
    for (int o = 16; o; o >>= 1) {
        float other = __shfl_xor_sync(0xffffffffu, v, o);
        v = is_max ? fmaxf(v, other) : (v + other);
    }
    if ((threadIdx.x & 31) == 0) warp_res[threadIdx.x >> 5] = v;
    __syncthreads();
    if (threadIdx.x == 0) {
        int nw = (blockDim.x + 31) >> 5;
        float r = warp_res[0];
        for (int i = 1; i < nw; i++) r = is_max ? fmaxf(r, warp_res[i]) : (r + warp_res[i]);
        result = r;
    }
    __syncthreads();
    return result;
}

__global__ __launch_bounds__(256) void round_tf32_k(const float* __restrict__ src,
                                                    float* __restrict__ dst, int n4) {
    int i = blockIdx.x * 256 + threadIdx.x;
    if (i < n4) {
        float4 v = ((const float4*)src)[i];
        v.x = f2tf_f(v.x); v.y = f2tf_f(v.y); v.z = f2tf_f(v.z); v.w = f2tf_f(v.w);
        ((float4*)dst)[i] = v;
    }
}

// deterministic fixed-order split-K reduction: dst[i] = sum_p src[i + p*stride4]
__global__ __launch_bounds__(256) void reduce_parts_k(const float* __restrict__ src,
                                                      float* __restrict__ dst,
                                                      int n4, long stride4, int parts) {
    int i = blockIdx.x * 256 + threadIdx.x;
    if (i >= n4) return;
    float4 a = ((const float4*)src)[i];
    for (int p = 1; p < parts; p++) {
        float4 b = ((const float4*)src)[i + (size_t)p * stride4];
        a.x += b.x; a.y += b.y; a.z += b.z; a.w += b.w;
    }
    ((float4*)dst)[i] = a;
}

// ============================================================================
// TF32 GEMM TN: C[M,N] = A[M,K] @ B[N,K]^T. Inputs pre-rounded tf32.
// blockIdx.z batching via strides doubles as split-K (sA=sB=Kchunk, sC=M*N).
// ============================================================================
__global__ __launch_bounds__(256, 2) void gemm_tn_tc(
    const float* __restrict__ A, const float* __restrict__ B, float* __restrict__ C,
    int K, int lda, int ldb, int ldc,
    long sA, long sB, long sC)
{
    int row0 = blockIdx.y * BM, col0 = blockIdx.x * BN;
    A += (long)blockIdx.z * sA;
    B += (long)blockIdx.z * sB;
    C += (long)blockIdx.z * sC;
    int niter = K / BK;

    extern __shared__ uint32_t smem[];
    uint32_t smem_b = (uint32_t)__cvta_generic_to_shared(smem);

    int tid = threadIdx.x, lane = tid & 31, warp = tid >> 5;
    int wm = warp >> 2, wn = warp & 3;

    int ldr = tid >> 3;
    int ldk = tid & 7;
    uint32_t dstA[4];
    const float* srcA[4];
    const float* srcB[4];
    #pragma unroll
    for (int i = 0; i < 4; i++) {
        int r = ldr + i * 32;
        dstA[i] = smem_b + ((((r << 3) + (ldk ^ (r & 7)))) << 4);
        srcA[i] = A + (long)(row0 + r) * lda + (ldk << 2);
        srcB[i] = B + (long)(col0 + r) * ldb + (ldk << 2);
    }

    int jr = ((lane >> 3) & 1) << 3;
    int jk = lane >> 4;
    int rr = lane & 7;
    uint32_t a_ad[4], b_ad[2];
    #pragma unroll
    for (int mt = 0; mt < 4; mt++) {
        int ar = wm * 64 + mt * 16 + jr + rr;
        a_ad[mt] = smem_b + (((ar << 3) + (jk ^ (ar & 7))) << 4);
    }
    #pragma unroll
    for (int ntp = 0; ntp < 2; ntp++) {
        int br = wn * 32 + ntp * 16 + jr + rr;
        b_ad[ntp] = smem_b + 16384 + (((br << 3) + (jk ^ (br & 7))) << 4);
    }

    float4 c[4][4];
    #pragma unroll
    for (int i = 0; i < 4; i++)
        #pragma unroll
        for (int j = 0; j < 4; j++) c[i][j] = make_float4(0.f, 0.f, 0.f, 0.f);

    #pragma unroll
    for (int i = 0; i < 4; i++) CP16(dstA[i], srcA[i]);
    #pragma unroll
    for (int i = 0; i < 4; i++) CP16(dstA[i] + 16384, srcB[i]);
    CP_COMMIT();
    if (niter > 1) {
        #pragma unroll
        for (int i = 0; i < 4; i++) CP16(dstA[i] + STAGE_BYTES, srcA[i] + BK);
        #pragma unroll
        for (int i = 0; i < 4; i++) CP16(dstA[i] + STAGE_BYTES + 16384, srcB[i] + BK);
    }
    CP_COMMIT();
    #pragma unroll
    for (int i = 0; i < 4; i++) { srcA[i] += 2 * BK; srcB[i] += 2 * BK; }

    int stage = 0;
    for (int k = 0; k < niter; k++) {
        CP_WAIT1();
        __syncthreads();

        if (k + 2 < niter) {
            int s2 = stage + 2; if (s2 >= 3) s2 -= 3;
            uint32_t so2 = (uint32_t)s2 * STAGE_BYTES;
            #pragma unroll
            for (int i = 0; i < 4; i++) CP16(dstA[i] + so2, srcA[i]);
            #pragma unroll
            for (int i = 0; i < 4; i++) CP16(dstA[i] + so2 + 16384, srcB[i]);
        }
        CP_COMMIT();
        #pragma unroll
        for (int i = 0; i < 4; i++) { srcA[i] += BK; srcB[i] += BK; }

        uint32_t so = (uint32_t)stage * STAGE_BYTES;
        uint32_t aa[4], bb[2];
        #pragma unroll
        for (int mt = 0; mt < 4; mt++) aa[mt] = a_ad[mt] + so;
        #pragma unroll
        for (int ntp = 0; ntp < 2; ntp++) bb[ntp] = b_ad[ntp] + so;

        #pragma unroll
        for (int ks = 0; ks < 4; ks++) {
            uint32_t af[4][4];
            #pragma unroll
            for (int mt = 0; mt < 4; mt++) ldsm4(af[mt], aa[mt] ^ (ks << 5));
            uint32_t bf[4][2];
            #pragma unroll
            for (int ntp = 0; ntp < 2; ntp++) {
                uint32_t t[4];
                ldsm4(t, bb[ntp] ^ (ks << 5));
                bf[ntp * 2][0]     = t[0];
                bf[ntp * 2 + 1][0] = t[1];
                bf[ntp * 2][1]     = t[2];
                bf[ntp * 2 + 1][1] = t[3];
            }
            #pragma unroll
            for (int mt = 0; mt < 4; mt++)
                #pragma unroll
                for (int nt = 0; nt < 4; nt++)
                    mma_tf32(c[mt][nt], af[mt], bf[nt]);
        }
        stage++; if (stage >= 3) stage -= 3;
    }

    #pragma unroll
    for (int mt = 0; mt < 4; mt++) {
        int m = row0 + wm * 64 + mt * 16 + (lane >> 2);
        #pragma unroll
        for (int nt = 0; nt < 4; nt++) {
            int n = col0 + wn * 32 + nt * 8 + ((lane & 3) << 1);
            *(float2*)(C + (long)m * ldc + n)       = make_float2(c[mt][nt].x, c[mt][nt].y);
            *(float2*)(C + (long)(m + 8) * ldc + n) = make_float2(c[mt][nt].z, c[mt][nt].w);
        }
    }
}

// ============================================================================
// Fused flash attention: per CTA = (head h, 64-row q tile qi), online softmax.
// ============================================================================
__global__ __launch_bounds__(256, 1) void flash_attn(const float* __restrict__ sink) {
    int bx = blockIdx.x;
    int h  = bx & 15;
    int qi = 31 - (bx >> 4);          // heavy tiles first
    int q0 = qi * 64;
    int jn = qi + 1;

    extern __shared__ float smf[];
    uint32_t smb = (uint32_t)__cvta_generic_to_shared(smf);
    uint32_t smQ = smb, smKV = smb + F_KV * 4, smKVT = smb + F_KVT * 4, smP = smb + F_P * 4;

    int tid = threadIdx.x, lane = tid & 31, warp = tid >> 5;
    int wm = warp >> 2, wn = warp & 3;
    int jr = ((lane >> 3) & 1) << 3;
    int jk = lane >> 4;
    int rr = lane & 7;
    int g  = lane >> 2;
    int e2 = (lane & 3) << 1;

    const float4* q4   = (const float4*)g_q + (size_t)q0 * 1024 + (size_t)h * 64;
    const float4* kv4  = (const float4*)g_kv;
    const float4* kvT4 = (const float4*)g_kvT;

    #pragma unroll
    for (int i = 0; i < 16; i++) {
        int id = tid + i * 256, row = id >> 6, k4 = id & 63;
        uint32_t dst = smQ + (uint32_t)((row << 6) + (k4 & 56) + ((k4 ^ row) & 7)) * 16;
        CP16(dst, q4 + (size_t)row * 1024 + k4);
    }
    #pragma unroll
    for (int i = 0; i < 16; i++) {
        int id = tid + i * 256, row = id >> 6, k4 = id & 63;
        uint32_t dst = smKV + (uint32_t)((row << 6) + (k4 & 56) + ((k4 ^ row) & 7)) * 16;
        CP16(dst, kv4 + (size_t)row * 64 + k4);
    }
    CP_COMMIT();
    #pragma unroll
    for (int i = 0; i < 16; i++) {
        int id = tid + i * 256, rd = id >> 4, k4 = id & 15;
        uint32_t dst = smKVT + (uint32_t)((rd << 4) + (k4 & 8) + ((k4 ^ rd) & 7)) * 16;
        CP16(dst, kvT4 + (size_t)rd * 512 + k4);
    }
    CP_COMMIT();

    uint32_t aSb[2], bSb, aPb[2], bPVb[4];
    #pragma unroll
    for (int mt = 0; mt < 2; mt++) {
        int ar = wm * 32 + mt * 16 + jr + rr;
        aSb[mt] = smQ + (uint32_t)((ar << 6) + (jk ^ (ar & 7))) * 16;
        aPb[mt] = smP + (uint32_t)((ar << 4) + (jk ^ (ar & 7))) * 16;
    }
    {
        int br = wn * 16 + jr + rr;
        bSb = smKV + (uint32_t)((br << 6) + (jk ^ (br & 7))) * 16;
    }
    #pragma unroll
    for (int ntp = 0; ntp < 4; ntp++) {
        int br = wn * 64 + ntp * 16 + jr + rr;
        bPVb[ntp] = smKVT + (uint32_t)((br << 4) + (jk ^ (br & 7))) * 16;
    }

    float4 cO[2][8];
    #pragma unroll
    for (int mt = 0; mt < 2; mt++)
        #pragma unroll
        for (int nt = 0; nt < 8; nt++) cO[mt][nt] = make_float4(0.f, 0.f, 0.f, 0.f);
    float mrow[4] = {-3.0e38f, -3.0e38f, -3.0e38f, -3.0e38f};
    float lrow[4] = {0.f, 0.f, 0.f, 0.f};

    for (int j = 0; j < jn; j++) {
        CP_WAIT1();
        __syncthreads();

        float4 sS[2][2];
        #pragma unroll
        for (int mt = 0; mt < 2; mt++)
            #pragma unroll
            for (int nt = 0; nt < 2; nt++) sS[mt][nt] = make_float4(0.f, 0.f, 0.f, 0.f);

        #pragma unroll
        for (int cc = 0; cc < 8; cc++) {
            uint32_t ao = (uint32_t)cc * 128;
            #pragma unroll
            for (int ks = 0; ks < 4; ks++) {
                uint32_t af[2][4];
                #pragma unroll
                for (int mt = 0; mt < 2; mt++) ldsm4(af[mt], (aSb[mt] + ao) ^ (ks << 5));
                uint32_t tb[4];
                ldsm4(tb, (bSb + ao) ^ (ks << 5));
                uint32_t b0[2] = {tb[0], tb[2]}, b1[2] = {tb[1], tb[3]};
                #pragma unroll
                for (int mt = 0; mt < 2; mt++) {
                    mma_tf32(sS[mt][0], af[mt], b0);
                    mma_tf32(sS[mt][1], af[mt], b1);
                }
            }
        }

        #pragma unroll
        for (int mt = 0; mt < 2; mt++)
            #pragma unroll
            for (int nt = 0; nt < 2; nt++) {
                sS[mt][nt].x *= SCALE_; sS[mt][nt].y *= SCALE_;
                sS[mt][nt].z *= SCALE_; sS[mt][nt].w *= SCALE_;
            }
        if (j == qi) {
            #pragma unroll
            for (int mt = 0; mt < 2; mt++) {
                int r0 = wm * 32 + mt * 16 + g;
                #pragma unroll
                for (int nt = 0; nt < 2; nt++) {
                    int c0 = wn * 16 + nt * 8 + e2;
                    if (c0 > r0)     sS[mt][nt].x = -3.0e38f;
                    if (c0 + 1 > r0) sS[mt][nt].y = -3.0e38f;
                    if (c0 > r0 + 8)     sS[mt][nt].z = -3.0e38f;
                    if (c0 + 1 > r0 + 8) sS[mt][nt].w = -3.0e38f;
                }
            }
        }

        float rm[4];
        #pragma unroll
        for (int mt = 0; mt < 2; mt++) {
            rm[mt * 2 + 0] = fmaxf(fmaxf(sS[mt][0].x, sS[mt][0].y), fmaxf(sS[mt][1].x, sS[mt][1].y));
            rm[mt * 2 + 1] = fmaxf(fmaxf(sS[mt][0].z, sS[mt][0].w), fmaxf(sS[mt][1].z, sS[mt][1].w));
        }
        #pragma unroll
        for (int i = 0; i < 4; i++) {
            rm[i] = fmaxf(rm[i], __shfl_xor_sync(0xffffffffu, rm[i], 1));
            rm[i] = fmaxf(rm[i], __shfl_xor_sync(0xffffffffu, rm[i], 2));
        }
        #pragma unroll
        for (int i = 0; i < 4; i++) {
            int row = wm * 32 + (i >> 1) * 16 + g + (i & 1) * 8;
            smf[F_RED + wn * 64 + row] = rm[i];
        }
        __syncthreads();   // (A)

        if (j + 1 < jn) {
            const float4* kvs = kv4 + (size_t)(j + 1) * 64 * 64;
            #pragma unroll
            for (int i = 0; i < 16; i++) {
                int id = tid + i * 256, row = id >> 6, k4 = id & 63;
                uint32_t dst = smKV + (uint32_t)((row << 6) + (k4 & 56) + ((k4 ^ row) & 7)) * 16;
                CP16(dst, kvs + (size_t)row * 64 + k4);
            }
        }
        CP_COMMIT();

        float mnew[4], alpha[4];
        #pragma unroll
        for (int i = 0; i < 4; i++) {
            int row = wm * 32 + (i >> 1) * 16 + g + (i & 1) * 8;
            float tm = fmaxf(fmaxf(smf[F_RED + row], smf[F_RED + 64 + row]),
                             fmaxf(smf[F_RED + 128 + row], smf[F_RED + 192 + row]));
            mnew[i] = fmaxf(mrow[i], tm);
            alpha[i] = __expf(mrow[i] - mnew[i]);
            mrow[i] = mnew[i];
        }

        float ls[4];
        #pragma unroll
        for (int mt = 0; mt < 2; mt++) {
            #pragma unroll
            for (int nt = 0; nt < 2; nt++) {
                sS[mt][nt].x = __expf(sS[mt][nt].x - mnew[mt * 2 + 0]);
                sS[mt][nt].y = __expf(sS[mt][nt].y - mnew[mt * 2 + 0]);
                sS[mt][nt].z = __expf(sS[mt][nt].z - mnew[mt * 2 + 1]);
                sS[mt][nt].w = __expf(sS[mt][nt].w - mnew[mt * 2 + 1]);
            }
            ls[mt * 2 + 0] = sS[mt][0].x + sS[mt][0].y + sS[mt][1].x + sS[mt][1].y;
            ls[mt * 2 + 1] = sS[mt][0].z + sS[mt][0].w + sS[mt][1].z + sS[mt][1].w;
        }
        #pragma unroll
        for (int i = 0; i < 4; i++) {
            ls[i] += __shfl_xor_sync(0xffffffffu, ls[i], 1);
            ls[i] += __shfl_xor_sync(0xffffffffu, ls[i], 2);
        }
        #pragma unroll
        for (int i = 0; i < 4; i++) {
            int row = wm * 32 + (i >> 1) * 16 + g + (i & 1) * 8;
            smf[F_RED + 256 + wn * 64 + row] = ls[i];
        }
        __syncthreads();   // (B)
        #pragma unroll
        for (int i = 0; i < 4; i++) {
            int row = wm * 32 + (i >> 1) * 16 + g + (i & 1) * 8;
            float tl = smf[F_RED + 256 + row] + smf[F_RED + 256 + 64 + row] +
                       smf[F_RED + 256 + 128 + row] + smf[F_RED + 256 + 192 + row];
            lrow[i] = lrow[i] * alpha[i] + tl;
        }

        #pragma unroll
        for (int mt = 0; mt < 2; mt++)
            #pragma unroll
            for (int nt = 0; nt < 8; nt++) {
                cO[mt][nt].x *= alpha[mt * 2 + 0];
                cO[mt][nt].y *= alpha[mt * 2 + 0];
                cO[mt][nt].z *= alpha[mt * 2 + 1];
                cO[mt][nt].w *= alpha[mt * 2 + 1];
            }

        #pragma unroll
        for (int mt = 0; mt < 2; mt++)
            #pragma unroll
            for (int nt = 0; nt < 2; nt++) {
                int c = wn * 16 + nt * 8 + e2;
                int k4 = c >> 2;
                {
                    int row = wm * 32 + mt * 16 + g;
                    int fi = F_P + (((row << 4) + (k4 & 8) + ((k4 ^ row) & 7)) << 2) + (c & 2);
                    *(float2*)(smf + fi) = make_float2(f2tf_f(sS[mt][nt].x), f2tf_f(sS[mt][nt].y));
                }
                {
                    int row = wm * 32 + mt * 16 + g + 8;
                    int fi = F_P + (((row << 4) + (k4 & 8) + ((k4 ^ row) & 7)) << 2) + (c & 2);
                    *(float2*)(smf + fi) = make_float2(f2tf_f(sS[mt][nt].z), f2tf_f(sS[mt][nt].w));
                }
            }

        CP_WAIT1();
        __syncthreads();   // (C)

        #pragma unroll
        for (int kk = 0; kk < 8; kk++) {
            uint32_t xo = (uint32_t)((kk & 3) << 5);
            uint32_t ad = (uint32_t)((kk >> 2) << 7);
            uint32_t af[2][4];
            #pragma unroll
            for (int mt = 0; mt < 2; mt++) ldsm4(af[mt], (aPb[mt] + ad) ^ xo);
            #pragma unroll
            for (int ntp = 0; ntp < 4; ntp++) {
                uint32_t tb[4];
                ldsm4(tb, (bPVb[ntp] + ad) ^ xo);
                uint32_t b0[2] = {tb[0], tb[2]}, b1[2] = {tb[1], tb[3]};
                #pragma unroll
                for (int mt = 0; mt < 2; mt++) {
                    mma_tf32(cO[mt][ntp * 2 + 0], af[mt], b0);
                    mma_tf32(cO[mt][ntp * 2 + 1], af[mt], b1);
                }
            }
        }
        __syncthreads();   // (D)

        if (j + 1 < jn) {
            const float4* kvts = kvT4 + (size_t)(j + 1) * 16;
            #pragma unroll
            for (int i = 0; i < 16; i++) {
                int id = tid + i * 256, rd = id >> 4, k4 = id & 15;
                uint32_t dst = smKVT + (uint32_t)((rd << 4) + (k4 & 8) + ((k4 ^ rd) & 7)) * 16;
                CP16(dst, kvts + (size_t)rd * 512 + k4);
            }
        }
        CP_COMMIT();
    }

    float snk = sink[h];
    float fac[4];
    #pragma unroll
    for (int i = 0; i < 4; i++) {
        float mf = fmaxf(mrow[i], snk);
        float af = __expf(mrow[i] - mf);
        float lf = lrow[i] * af + __expf(snk - mf);
        fac[i] = af / lf;
    }
    #pragma unroll
    for (int mt = 0; mt < 2; mt++) {
        int r = q0 + wm * 32 + mt * 16 + g;
        #pragma unroll
        for (int nt = 0; nt < 8; nt++) {
            int c = wn * 64 + nt * 8 + e2;
            float* p0 = g_o + (size_t)r * (H_ * D_) + (size_t)h * D_ + c;
            *(float2*)p0 = make_float2(cO[mt][nt].x * fac[mt * 2 + 0], cO[mt][nt].y * fac[mt * 2 + 0]);
            *(float2*)(p0 + (size_t)8 * (H_ * D_)) =
                make_float2(cO[mt][nt].z * fac[mt * 2 + 1], cO[mt][nt].w * fac[mt * 2 + 1]);
        }
    }
}

// ---------------- elementwise / norm kernels ----------------
__global__ void cos_sin_k(const float* __restrict__ freqs) {
    int i = blockIdx.x * blockDim.x + threadIdx.x;
    if (i < S_ * RH_) {
        float f = freqs[i];
        g_cos[i] = cosf(f);
        g_sin[i] = sinf(f);
    }
}

__global__ __launch_bounds__(256) void rms_qa(const float* __restrict__ w) {
    int s = blockIdx.x;
    float* row = g_qa + (long)s * QL_;
    float ss = 0.f;
    for (int i = threadIdx.x; i < QL_; i += 256) { float v = row[i]; ss += v * v; }
    ss = block_reduce(ss, false);
    float sc = rsqrtf(ss / QL_ + EPS_);
    for (int i = threadIdx.x; i < QL_; i += 256) row[i] = f2tf_f(row[i] * sc * w[i]);
}

__global__ __launch_bounds__(256) void q_post() {
    int s = blockIdx.x, h = blockIdx.y;
    float* row = g_q + (size_t)s * (H_ * D_) + (size_t)h * D_;
    int d = threadIdx.x;
    float v = row[d];
    float ss = block_reduce(v * v, false);
    float sc = rsqrtf(ss / D_ + EPS_);
    __shared__ float sh[D_];
    sh[d] = v * sc;
    __syncthreads();
    float out;
    if (d < NOPE_) out = sh[d];
    else {
        int p = d - NOPE_, i = p >> 1;
        float cc = g_cos[s * RH_ + i], sn = g_sin[s * RH_ + i];
        float x1 = sh[NOPE_ + (i << 1)], x2 = sh[NOPE_ + (i << 1) + 1];
        out = (p & 1) ? (x1 * sn + x2 * cc) : (x1 * cc - x2 * sn);
    }
    row[d] = f2tf_f(out);
}

__global__ __launch_bounds__(256) void kv_post(const float* __restrict__ w) {
    int s = blockIdx.x;
    float* row = g_kv + (long)s * D_;
    int d = threadIdx.x;
    float v = row[d];
    float ss = block_reduce(v * v, false);
    float sc = rsqrtf(ss / D_ + EPS_);
    __shared__ float sh[D_];
    sh[d] = v * sc * w[d];
    __syncthreads();
    float out;
    if (d < NOPE_) out = sh[d];
    else {
        int p = d - NOPE_, i = p >> 1;
        float cc = g_cos[s * RH_ + i], sn = g_sin[s * RH_ + i];
        float x1 = sh[NOPE_ + (i << 1)], x2 = sh[NOPE_ + (i << 1) + 1];
        out = (p & 1) ? (x1 * sn + x2 * cc) : (x1 * cc - x2 * sn);
    }
    row[d] = f2tf_f(out);
}

__global__ __launch_bounds__(256) void transpose_kv() {
    __shared__ float t[32][33];
    int x = threadIdx.x & 31, y = threadIdx.x >> 5;
    #pragma unroll
    for (int i = 0; i < 4; i++) {
        int trow = blockIdx.x * 32 + y + i * 8;
        t[y + i * 8][x] = g_kv[(size_t)trow * D_ + blockIdx.y * 32 + x];
    }
    __syncthreads();
    #pragma unroll
    for (int i = 0; i < 4; i++) {
        int drow = blockIdx.y * 32 + y + i * 8;
        g_kvT[(size_t)drow * S_ + blockIdx.x * 32 + x] = t[x][y + i * 8];
    }
}

__global__ __launch_bounds__(256) void o_post() {
    int s = blockIdx.x, h = blockIdx.y;
    float* row = g_o + (size_t)s * (H_ * D_) + (size_t)h * D_;
    int d = threadIdx.x;
    __shared__ float sh[R_];
    float v = row[d];
    if (d >= NOPE_) sh[d - NOPE_] = v;
    __syncthreads();
    float out;
    if (d < NOPE_) out = v;
    else {
        int p = d - NOPE_, i = p >> 1;
        float cc = g_cos[s * RH_ + i], sn = g_sin[s * RH_ + i];
        float x1 = sh[i << 1], x2 = sh[(i << 1) + 1];
        out = (p & 1) ? (x2 * cc - x1 * sn) : (x1 * cc + x2 * sn);
    }
    row[d] = f2tf_f(out);
}

__global__ __launch_bounds__(256) void round_or_k() {
    int i = blockIdx.x * 256 + threadIdx.x;
    float4 v = ((const float4*)g_or)[i];
    v.x = f2tf_f(v.x); v.y = f2tf_f(v.y); v.z = f2tf_f(v.z); v.w = f2tf_f(v.w);
    ((float4*)g_or)[i] = v;
}

// ---------------- launch ----------------
extern "C" void kernel_launch(void* const* d_in, const int* in_sizes, int n_in,
                              void* d_out, int out_size) {
    const float* x        = (const float*)d_in[0];
    const float* freqs    = (const float*)d_in[1];
    const float* wq_a     = (const float*)d_in[2];
    const float* q_norm_w = (const float*)d_in[3];
    const float* wq_b     = (const float*)d_in[4];
    const float* wkv      = (const float*)d_in[5];
    const float* kv_norm_w= (const float*)d_in[6];
    const float* wo_a_w   = (const float*)d_in[7];
    const float* wo_b     = (const float*)d_in[8];
    const float* sink     = (const float*)d_in[9];
    float* out = (float*)d_out;

    float *p_x, *p_wqa, *p_wqb, *p_wkv, *p_woa, *p_wob;
    float *p_qa, *p_q, *p_kv, *p_o, *p_or, *p_part;
    cudaGetSymbolAddress((void**)&p_x,   g_x);
    cudaGetSymbolAddress((void**)&p_wqa, g_wqa);
    cudaGetSymbolAddress((void**)&p_wqb, g_wqb);
    cudaGetSymbolAddress((void**)&p_wkv, g_wkv);
    cudaGetSymbolAddress((void**)&p_woa, g_woa);
    cudaGetSymbolAddress((void**)&p_wob, g_wob);
    cudaGetSymbolAddress((void**)&p_qa,  g_qa);
    cudaGetSymbolAddress((void**)&p_q,   g_q);
    cudaGetSymbolAddress((void**)&p_kv,  g_kv);
    cudaGetSymbolAddress((void**)&p_o,   g_o);
    cudaGetSymbolAddress((void**)&p_or,  g_or);
    cudaGetSymbolAddress((void**)&p_part, g_part);

    cudaFuncSetAttribute(gemm_tn_tc, cudaFuncAttributeMaxDynamicSharedMemorySize, GEMM_SMEM);
    cudaFuncSetAttribute(flash_attn, cudaFuncAttributeMaxDynamicSharedMemorySize, FLASH_SMEM);

    cos_sin_k<<<(S_ * RH_ + 255) / 256, 256>>>(freqs);

    round_tf32_k<<<(S_ * HID_ / 4 + 255) / 256, 256>>>(x, p_x, S_ * HID_ / 4);
    round_tf32_k<<<(QL_ * HID_ / 4 + 255) / 256, 256>>>(wq_a, p_wqa, QL_ * HID_ / 4);
    round_tf32_k<<<(H_ * D_ * QL_ / 4 + 255) / 256, 256>>>(wq_b, p_wqb, H_ * D_ * QL_ / 4);
    round_tf32_k<<<(D_ * HID_ / 4 + 255) / 256, 256>>>(wkv, p_wkv, D_ * HID_ / 4);
    round_tf32_k<<<(G_ * OR_ * 1024 / 4 + 255) / 256, 256>>>(wo_a_w, p_woa, G_ * OR_ * 1024 / 4);
    round_tf32_k<<<(HID_ * G_ * OR_ / 4 + 255) / 256, 256>>>(wo_b, p_wob, HID_ * G_ * OR_ / 4);

    // q_a = x @ wq_a^T   — split-K x4: Kc=512, partials in g_part
    gemm_tn_tc<<<dim3(QL_ / BN, S_ / BM, 4), 256, GEMM_SMEM>>>(p_x, p_wqa, p_part,
        512, HID_, HID_, QL_, 512, 512, (long)S_ * QL_);
    reduce_parts_k<<<(S_ * QL_ / 4 + 255) / 256, 256>>>(p_part, p_qa,
        S_ * QL_ / 4, (long)S_ * QL_ / 4, 4);
    rms_qa<<<S_, 256>>>(q_norm_w);

    // q = qa @ wq_b^T    (full chip already)
    gemm_tn_tc<<<dim3((H_ * D_) / BN, S_ / BM, 1), 256, GEMM_SMEM>>>(p_qa, p_wqb, p_q,
        QL_, QL_, QL_, H_ * D_, 0, 0, 0);
    q_post<<<dim3(S_, H_), 256>>>();

    // kv = x @ wkv^T     — split-K x8: Kc=256
    gemm_tn_tc<<<dim3(D_ / BN, S_ / BM, 8), 256, GEMM_SMEM>>>(p_x, p_wkv, p_part,
        256, HID_, HID_, D_, 256, 256, (long)S_ * D_);
    reduce_parts_k<<<(S_ * D_ / 4 + 255) / 256, 256>>>(p_part, p_kv,
        S_ * D_ / 4, (long)S_ * D_ / 4, 8);
    kv_post<<<S_, 256>>>(kv_norm_w);
    transpose_kv<<<dim3(S_ / 32, D_ / 32), 256>>>();

    // fused attention
    flash_attn<<<512, 256, FLASH_SMEM>>>(sink);

    o_post<<<dim3(S_, H_), 256>>>();

    // grouped wo_a
    gemm_tn_tc<<<dim3(OR_ / BN, S_ / BM, G_), 256, GEMM_SMEM>>>(p_o, p_woa, p_or,
        (H_ / G_) * D_, H_ * D_, (H_ / G_) * D_, G_ * OR_,
        (long)(H_ / G_) * D_, (long)OR_ * (H_ / G_) * D_, (long)OR_);
    round_or_k<<<(S_ * G_ * OR_ / 4) / 256, 256>>>();

    // out = o_r @ wo_b^T — split-K x2: Kc=1024
    gemm_tn_tc<<<dim3(HID_ / BN, S_ / BM, 2), 256, GEMM_SMEM>>>(p_or, p_wob, p_part,
        1024, G_ * OR_, G_ * OR_, HID_, 1024, 1024, (long)S_ * HID_);
    reduce_parts_k<<<(S_ * HID_ / 4 + 255) / 256, 256>>>(p_part, out,
        S_ * HID_ / 4, (long)S_ * HID_ / 4, 2);
}

// round 10
// speedup vs baseline: 2.1860x; 1.0059x over previous
#include <cuda_runtime.h>
#include <cstdint>

#define S_    2048
#define HID_  2048
#define H_    16
#define D_    256
#define R_    64
#define RH_   32          // R/2
#define NOPE_ 192
#define QL_   1024
#define OR_   512
#define G_    4
#define EPS_  1e-6f
#define SCALE_ 0.0625f    // 256^-0.5

#define BM 128
#define BN 128
#define BK 32
#define STAGE_BYTES 32768
#define GEMM_SMEM (3 * STAGE_BYTES)

// flash smem (floats): Q 16384 | KV 16384 | KVT 16384 | P 4096 | RED 512
#define F_Q   0
#define F_KV  16384
#define F_KVT 32768
#define F_P   49152
#define F_RED 53248
#define FLASH_SMEM ((53248 + 512) * 4)

// ---------------- scratch ----------------
__device__ float g_cos[S_ * RH_];
__device__ float g_sin[S_ * RH_];
__device__ float g_x[(size_t)S_ * HID_];
__device__ float g_wqa[(size_t)QL_ * HID_];
__device__ float g_wqb[(size_t)H_ * D_ * QL_];
__device__ float g_wkv[(size_t)D_ * HID_];
__device__ float g_woa[(size_t)G_ * OR_ * 1024];
__device__ float g_wob[(size_t)HID_ * G_ * OR_];
__device__ float g_qa[(size_t)S_ * QL_];
__device__ float g_q[(size_t)S_ * H_ * D_];
__device__ float g_kv[(size_t)S_ * D_];
__device__ float g_kvT[(size_t)D_ * S_];
__device__ float g_o[(size_t)S_ * H_ * D_];
__device__ float g_or[(size_t)S_ * G_ * OR_];
__device__ float g_part[(size_t)8 * 1024 * 1024];   // 32 MB split-K partials

// ---------------- helpers ----------------
__device__ __forceinline__ uint32_t f2tf(float x) {
    uint32_t r;
    asm("cvt.rna.tf32.f32 %0, %1;" : "=r"(r) : "f"(x));
    return r;
}
__device__ __forceinline__ float f2tf_f(float x) { return __uint_as_float(f2tf(x)); }

__device__ __forceinline__ void mma_tf32(float4& c, const uint32_t a[4], const uint32_t b[2]) {
    asm volatile(
        "mma.sync.aligned.m16n8k8.row.col.f32.tf32.tf32.f32 "
        "{%0,%1,%2,%3}, {%4,%5,%6,%7}, {%8,%9}, {%0,%1,%2,%3};\n"
        : "+f"(c.x), "+f"(c.y), "+f"(c.z), "+f"(c.w)
        : "r"(a[0]), "r"(a[1]), "r"(a[2]), "r"(a[3]), "r"(b[0]), "r"(b[1]));
}
__device__ __forceinline__ void ldsm4(uint32_t* d, uint32_t addr) {
    asm volatile("ldmatrix.sync.aligned.m8n8.x4.shared.b16 {%0,%1,%2,%3}, [%4];"
        : "=r"(d[0]), "=r"(d[1]), "=r"(d[2]), "=r"(d[3]) : "r"(addr));
}
#define CP16(dst, src) \
    asm volatile("cp.async.cg.shared.global [%0], [%1], 16;\n" :: "r"(dst), "l"(src))
#define CP_COMMIT() asm volatile("cp.async.commit_group;\n")
#define CP_WAIT1()  asm volatile("cp.async.wait_group 1;\n")

__device__ __forceinline__ float block_reduce(float v, bool is_max) {
    __shared__ float warp_res[8];
    __shared__ float result;
    __syncthreads();
    #pragma unroll
    for (int o = 16; o; o >>= 1) {
        float other = __shfl_xor_sync(0xffffffffu, v, o);
        v = is_max ? fmaxf(v, other) : (v + other);
    }
    if ((threadIdx.x & 31) == 0) warp_res[threadIdx.x >> 5] = v;
    __syncthreads();
    if (threadIdx.x == 0) {
        int nw = (blockDim.x + 31) >> 5;
        float r = warp_res[0];
        for (int i = 1; i < nw; i++) r = is_max ? fmaxf(r, warp_res[i]) : (r + warp_res[i]);
        result = r;
    }
    __syncthreads();
    return result;
}

__global__ __launch_bounds__(256) void round_tf32_k(const float* __restrict__ src,
                                                    float* __restrict__ dst, int n4) {
    int i = blockIdx.x * 256 + threadIdx.x;
    if (i < n4) {
        float4 v = ((const float4*)src)[i];
        v.x = f2tf_f(v.x); v.y = f2tf_f(v.y); v.z = f2tf_f(v.z); v.w = f2tf_f(v.w);
        ((float4*)dst)[i] = v;
    }
}

// deterministic fixed-order split-K reduction
__global__ __launch_bounds__(256) void reduce_parts_k(const float* __restrict__ src,
                                                      float* __restrict__ dst,
                                                      int n4, long stride4, int parts) {
    int i = blockIdx.x * 256 + threadIdx.x;
    if (i >= n4) return;
    float4 a = ((const float4*)src)[i];
    for (int p = 1; p < parts; p++) {
        float4 b = ((const float4*)src)[i + (size_t)p * stride4];
        a.x += b.x; a.y += b.y; a.z += b.z; a.w += b.w;
    }
    ((float4*)dst)[i] = a;
}

// ============================================================================
// TF32 GEMM TN: C[M,N] = A[M,K] @ B[N,K]^T. Inputs pre-rounded tf32.
// 512 threads (16 warps, 4x4 grid, 32x32 warp tile), 128x128x32 CTA tile,
// 3-stage cp.async pipeline, ldmatrix.x4, XOR-swizzled float4 layout.
// rnd: apply tf32 rounding at the epilogue store.
// ============================================================================
__global__ __launch_bounds__(512, 2) void gemm_tn_tc(
    const float* __restrict__ A, const float* __restrict__ B, float* __restrict__ C,
    int K, int lda, int ldb, int ldc,
    long sA, long sB, long sC, int rnd)
{
    int row0 = blockIdx.y * BM, col0 = blockIdx.x * BN;
    A += (long)blockIdx.z * sA;
    B += (long)blockIdx.z * sB;
    C += (long)blockIdx.z * sC;
    int niter = K / BK;

    extern __shared__ uint32_t smem[];
    uint32_t smem_b = (uint32_t)__cvta_generic_to_shared(smem);

    int tid = threadIdx.x, lane = tid & 31, warp = tid >> 5;
    int wm = warp >> 2, wn = warp & 3;   // 4 x 4 warps

    // ---- loader: 2 float4 per thread per matrix ----
    int ldr = tid >> 3;        // 0..63 (+64*i)
    int ldk = tid & 7;
    uint32_t dstA[2];
    const float* srcA[2];
    const float* srcB[2];
    #pragma unroll
    for (int i = 0; i < 2; i++) {
        int r = ldr + i * 64;
        dstA[i] = smem_b + ((((r << 3) + (ldk ^ (r & 7)))) << 4);
        srcA[i] = A + (long)(row0 + r) * lda + (ldk << 2);
        srcB[i] = B + (long)(col0 + r) * ldb + (ldk << 2);
    }

    // ---- fragment base addresses (stage 0) ----
    int jr = ((lane >> 3) & 1) << 3;
    int jk = lane >> 4;
    int rr = lane & 7;
    uint32_t a_ad[2], b_ad[2];
    #pragma unroll
    for (int mt = 0; mt < 2; mt++) {
        int ar = wm * 32 + mt * 16 + jr + rr;
        a_ad[mt] = smem_b + (((ar << 3) + (jk ^ (ar & 7))) << 4);
    }
    #pragma unroll
    for (int ntp = 0; ntp < 2; ntp++) {
        int br = wn * 32 + ntp * 16 + jr + rr;
        b_ad[ntp] = smem_b + 16384 + (((br << 3) + (jk ^ (br & 7))) << 4);
    }

    float4 c[2][4];
    #pragma unroll
    for (int i = 0; i < 2; i++)
        #pragma unroll
        for (int j = 0; j < 4; j++) c[i][j] = make_float4(0.f, 0.f, 0.f, 0.f);

    // ---- prologue: stages 0,1 ----
    #pragma unroll
    for (int i = 0; i < 2; i++) CP16(dstA[i], srcA[i]);
    #pragma unroll
    for (int i = 0; i < 2; i++) CP16(dstA[i] + 16384, srcB[i]);
    CP_COMMIT();
    if (niter > 1) {
        #pragma unroll
        for (int i = 0; i < 2; i++) CP16(dstA[i] + STAGE_BYTES, srcA[i] + BK);
        #pragma unroll
        for (int i = 0; i < 2; i++) CP16(dstA[i] + STAGE_BYTES + 16384, srcB[i] + BK);
    }
    CP_COMMIT();
    #pragma unroll
    for (int i = 0; i < 2; i++) { srcA[i] += 2 * BK; srcB[i] += 2 * BK; }

    int stage = 0;
    for (int k = 0; k < niter; k++) {
        CP_WAIT1();
        __syncthreads();

        if (k + 2 < niter) {
            int s2 = stage + 2; if (s2 >= 3) s2 -= 3;
            uint32_t so2 = (uint32_t)s2 * STAGE_BYTES;
            #pragma unroll
            for (int i = 0; i < 2; i++) CP16(dstA[i] + so2, srcA[i]);
            #pragma unroll
            for (int i = 0; i < 2; i++) CP16(dstA[i] + so2 + 16384, srcB[i]);
        }
        CP_COMMIT();
        #pragma unroll
        for (int i = 0; i < 2; i++) { srcA[i] += BK; srcB[i] += BK; }

        uint32_t so = (uint32_t)stage * STAGE_BYTES;
        uint32_t aa[2], bb[2];
        #pragma unroll
        for (int mt = 0; mt < 2; mt++) aa[mt] = a_ad[mt] + so;
        #pragma unroll
        for (int ntp = 0; ntp < 2; ntp++) bb[ntp] = b_ad[ntp] + so;

        #pragma unroll
        for (int ks = 0; ks < 4; ks++) {
            uint32_t af[2][4];
            #pragma unroll
            for (int mt = 0; mt < 2; mt++) ldsm4(af[mt], aa[mt] ^ (ks << 5));
            uint32_t bf[4][2];
            #pragma unroll
            for (int ntp = 0; ntp < 2; ntp++) {
                uint32_t t[4];
                ldsm4(t, bb[ntp] ^ (ks << 5));
                bf[ntp * 2][0]     = t[0];
                bf[ntp * 2 + 1][0] = t[1];
                bf[ntp * 2][1]     = t[2];
                bf[ntp * 2 + 1][1] = t[3];
            }
            #pragma unroll
            for (int mt = 0; mt < 2; mt++)
                #pragma unroll
                for (int nt = 0; nt < 4; nt++)
                    mma_tf32(c[mt][nt], af[mt], bf[nt]);
        }
        stage++; if (stage >= 3) stage -= 3;
    }

    // epilogue
    #pragma unroll
    for (int mt = 0; mt < 2; mt++) {
        int m = row0 + wm * 32 + mt * 16 + (lane >> 2);
        #pragma unroll
        for (int nt = 0; nt < 4; nt++) {
            int n = col0 + wn * 32 + nt * 8 + ((lane & 3) << 1);
            float4 v = c[mt][nt];
            if (rnd) { v.x = f2tf_f(v.x); v.y = f2tf_f(v.y); v.z = f2tf_f(v.z); v.w = f2tf_f(v.w); }
            *(float2*)(C + (long)m * ldc + n)       = make_float2(v.x, v.y);
            *(float2*)(C + (long)(m + 8) * ldc + n) = make_float2(v.z, v.w);
        }
    }
}

// ============================================================================
// Fused flash attention: per CTA = (head h, 64-row q tile qi), online softmax.
// ============================================================================
__global__ __launch_bounds__(256, 1) void flash_attn(const float* __restrict__ sink) {
    int bx = blockIdx.x;
    int h  = bx & 15;
    int qi = 31 - (bx >> 4);          // heavy tiles first
    int q0 = qi * 64;
    int jn = qi + 1;

    extern __shared__ float smf[];
    uint32_t smb = (uint32_t)__cvta_generic_to_shared(smf);
    uint32_t smQ = smb, smKV = smb + F_KV * 4, smKVT = smb + F_KVT * 4, smP = smb + F_P * 4;

    int tid = threadIdx.x, lane = tid & 31, warp = tid >> 5;
    int wm = warp >> 2, wn = warp & 3;
    int jr = ((lane >> 3) & 1) << 3;
    int jk = lane >> 4;
    int rr = lane & 7;
    int g  = lane >> 2;
    int e2 = (lane & 3) << 1;

    const float4* q4   = (const float4*)g_q + (size_t)q0 * 1024 + (size_t)h * 64;
    const float4* kv4  = (const float4*)g_kv;
    const float4* kvT4 = (const float4*)g_kvT;

    #pragma unroll
    for (int i = 0; i < 16; i++) {
        int id = tid + i * 256, row = id >> 6, k4 = id & 63;
        uint32_t dst = smQ + (uint32_t)((row << 6) + (k4 & 56) + ((k4 ^ row) & 7)) * 16;
        CP16(dst, q4 + (size_t)row * 1024 + k4);
    }
    #pragma unroll
    for (int i = 0; i < 16; i++) {
        int id = tid + i * 256, row = id >> 6, k4 = id & 63;
        uint32_t dst = smKV + (uint32_t)((row << 6) + (k4 & 56) + ((k4 ^ row) & 7)) * 16;
        CP16(dst, kv4 + (size_t)row * 64 + k4);
    }
    CP_COMMIT();
    #pragma unroll
    for (int i = 0; i < 16; i++) {
        int id = tid + i * 256, rd = id >> 4, k4 = id & 15;
        uint32_t dst = smKVT + (uint32_t)((rd << 4) + (k4 & 8) + ((k4 ^ rd) & 7)) * 16;
        CP16(dst, kvT4 + (size_t)rd * 512 + k4);
    }
    CP_COMMIT();

    uint32_t aSb[2], bSb, aPb[2], bPVb[4];
    #pragma unroll
    for (int mt = 0; mt < 2; mt++) {
        int ar = wm * 32 + mt * 16 + jr + rr;
        aSb[mt] = smQ + (uint32_t)((ar << 6) + (jk ^ (ar & 7))) * 16;
        aPb[mt] = smP + (uint32_t)((ar << 4) + (jk ^ (ar & 7))) * 16;
    }
    {
        int br = wn * 16 + jr + rr;
        bSb = smKV + (uint32_t)((br << 6) + (jk ^ (br & 7))) * 16;
    }
    #pragma unroll
    for (int ntp = 0; ntp < 4; ntp++) {
        int br = wn * 64 + ntp * 16 + jr + rr;
        bPVb[ntp] = smKVT + (uint32_t)((br << 4) + (jk ^ (br & 7))) * 16;
    }

    float4 cO[2][8];
    #pragma unroll
    for (int mt = 0; mt < 2; mt++)
        #pragma unroll
        for (int nt = 0; nt < 8; nt++) cO[mt][nt] = make_float4(0.f, 0.f, 0.f, 0.f);
    float mrow[4] = {-3.0e38f, -3.0e38f, -3.0e38f, -3.0e38f};
    float lrow[4] = {0.f, 0.f, 0.f, 0.f};

    for (int j = 0; j < jn; j++) {
        CP_WAIT1();
        __syncthreads();

        float4 sS[2][2];
        #pragma unroll
        for (int mt = 0; mt < 2; mt++)
            #pragma unroll
            for (int nt = 0; nt < 2; nt++) sS[mt][nt] = make_float4(0.f, 0.f, 0.f, 0.f);

        #pragma unroll
        for (int cc = 0; cc < 8; cc++) {
            uint32_t ao = (uint32_t)cc * 128;
            #pragma unroll
            for (int ks = 0; ks < 4; ks++) {
                uint32_t af[2][4];
                #pragma unroll
                for (int mt = 0; mt < 2; mt++) ldsm4(af[mt], (aSb[mt] + ao) ^ (ks << 5));
                uint32_t tb[4];
                ldsm4(tb, (bSb + ao) ^ (ks << 5));
                uint32_t b0[2] = {tb[0], tb[2]}, b1[2] = {tb[1], tb[3]};
                #pragma unroll
                for (int mt = 0; mt < 2; mt++) {
                    mma_tf32(sS[mt][0], af[mt], b0);
                    mma_tf32(sS[mt][1], af[mt], b1);
                }
            }
        }

        #pragma unroll
        for (int mt = 0; mt < 2; mt++)
            #pragma unroll
            for (int nt = 0; nt < 2; nt++) {
                sS[mt][nt].x *= SCALE_; sS[mt][nt].y *= SCALE_;
                sS[mt][nt].z *= SCALE_; sS[mt][nt].w *= SCALE_;
            }
        if (j == qi) {
            #pragma unroll
            for (int mt = 0; mt < 2; mt++) {
                int r0 = wm * 32 + mt * 16 + g;
                #pragma unroll
                for (int nt = 0; nt < 2; nt++) {
                    int c0 = wn * 16 + nt * 8 + e2;
                    if (c0 > r0)     sS[mt][nt].x = -3.0e38f;
                    if (c0 + 1 > r0) sS[mt][nt].y = -3.0e38f;
                    if (c0 > r0 + 8)     sS[mt][nt].z = -3.0e38f;
                    if (c0 + 1 > r0 + 8) sS[mt][nt].w = -3.0e38f;
                }
            }
        }

        float rm[4];
        #pragma unroll
        for (int mt = 0; mt < 2; mt++) {
            rm[mt * 2 + 0] = fmaxf(fmaxf(sS[mt][0].x, sS[mt][0].y), fmaxf(sS[mt][1].x, sS[mt][1].y));
            rm[mt * 2 + 1] = fmaxf(fmaxf(sS[mt][0].z, sS[mt][0].w), fmaxf(sS[mt][1].z, sS[mt][1].w));
        }
        #pragma unroll
        for (int i = 0; i < 4; i++) {
            rm[i] = fmaxf(rm[i], __shfl_xor_sync(0xffffffffu, rm[i], 1));
            rm[i] = fmaxf(rm[i], __shfl_xor_sync(0xffffffffu, rm[i], 2));
        }
        #pragma unroll
        for (int i = 0; i < 4; i++) {
            int row = wm * 32 + (i >> 1) * 16 + g + (i & 1) * 8;
            smf[F_RED + wn * 64 + row] = rm[i];
        }
        __syncthreads();   // (A)

        if (j + 1 < jn) {
            const float4* kvs = kv4 + (size_t)(j + 1) * 64 * 64;
            #pragma unroll
            for (int i = 0; i < 16; i++) {
                int id = tid + i * 256, row = id >> 6, k4 = id & 63;
                uint32_t dst = smKV + (uint32_t)((row << 6) + (k4 & 56) + ((k4 ^ row) & 7)) * 16;
                CP16(dst, kvs + (size_t)row * 64 + k4);
            }
        }
        CP_COMMIT();

        float mnew[4], alpha[4];
        #pragma unroll
        for (int i = 0; i < 4; i++) {
            int row = wm * 32 + (i >> 1) * 16 + g + (i & 1) * 8;
            float tm = fmaxf(fmaxf(smf[F_RED + row], smf[F_RED + 64 + row]),
                             fmaxf(smf[F_RED + 128 + row], smf[F_RED + 192 + row]));
            mnew[i] = fmaxf(mrow[i], tm);
            alpha[i] = __expf(mrow[i] - mnew[i]);
            mrow[i] = mnew[i];
        }

        float ls[4];
        #pragma unroll
        for (int mt = 0; mt < 2; mt++) {
            #pragma unroll
            for (int nt = 0; nt < 2; nt++) {
                sS[mt][nt].x = __expf(sS[mt][nt].x - mnew[mt * 2 + 0]);
                sS[mt][nt].y = __expf(sS[mt][nt].y - mnew[mt * 2 + 0]);
                sS[mt][nt].z = __expf(sS[mt][nt].z - mnew[mt * 2 + 1]);
                sS[mt][nt].w = __expf(sS[mt][nt].w - mnew[mt * 2 + 1]);
            }
            ls[mt * 2 + 0] = sS[mt][0].x + sS[mt][0].y + sS[mt][1].x + sS[mt][1].y;
            ls[mt * 2 + 1] = sS[mt][0].z + sS[mt][0].w + sS[mt][1].z + sS[mt][1].w;
        }
        #pragma unroll
        for (int i = 0; i < 4; i++) {
            ls[i] += __shfl_xor_sync(0xffffffffu, ls[i], 1);
            ls[i] += __shfl_xor_sync(0xffffffffu, ls[i], 2);
        }
        #pragma unroll
        for (int i = 0; i < 4; i++) {
            int row = wm * 32 + (i >> 1) * 16 + g + (i & 1) * 8;
            smf[F_RED + 256 + wn * 64 + row] = ls[i];
        }
        __syncthreads();   // (B)
        #pragma unroll
        for (int i = 0; i < 4; i++) {
            int row = wm * 32 + (i >> 1) * 16 + g + (i & 1) * 8;
            float tl = smf[F_RED + 256 + row] + smf[F_RED + 256 + 64 + row] +
                       smf[F_RED + 256 + 128 + row] + smf[F_RED + 256 + 192 + row];
            lrow[i] = lrow[i] * alpha[i] + tl;
        }

        #pragma unroll
        for (int mt = 0; mt < 2; mt++)
            #pragma unroll
            for (int nt = 0; nt < 8; nt++) {
                cO[mt][nt].x *= alpha[mt * 2 + 0];
                cO[mt][nt].y *= alpha[mt * 2 + 0];
                cO[mt][nt].z *= alpha[mt * 2 + 1];
                cO[mt][nt].w *= alpha[mt * 2 + 1];
            }

        #pragma unroll
        for (int mt = 0; mt < 2; mt++)
            #pragma unroll
            for (int nt = 0; nt < 2; nt++) {
                int c = wn * 16 + nt * 8 + e2;
                int k4 = c >> 2;
                {
                    int row = wm * 32 + mt * 16 + g;
                    int fi = F_P + (((row << 4) + (k4 & 8) + ((k4 ^ row) & 7)) << 2) + (c & 2);
                    *(float2*)(smf + fi) = make_float2(f2tf_f(sS[mt][nt].x), f2tf_f(sS[mt][nt].y));
                }
                {
                    int row = wm * 32 + mt * 16 + g + 8;
                    int fi = F_P + (((row << 4) + (k4 & 8) + ((k4 ^ row) & 7)) << 2) + (c & 2);
                    *(float2*)(smf + fi) = make_float2(f2tf_f(sS[mt][nt].z), f2tf_f(sS[mt][nt].w));
                }
            }

        CP_WAIT1();
        __syncthreads();   // (C)

        #pragma unroll
        for (int kk = 0; kk < 8; kk++) {
            uint32_t xo = (uint32_t)((kk & 3) << 5);
            uint32_t ad = (uint32_t)((kk >> 2) << 7);
            uint32_t af[2][4];
            #pragma unroll
            for (int mt = 0; mt < 2; mt++) ldsm4(af[mt], (aPb[mt] + ad) ^ xo);
            #pragma unroll
            for (int ntp = 0; ntp < 4; ntp++) {
                uint32_t tb[4];
                ldsm4(tb, (bPVb[ntp] + ad) ^ xo);
                uint32_t b0[2] = {tb[0], tb[2]}, b1[2] = {tb[1], tb[3]};
                #pragma unroll
                for (int mt = 0; mt < 2; mt++) {
                    mma_tf32(cO[mt][ntp * 2 + 0], af[mt], b0);
                    mma_tf32(cO[mt][ntp * 2 + 1], af[mt], b1);
                }
            }
        }
        __syncthreads();   // (D)

        if (j + 1 < jn) {
            const float4* kvts = kvT4 + (size_t)(j + 1) * 16;
            #pragma unroll
            for (int i = 0; i < 16; i++) {
                int id = tid + i * 256, rd = id >> 4, k4 = id & 15;
                uint32_t dst = smKVT + (uint32_t)((rd << 4) + (k4 & 8) + ((k4 ^ rd) & 7)) * 16;
                CP16(dst, kvts + (size_t)rd * 512 + k4);
            }
        }
        CP_COMMIT();
    }

    float snk = sink[h];
    float fac[4];
    #pragma unroll
    for (int i = 0; i < 4; i++) {
        float mf = fmaxf(mrow[i], snk);
        float af = __expf(mrow[i] - mf);
        float lf = lrow[i] * af + __expf(snk - mf);
        fac[i] = af / lf;
    }
    #pragma unroll
    for (int mt = 0; mt < 2; mt++) {
        int r = q0 + wm * 32 + mt * 16 + g;
        #pragma unroll
        for (int nt = 0; nt < 8; nt++) {
            int c = wn * 64 + nt * 8 + e2;
            float* p0 = g_o + (size_t)r * (H_ * D_) + (size_t)h * D_ + c;
            *(float2*)p0 = make_float2(cO[mt][nt].x * fac[mt * 2 + 0], cO[mt][nt].y * fac[mt * 2 + 0]);
            *(float2*)(p0 + (size_t)8 * (H_ * D_)) =
                make_float2(cO[mt][nt].z * fac[mt * 2 + 1], cO[mt][nt].w * fac[mt * 2 + 1]);
        }
    }
}

// ---------------- elementwise / norm kernels ----------------
__global__ void cos_sin_k(const float* __restrict__ freqs) {
    int i = blockIdx.x * blockDim.x + threadIdx.x;
    if (i < S_ * RH_) {
        float f = freqs[i];
        g_cos[i] = cosf(f);
        g_sin[i] = sinf(f);
    }
}

__global__ __launch_bounds__(256) void rms_qa(const float* __restrict__ w) {
    int s = blockIdx.x;
    float* row = g_qa + (long)s * QL_;
    float ss = 0.f;
    for (int i = threadIdx.x; i < QL_; i += 256) { float v = row[i]; ss += v * v; }
    ss = block_reduce(ss, false);
    float sc = rsqrtf(ss / QL_ + EPS_);
    for (int i = threadIdx.x; i < QL_; i += 256) row[i] = f2tf_f(row[i] * sc * w[i]);
}

__global__ __launch_bounds__(256) void q_post() {
    int s = blockIdx.x, h = blockIdx.y;
    float* row = g_q + (size_t)s * (H_ * D_) + (size_t)h * D_;
    int d = threadIdx.x;
    float v = row[d];
    float ss = block_reduce(v * v, false);
    float sc = rsqrtf(ss / D_ + EPS_);
    __shared__ float sh[D_];
    sh[d] = v * sc;
    __syncthreads();
    float out;
    if (d < NOPE_) out = sh[d];
    else {
        int p = d - NOPE_, i = p >> 1;
        float cc = g_cos[s * RH_ + i], sn = g_sin[s * RH_ + i];
        float x1 = sh[NOPE_ + (i << 1)], x2 = sh[NOPE_ + (i << 1) + 1];
        out = (p & 1) ? (x1 * sn + x2 * cc) : (x1 * cc - x2 * sn);
    }
    row[d] = f2tf_f(out);
}

__global__ __launch_bounds__(256) void kv_post(const float* __restrict__ w) {
    int s = blockIdx.x;
    float* row = g_kv + (long)s * D_;
    int d = threadIdx.x;
    float v = row[d];
    float ss = block_reduce(v * v, false);
    float sc = rsqrtf(ss / D_ + EPS_);
    __shared__ float sh[D_];
    sh[d] = v * sc * w[d];
    __syncthreads();
    float out;
    if (d < NOPE_) out = sh[d];
    else {
        int p = d - NOPE_, i = p >> 1;
        float cc = g_cos[s * RH_ + i], sn = g_sin[s * RH_ + i];
        float x1 = sh[NOPE_ + (i << 1)], x2 = sh[NOPE_ + (i << 1) + 1];
        out = (p & 1) ? (x1 * sn + x2 * cc) : (x1 * cc - x2 * sn);
    }
    row[d] = f2tf_f(out);
}

__global__ __launch_bounds__(256) void transpose_kv() {
    __shared__ float t[32][33];
    int x = threadIdx.x & 31, y = threadIdx.x >> 5;
    #pragma unroll
    for (int i = 0; i < 4; i++) {
        int trow = blockIdx.x * 32 + y + i * 8;
        t[y + i * 8][x] = g_kv[(size_t)trow * D_ + blockIdx.y * 32 + x];
    }
    __syncthreads();
    #pragma unroll
    for (int i = 0; i < 4; i++) {
        int drow = blockIdx.y * 32 + y + i * 8;
        g_kvT[(size_t)drow * S_ + blockIdx.x * 32 + x] = t[x][y + i * 8];
    }
}

__global__ __launch_bounds__(256) void o_post() {
    int s = blockIdx.x, h = blockIdx.y;
    float* row = g_o + (size_t)s * (H_ * D_) + (size_t)h * D_;
    int d = threadIdx.x;
    __shared__ float sh[R_];
    float v = row[d];
    if (d >= NOPE_) sh[d - NOPE_] = v;
    __syncthreads();
    float out;
    if (d < NOPE_) out = v;
    else {
        int p = d - NOPE_, i = p >> 1;
        float cc = g_cos[s * RH_ + i], sn = g_sin[s * RH_ + i];
        float x1 = sh[i << 1], x2 = sh[(i << 1) + 1];
        out = (p & 1) ? (x2 * cc - x1 * sn) : (x1 * cc + x2 * sn);
    }
    row[d] = f2tf_f(out);
}

// ---------------- launch ----------------
extern "C" void kernel_launch(void* const* d_in, const int* in_sizes, int n_in,
                              void* d_out, int out_size) {
    const float* x        = (const float*)d_in[0];
    const float* freqs    = (const float*)d_in[1];
    const float* wq_a     = (const float*)d_in[2];
    const float* q_norm_w = (const float*)d_in[3];
    const float* wq_b     = (const float*)d_in[4];
    const float* wkv      = (const float*)d_in[5];
    const float* kv_norm_w= (const float*)d_in[6];
    const float* wo_a_w   = (const float*)d_in[7];
    const float* wo_b     = (const float*)d_in[8];
    const float* sink     = (const float*)d_in[9];
    float* out = (float*)d_out;

    float *p_x, *p_wqa, *p_wqb, *p_wkv, *p_woa, *p_wob;
    float *p_qa, *p_q, *p_kv, *p_o, *p_or, *p_part;
    cudaGetSymbolAddress((void**)&p_x,   g_x);
    cudaGetSymbolAddress((void**)&p_wqa, g_wqa);
    cudaGetSymbolAddress((void**)&p_wqb, g_wqb);
    cudaGetSymbolAddress((void**)&p_wkv, g_wkv);
    cudaGetSymbolAddress((void**)&p_woa, g_woa);
    cudaGetSymbolAddress((void**)&p_wob, g_wob);
    cudaGetSymbolAddress((void**)&p_qa,  g_qa);
    cudaGetSymbolAddress((void**)&p_q,   g_q);
    cudaGetSymbolAddress((void**)&p_kv,  g_kv);
    cudaGetSymbolAddress((void**)&p_o,   g_o);
    cudaGetSymbolAddress((void**)&p_or,  g_or);
    cudaGetSymbolAddress((void**)&p_part, g_part);

    cudaFuncSetAttribute(gemm_tn_tc, cudaFuncAttributeMaxDynamicSharedMemorySize, GEMM_SMEM);
    cudaFuncSetAttribute(flash_attn, cudaFuncAttributeMaxDynamicSharedMemorySize, FLASH_SMEM);

    cos_sin_k<<<(S_ * RH_ + 255) / 256, 256>>>(freqs);

    round_tf32_k<<<(S_ * HID_ / 4 + 255) / 256, 256>>>(x, p_x, S_ * HID_ / 4);
    round_tf32_k<<<(QL_ * HID_ / 4 + 255) / 256, 256>>>(wq_a, p_wqa, QL_ * HID_ / 4);
    round_tf32_k<<<(H_ * D_ * QL_ / 4 + 255) / 256, 256>>>(wq_b, p_wqb, H_ * D_ * QL_ / 4);
    round_tf32_k<<<(D_ * HID_ / 4 + 255) / 256, 256>>>(wkv, p_wkv, D_ * HID_ / 4);
    round_tf32_k<<<(G_ * OR_ * 1024 / 4 + 255) / 256, 256>>>(wo_a_w, p_woa, G_ * OR_ * 1024 / 4);
    round_tf32_k<<<(HID_ * G_ * OR_ / 4 + 255) / 256, 256>>>(wo_b, p_wob, HID_ * G_ * OR_ / 4);

    // q_a = x @ wq_a^T   — split-K x4: Kc=512
    gemm_tn_tc<<<dim3(QL_ / BN, S_ / BM, 4), 512, GEMM_SMEM>>>(p_x, p_wqa, p_part,
        512, HID_, HID_, QL_, 512, 512, (long)S_ * QL_, 0);
    reduce_parts_k<<<(S_ * QL_ / 4 + 255) / 256, 256>>>(p_part, p_qa,
        S_ * QL_ / 4, (long)S_ * QL_ / 4, 4);
    rms_qa<<<S_, 256>>>(q_norm_w);

    // q = qa @ wq_b^T
    gemm_tn_tc<<<dim3((H_ * D_) / BN, S_ / BM, 1), 512, GEMM_SMEM>>>(p_qa, p_wqb, p_q,
        QL_, QL_, QL_, H_ * D_, 0, 0, 0, 0);
    q_post<<<dim3(S_, H_), 256>>>();

    // kv = x @ wkv^T     — split-K x8: Kc=256
    gemm_tn_tc<<<dim3(D_ / BN, S_ / BM, 8), 512, GEMM_SMEM>>>(p_x, p_wkv, p_part,
        256, HID_, HID_, D_, 256, 256, (long)S_ * D_, 0);
    reduce_parts_k<<<(S_ * D_ / 4 + 255) / 256, 256>>>(p_part, p_kv,
        S_ * D_ / 4, (long)S_ * D_ / 4, 8);
    kv_post<<<S_, 256>>>(kv_norm_w);
    transpose_kv<<<dim3(S_ / 32, D_ / 32), 256>>>();

    // fused attention
    flash_attn<<<512, 256, FLASH_SMEM>>>(sink);

    o_post<<<dim3(S_, H_), 256>>>();

    // grouped wo_a (tf32-rounded output in epilogue)
    gemm_tn_tc<<<dim3(OR_ / BN, S_ / BM, G_), 512, GEMM_SMEM>>>(p_o, p_woa, p_or,
        (H_ / G_) * D_, H_ * D_, (H_ / G_) * D_, G_ * OR_,
        (long)(H_ / G_) * D_, (long)OR_ * (H_ / G_) * D_, (long)OR_, 1);

    // out = o_r @ wo_b^T — split-K x2: Kc=1024
    gemm_tn_tc<<<dim3(HID_ / BN, S_ / BM, 2), 512, GEMM_SMEM>>>(p_or, p_wob, p_part,
        1024, G_ * OR_, G_ * OR_, HID_, 1024, 1024, (long)S_ * HID_, 0);
    reduce_parts_k<<<(S_ * HID_ / 4 + 255) / 256, 256>>>(p_part, out,
        S_ * HID_ / 4, (long)S_ * HID_ / 4, 2);
}

// round 11
// speedup vs baseline: 2.2641x; 1.0357x over previous
#include <cuda_runtime.h>
#include <cstdint>

#define S_    2048
#define HID_  2048
#define H_    16
#define D_    256
#define R_    64
#define RH_   32          // R/2
#define NOPE_ 192
#define QL_   1024
#define OR_   512
#define G_    4
#define EPS_  1e-6f
#define SCALE_ 0.0625f    // 256^-0.5

#define BM 128
#define BN 64
#define BK 32
#define STAGE_BYTES 24576            // A 16KB + B 8KB per stage
#define GEMM_SMEM (3 * STAGE_BYTES)  // 72 KB -> 3 CTAs/SM

// flash smem (floats): Q 16384 | KV 16384 | KVT 16384 | P 4096 | RED 512
#define F_Q   0
#define F_KV  16384
#define F_KVT 32768
#define F_P   49152
#define F_RED 53248
#define FLASH_SMEM ((53248 + 512) * 4)

// ---------------- scratch ----------------
__device__ float g_cos[S_ * RH_];
__device__ float g_sin[S_ * RH_];
__device__ float g_x[(size_t)S_ * HID_];
__device__ float g_wqa[(size_t)QL_ * HID_];
__device__ float g_wqb[(size_t)H_ * D_ * QL_];
__device__ float g_wkv[(size_t)D_ * HID_];
__device__ float g_woa[(size_t)G_ * OR_ * 1024];
__device__ float g_wob[(size_t)HID_ * G_ * OR_];
__device__ float g_qa[(size_t)S_ * QL_];
__device__ float g_q[(size_t)S_ * H_ * D_];
__device__ float g_kv[(size_t)S_ * D_];
__device__ float g_kvT[(size_t)D_ * S_];
__device__ float g_o[(size_t)S_ * H_ * D_];
__device__ float g_or[(size_t)S_ * G_ * OR_];
__device__ float g_part[(size_t)8 * 1024 * 1024];   // 32 MB split-K partials

// ---------------- helpers ----------------
__device__ __forceinline__ uint32_t f2tf(float x) {
    uint32_t r;
    asm("cvt.rna.tf32.f32 %0, %1;" : "=r"(r) : "f"(x));
    return r;
}
__device__ __forceinline__ float f2tf_f(float x) { return __uint_as_float(f2tf(x)); }

__device__ __forceinline__ void mma_tf32(float4& c, const uint32_t a[4], const uint32_t b[2]) {
    asm volatile(
        "mma.sync.aligned.m16n8k8.row.col.f32.tf32.tf32.f32 "
        "{%0,%1,%2,%3}, {%4,%5,%6,%7}, {%8,%9}, {%0,%1,%2,%3};\n"
        : "+f"(c.x), "+f"(c.y), "+f"(c.z), "+f"(c.w)
        : "r"(a[0]), "r"(a[1]), "r"(a[2]), "r"(a[3]), "r"(b[0]), "r"(b[1]));
}
__device__ __forceinline__ void ldsm4(uint32_t* d, uint32_t addr) {
    asm volatile("ldmatrix.sync.aligned.m8n8.x4.shared.b16 {%0,%1,%2,%3}, [%4];"
        : "=r"(d[0]), "=r"(d[1]), "=r"(d[2]), "=r"(d[3]) : "r"(addr));
}
#define CP16(dst, src) \
    asm volatile("cp.async.cg.shared.global [%0], [%1], 16;\n" :: "r"(dst), "l"(src))
#define CP_COMMIT() asm volatile("cp.async.commit_group;\n")
#define CP_WAIT1()  asm volatile("cp.async.wait_group 1;\n")

__device__ __forceinline__ float block_reduce(float v, bool is_max) {
    __shared__ float warp_res[8];
    __shared__ float result;
    __syncthreads();
    #pragma unroll
    for (int o = 16; o; o >>= 1) {
        float other = __shfl_xor_sync(0xffffffffu, v, o);
        v = is_max ? fmaxf(v, other) : (v + other);
    }
    if ((threadIdx.x & 31) == 0) warp_res[threadIdx.x >> 5] = v;
    __syncthreads();
    if (threadIdx.x == 0) {
        int nw = (blockDim.x + 31) >> 5;
        float r = warp_res[0];
        for (int i = 1; i < nw; i++) r = is_max ? fmaxf(r, warp_res[i]) : (r + warp_res[i]);
        result = r;
    }
    __syncthreads();
    return result;
}

__global__ __launch_bounds__(256) void round_tf32_k(const float* __restrict__ src,
                                                    float* __restrict__ dst, int n4) {
    int i = blockIdx.x * 256 + threadIdx.x;
    if (i < n4) {
        float4 v = ((const float4*)src)[i];
        v.x = f2tf_f(v.x); v.y = f2tf_f(v.y); v.z = f2tf_f(v.z); v.w = f2tf_f(v.w);
        ((float4*)dst)[i] = v;
    }
}

// deterministic fixed-order split-K reduction
__global__ __launch_bounds__(256) void reduce_parts_k(const float* __restrict__ src,
                                                      float* __restrict__ dst,
                                                      int n4, long stride4, int parts) {
    int i = blockIdx.x * 256 + threadIdx.x;
    if (i >= n4) return;
    float4 a = ((const float4*)src)[i];
    for (int p = 1; p < parts; p++) {
        float4 b = ((const float4*)src)[i + (size_t)p * stride4];
        a.x += b.x; a.y += b.y; a.z += b.z; a.w += b.w;
    }
    ((float4*)dst)[i] = a;
}

// ============================================================================
// TF32 GEMM TN: C[M,N] = A[M,K] @ B[N,K]^T. Inputs pre-rounded tf32.
// 128x64x32 CTA tile, 256 threads (8 warps 4x2, 32x32 warp tile),
// 3-stage cp.async pipeline (72 KB -> 3 CTAs/SM), ldmatrix.x4, XOR swizzle.
// rnd: tf32-round the epilogue store.
// ============================================================================
__global__ __launch_bounds__(256, 3) void gemm_tn_tc(
    const float* __restrict__ A, const float* __restrict__ B, float* __restrict__ C,
    int K, int lda, int ldb, int ldc,
    long sA, long sB, long sC, int rnd)
{
    int row0 = blockIdx.y * BM, col0 = blockIdx.x * BN;
    A += (long)blockIdx.z * sA;
    B += (long)blockIdx.z * sB;
    C += (long)blockIdx.z * sC;
    int niter = K / BK;

    extern __shared__ uint32_t smem[];
    uint32_t smem_b = (uint32_t)__cvta_generic_to_shared(smem);

    int tid = threadIdx.x, lane = tid & 31, warp = tid >> 5;
    int wm = warp >> 1, wn = warp & 1;   // 4 x 2 warps

    // ---- loader: A 4 float4/thread, B 2 float4/thread ----
    int ldr = tid >> 3;        // 0..31
    int ldk = tid & 7;
    uint32_t dstA[4], dstB[2];
    const float* srcA[4];
    const float* srcB[2];
    #pragma unroll
    for (int i = 0; i < 4; i++) {
        int r = ldr + i * 32;
        dstA[i] = smem_b + ((((r << 3) + (ldk ^ (r & 7)))) << 4);
        srcA[i] = A + (long)(row0 + r) * lda + (ldk << 2);
    }
    #pragma unroll
    for (int i = 0; i < 2; i++) {
        int r = ldr + i * 32;
        dstB[i] = smem_b + 16384 + ((((r << 3) + (ldk ^ (r & 7)))) << 4);
        srcB[i] = B + (long)(col0 + r) * ldb + (ldk << 2);
    }

    // ---- fragment base addresses (stage 0) ----
    int jr = ((lane >> 3) & 1) << 3;
    int jk = lane >> 4;
    int rr = lane & 7;
    uint32_t a_ad[2], b_ad[2];
    #pragma unroll
    for (int mt = 0; mt < 2; mt++) {
        int ar = wm * 32 + mt * 16 + jr + rr;
        a_ad[mt] = smem_b + (((ar << 3) + (jk ^ (ar & 7))) << 4);
    }
    #pragma unroll
    for (int ntp = 0; ntp < 2; ntp++) {
        int br = wn * 32 + ntp * 16 + jr + rr;
        b_ad[ntp] = smem_b + 16384 + (((br << 3) + (jk ^ (br & 7))) << 4);
    }

    float4 c[2][4];
    #pragma unroll
    for (int i = 0; i < 2; i++)
        #pragma unroll
        for (int j = 0; j < 4; j++) c[i][j] = make_float4(0.f, 0.f, 0.f, 0.f);

    // ---- prologue: stages 0,1 ----
    #pragma unroll
    for (int i = 0; i < 4; i++) CP16(dstA[i], srcA[i]);
    #pragma unroll
    for (int i = 0; i < 2; i++) CP16(dstB[i], srcB[i]);
    CP_COMMIT();
    if (niter > 1) {
        #pragma unroll
        for (int i = 0; i < 4; i++) CP16(dstA[i] + STAGE_BYTES, srcA[i] + BK);
        #pragma unroll
        for (int i = 0; i < 2; i++) CP16(dstB[i] + STAGE_BYTES, srcB[i] + BK);
    }
    CP_COMMIT();
    #pragma unroll
    for (int i = 0; i < 4; i++) srcA[i] += 2 * BK;
    #pragma unroll
    for (int i = 0; i < 2; i++) srcB[i] += 2 * BK;

    int stage = 0;
    for (int k = 0; k < niter; k++) {
        CP_WAIT1();
        __syncthreads();

        if (k + 2 < niter) {
            int s2 = stage + 2; if (s2 >= 3) s2 -= 3;
            uint32_t so2 = (uint32_t)s2 * STAGE_BYTES;
            #pragma unroll
            for (int i = 0; i < 4; i++) CP16(dstA[i] + so2, srcA[i]);
            #pragma unroll
            for (int i = 0; i < 2; i++) CP16(dstB[i] + so2, srcB[i]);
        }
        CP_COMMIT();
        #pragma unroll
        for (int i = 0; i < 4; i++) srcA[i] += BK;
        #pragma unroll
        for (int i = 0; i < 2; i++) srcB[i] += BK;

        uint32_t so = (uint32_t)stage * STAGE_BYTES;
        uint32_t aa[2], bb[2];
        #pragma unroll
        for (int mt = 0; mt < 2; mt++) aa[mt] = a_ad[mt] + so;
        #pragma unroll
        for (int ntp = 0; ntp < 2; ntp++) bb[ntp] = b_ad[ntp] + so;

        #pragma unroll
        for (int ks = 0; ks < 4; ks++) {
            uint32_t af[2][4];
            #pragma unroll
            for (int mt = 0; mt < 2; mt++) ldsm4(af[mt], aa[mt] ^ (ks << 5));
            uint32_t bf[4][2];
            #pragma unroll
            for (int ntp = 0; ntp < 2; ntp++) {
                uint32_t t[4];
                ldsm4(t, bb[ntp] ^ (ks << 5));
                bf[ntp * 2][0]     = t[0];
                bf[ntp * 2 + 1][0] = t[1];
                bf[ntp * 2][1]     = t[2];
                bf[ntp * 2 + 1][1] = t[3];
            }
            #pragma unroll
            for (int mt = 0; mt < 2; mt++)
                #pragma unroll
                for (int nt = 0; nt < 4; nt++)
                    mma_tf32(c[mt][nt], af[mt], bf[nt]);
        }
        stage++; if (stage >= 3) stage -= 3;
    }

    // epilogue
    #pragma unroll
    for (int mt = 0; mt < 2; mt++) {
        int m = row0 + wm * 32 + mt * 16 + (lane >> 2);
        #pragma unroll
        for (int nt = 0; nt < 4; nt++) {
            int n = col0 + wn * 32 + nt * 8 + ((lane & 3) << 1);
            float4 v = c[mt][nt];
            if (rnd) { v.x = f2tf_f(v.x); v.y = f2tf_f(v.y); v.z = f2tf_f(v.z); v.w = f2tf_f(v.w); }
            *(float2*)(C + (long)m * ldc + n)       = make_float2(v.x, v.y);
            *(float2*)(C + (long)(m + 8) * ldc + n) = make_float2(v.z, v.w);
        }
    }
}

// ============================================================================
// Fused flash attention: per CTA = (head h, 64-row q tile qi), online softmax.
// ============================================================================
__global__ __launch_bounds__(256, 1) void flash_attn(const float* __restrict__ sink) {
    int bx = blockIdx.x;
    int h  = bx & 15;
    int qi = 31 - (bx >> 4);          // heavy tiles first
    int q0 = qi * 64;
    int jn = qi + 1;

    extern __shared__ float smf[];
    uint32_t smb = (uint32_t)__cvta_generic_to_shared(smf);
    uint32_t smQ = smb, smKV = smb + F_KV * 4, smKVT = smb + F_KVT * 4, smP = smb + F_P * 4;

    int tid = threadIdx.x, lane = tid & 31, warp = tid >> 5;
    int wm = warp >> 2, wn = warp & 3;
    int jr = ((lane >> 3) & 1) << 3;
    int jk = lane >> 4;
    int rr = lane & 7;
    int g  = lane >> 2;
    int e2 = (lane & 3) << 1;

    const float4* q4   = (const float4*)g_q + (size_t)q0 * 1024 + (size_t)h * 64;
    const float4* kv4  = (const float4*)g_kv;
    const float4* kvT4 = (const float4*)g_kvT;

    #pragma unroll
    for (int i = 0; i < 16; i++) {
        int id = tid + i * 256, row = id >> 6, k4 = id & 63;
        uint32_t dst = smQ + (uint32_t)((row << 6) + (k4 & 56) + ((k4 ^ row) & 7)) * 16;
        CP16(dst, q4 + (size_t)row * 1024 + k4);
    }
    #pragma unroll
    for (int i = 0; i < 16; i++) {
        int id = tid + i * 256, row = id >> 6, k4 = id & 63;
        uint32_t dst = smKV + (uint32_t)((row << 6) + (k4 & 56) + ((k4 ^ row) & 7)) * 16;
        CP16(dst, kv4 + (size_t)row * 64 + k4);
    }
    CP_COMMIT();
    #pragma unroll
    for (int i = 0; i < 16; i++) {
        int id = tid + i * 256, rd = id >> 4, k4 = id & 15;
        uint32_t dst = smKVT + (uint32_t)((rd << 4) + (k4 & 8) + ((k4 ^ rd) & 7)) * 16;
        CP16(dst, kvT4 + (size_t)rd * 512 + k4);
    }
    CP_COMMIT();

    uint32_t aSb[2], bSb, aPb[2], bPVb[4];
    #pragma unroll
    for (int mt = 0; mt < 2; mt++) {
        int ar = wm * 32 + mt * 16 + jr + rr;
        aSb[mt] = smQ + (uint32_t)((ar << 6) + (jk ^ (ar & 7))) * 16;
        aPb[mt] = smP + (uint32_t)((ar << 4) + (jk ^ (ar & 7))) * 16;
    }
    {
        int br = wn * 16 + jr + rr;
        bSb = smKV + (uint32_t)((br << 6) + (jk ^ (br & 7))) * 16;
    }
    #pragma unroll
    for (int ntp = 0; ntp < 4; ntp++) {
        int br = wn * 64 + ntp * 16 + jr + rr;
        bPVb[ntp] = smKVT + (uint32_t)((br << 4) + (jk ^ (br & 7))) * 16;
    }

    float4 cO[2][8];
    #pragma unroll
    for (int mt = 0; mt < 2; mt++)
        #pragma unroll
        for (int nt = 0; nt < 8; nt++) cO[mt][nt] = make_float4(0.f, 0.f, 0.f, 0.f);
    float mrow[4] = {-3.0e38f, -3.0e38f, -3.0e38f, -3.0e38f};
    float lrow[4] = {0.f, 0.f, 0.f, 0.f};

    for (int j = 0; j < jn; j++) {
        CP_WAIT1();
        __syncthreads();

        float4 sS[2][2];
        #pragma unroll
        for (int mt = 0; mt < 2; mt++)
            #pragma unroll
            for (int nt = 0; nt < 2; nt++) sS[mt][nt] = make_float4(0.f, 0.f, 0.f, 0.f);

        #pragma unroll
        for (int cc = 0; cc < 8; cc++) {
            uint32_t ao = (uint32_t)cc * 128;
            #pragma unroll
            for (int ks = 0; ks < 4; ks++) {
                uint32_t af[2][4];
                #pragma unroll
                for (int mt = 0; mt < 2; mt++) ldsm4(af[mt], (aSb[mt] + ao) ^ (ks << 5));
                uint32_t tb[4];
                ldsm4(tb, (bSb + ao) ^ (ks << 5));
                uint32_t b0[2] = {tb[0], tb[2]}, b1[2] = {tb[1], tb[3]};
                #pragma unroll
                for (int mt = 0; mt < 2; mt++) {
                    mma_tf32(sS[mt][0], af[mt], b0);
                    mma_tf32(sS[mt][1], af[mt], b1);
                }
            }
        }

        #pragma unroll
        for (int mt = 0; mt < 2; mt++)
            #pragma unroll
            for (int nt = 0; nt < 2; nt++) {
                sS[mt][nt].x *= SCALE_; sS[mt][nt].y *= SCALE_;
                sS[mt][nt].z *= SCALE_; sS[mt][nt].w *= SCALE_;
            }
        if (j == qi) {
            #pragma unroll
            for (int mt = 0; mt < 2; mt++) {
                int r0 = wm * 32 + mt * 16 + g;
                #pragma unroll
                for (int nt = 0; nt < 2; nt++) {
                    int c0 = wn * 16 + nt * 8 + e2;
                    if (c0 > r0)     sS[mt][nt].x = -3.0e38f;
                    if (c0 + 1 > r0) sS[mt][nt].y = -3.0e38f;
                    if (c0 > r0 + 8)     sS[mt][nt].z = -3.0e38f;
                    if (c0 + 1 > r0 + 8) sS[mt][nt].w = -3.0e38f;
                }
            }
        }

        float rm[4];
        #pragma unroll
        for (int mt = 0; mt < 2; mt++) {
            rm[mt * 2 + 0] = fmaxf(fmaxf(sS[mt][0].x, sS[mt][0].y), fmaxf(sS[mt][1].x, sS[mt][1].y));
            rm[mt * 2 + 1] = fmaxf(fmaxf(sS[mt][0].z, sS[mt][0].w), fmaxf(sS[mt][1].z, sS[mt][1].w));
        }
        #pragma unroll
        for (int i = 0; i < 4; i++) {
            rm[i] = fmaxf(rm[i], __shfl_xor_sync(0xffffffffu, rm[i], 1));
            rm[i] = fmaxf(rm[i], __shfl_xor_sync(0xffffffffu, rm[i], 2));
        }
        #pragma unroll
        for (int i = 0; i < 4; i++) {
            int row = wm * 32 + (i >> 1) * 16 + g + (i & 1) * 8;
            smf[F_RED + wn * 64 + row] = rm[i];
        }
        __syncthreads();   // (A)

        if (j + 1 < jn) {
            const float4* kvs = kv4 + (size_t)(j + 1) * 64 * 64;
            #pragma unroll
            for (int i = 0; i < 16; i++) {
                int id = tid + i * 256, row = id >> 6, k4 = id & 63;
                uint32_t dst = smKV + (uint32_t)((row << 6) + (k4 & 56) + ((k4 ^ row) & 7)) * 16;
                CP16(dst, kvs + (size_t)row * 64 + k4);
            }
        }
        CP_COMMIT();

        float mnew[4], alpha[4];
        #pragma unroll
        for (int i = 0; i < 4; i++) {
            int row = wm * 32 + (i >> 1) * 16 + g + (i & 1) * 8;
            float tm = fmaxf(fmaxf(smf[F_RED + row], smf[F_RED + 64 + row]),
                             fmaxf(smf[F_RED + 128 + row], smf[F_RED + 192 + row]));
            mnew[i] = fmaxf(mrow[i], tm);
            alpha[i] = __expf(mrow[i] - mnew[i]);
            mrow[i] = mnew[i];
        }

        float ls[4];
        #pragma unroll
        for (int mt = 0; mt < 2; mt++) {
            #pragma unroll
            for (int nt = 0; nt < 2; nt++) {
                sS[mt][nt].x = __expf(sS[mt][nt].x - mnew[mt * 2 + 0]);
                sS[mt][nt].y = __expf(sS[mt][nt].y - mnew[mt * 2 + 0]);
                sS[mt][nt].z = __expf(sS[mt][nt].z - mnew[mt * 2 + 1]);
                sS[mt][nt].w = __expf(sS[mt][nt].w - mnew[mt * 2 + 1]);
            }
            ls[mt * 2 + 0] = sS[mt][0].x + sS[mt][0].y + sS[mt][1].x + sS[mt][1].y;
            ls[mt * 2 + 1] = sS[mt][0].z + sS[mt][0].w + sS[mt][1].z + sS[mt][1].w;
        }
        #pragma unroll
        for (int i = 0; i < 4; i++) {
            ls[i] += __shfl_xor_sync(0xffffffffu, ls[i], 1);
            ls[i] += __shfl_xor_sync(0xffffffffu, ls[i], 2);
        }
        #pragma unroll
        for (int i = 0; i < 4; i++) {
            int row = wm * 32 + (i >> 1) * 16 + g + (i & 1) * 8;
            smf[F_RED + 256 + wn * 64 + row] = ls[i];
        }
        __syncthreads();   // (B)
        #pragma unroll
        for (int i = 0; i < 4; i++) {
            int row = wm * 32 + (i >> 1) * 16 + g + (i & 1) * 8;
            float tl = smf[F_RED + 256 + row] + smf[F_RED + 256 + 64 + row] +
                       smf[F_RED + 256 + 128 + row] + smf[F_RED + 256 + 192 + row];
            lrow[i] = lrow[i] * alpha[i] + tl;
        }

        #pragma unroll
        for (int mt = 0; mt < 2; mt++)
            #pragma unroll
            for (int nt = 0; nt < 8; nt++) {
                cO[mt][nt].x *= alpha[mt * 2 + 0];
                cO[mt][nt].y *= alpha[mt * 2 + 0];
                cO[mt][nt].z *= alpha[mt * 2 + 1];
                cO[mt][nt].w *= alpha[mt * 2 + 1];
            }

        #pragma unroll
        for (int mt = 0; mt < 2; mt++)
            #pragma unroll
            for (int nt = 0; nt < 2; nt++) {
                int c = wn * 16 + nt * 8 + e2;
                int k4 = c >> 2;
                {
                    int row = wm * 32 + mt * 16 + g;
                    int fi = F_P + (((row << 4) + (k4 & 8) + ((k4 ^ row) & 7)) << 2) + (c & 2);
                    *(float2*)(smf + fi) = make_float2(f2tf_f(sS[mt][nt].x), f2tf_f(sS[mt][nt].y));
                }
                {
                    int row = wm * 32 + mt * 16 + g + 8;
                    int fi = F_P + (((row << 4) + (k4 & 8) + ((k4 ^ row) & 7)) << 2) + (c & 2);
                    *(float2*)(smf + fi) = make_float2(f2tf_f(sS[mt][nt].z), f2tf_f(sS[mt][nt].w));
                }
            }

        CP_WAIT1();
        __syncthreads();   // (C)

        #pragma unroll
        for (int kk = 0; kk < 8; kk++) {
            uint32_t xo = (uint32_t)((kk & 3) << 5);
            uint32_t ad = (uint32_t)((kk >> 2) << 7);
            uint32_t af[2][4];
            #pragma unroll
            for (int mt = 0; mt < 2; mt++) ldsm4(af[mt], (aPb[mt] + ad) ^ xo);
            #pragma unroll
            for (int ntp = 0; ntp < 4; ntp++) {
                uint32_t tb[4];
                ldsm4(tb, (bPVb[ntp] + ad) ^ xo);
                uint32_t b0[2] = {tb[0], tb[2]}, b1[2] = {tb[1], tb[3]};
                #pragma unroll
                for (int mt = 0; mt < 2; mt++) {
                    mma_tf32(cO[mt][ntp * 2 + 0], af[mt], b0);
                    mma_tf32(cO[mt][ntp * 2 + 1], af[mt], b1);
                }
            }
        }
        __syncthreads();   // (D)

        if (j + 1 < jn) {
            const float4* kvts = kvT4 + (size_t)(j + 1) * 16;
            #pragma unroll
            for (int i = 0; i < 16; i++) {
                int id = tid + i * 256, rd = id >> 4, k4 = id & 15;
                uint32_t dst = smKVT + (uint32_t)((rd << 4) + (k4 & 8) + ((k4 ^ rd) & 7)) * 16;
                CP16(dst, kvts + (size_t)rd * 512 + k4);
            }
        }
        CP_COMMIT();
    }

    float snk = sink[h];
    float fac[4];
    #pragma unroll
    for (int i = 0; i < 4; i++) {
        float mf = fmaxf(mrow[i], snk);
        float af = __expf(mrow[i] - mf);
        float lf = lrow[i] * af + __expf(snk - mf);
        fac[i] = af / lf;
    }
    #pragma unroll
    for (int mt = 0; mt < 2; mt++) {
        int r = q0 + wm * 32 + mt * 16 + g;
        #pragma unroll
        for (int nt = 0; nt < 8; nt++) {
            int c = wn * 64 + nt * 8 + e2;
            float* p0 = g_o + (size_t)r * (H_ * D_) + (size_t)h * D_ + c;
            *(float2*)p0 = make_float2(cO[mt][nt].x * fac[mt * 2 + 0], cO[mt][nt].y * fac[mt * 2 + 0]);
            *(float2*)(p0 + (size_t)8 * (H_ * D_)) =
                make_float2(cO[mt][nt].z * fac[mt * 2 + 1], cO[mt][nt].w * fac[mt * 2 + 1]);
        }
    }
}

// ---------------- elementwise / norm kernels ----------------
__global__ void cos_sin_k(const float* __restrict__ freqs) {
    int i = blockIdx.x * blockDim.x + threadIdx.x;
    if (i < S_ * RH_) {
        float f = freqs[i];
        g_cos[i] = cosf(f);
        g_sin[i] = sinf(f);
    }
}

__global__ __launch_bounds__(256) void rms_qa(const float* __restrict__ w) {
    int s = blockIdx.x;
    float* row = g_qa + (long)s * QL_;
    float ss = 0.f;
    for (int i = threadIdx.x; i < QL_; i += 256) { float v = row[i]; ss += v * v; }
    ss = block_reduce(ss, false);
    float sc = rsqrtf(ss / QL_ + EPS_);
    for (int i = threadIdx.x; i < QL_; i += 256) row[i] = f2tf_f(row[i] * sc * w[i]);
}

__global__ __launch_bounds__(256) void q_post() {
    int s = blockIdx.x, h = blockIdx.y;
    float* row = g_q + (size_t)s * (H_ * D_) + (size_t)h * D_;
    int d = threadIdx.x;
    float v = row[d];
    float ss = block_reduce(v * v, false);
    float sc = rsqrtf(ss / D_ + EPS_);
    __shared__ float sh[D_];
    sh[d] = v * sc;
    __syncthreads();
    float out;
    if (d < NOPE_) out = sh[d];
    else {
        int p = d - NOPE_, i = p >> 1;
        float cc = g_cos[s * RH_ + i], sn = g_sin[s * RH_ + i];
        float x1 = sh[NOPE_ + (i << 1)], x2 = sh[NOPE_ + (i << 1) + 1];
        out = (p & 1) ? (x1 * sn + x2 * cc) : (x1 * cc - x2 * sn);
    }
    row[d] = f2tf_f(out);
}

__global__ __launch_bounds__(256) void kv_post(const float* __restrict__ w) {
    int s = blockIdx.x;
    float* row = g_kv + (long)s * D_;
    int d = threadIdx.x;
    float v = row[d];
    float ss = block_reduce(v * v, false);
    float sc = rsqrtf(ss / D_ + EPS_);
    __shared__ float sh[D_];
    sh[d] = v * sc * w[d];
    __syncthreads();
    float out;
    if (d < NOPE_) out = sh[d];
    else {
        int p = d - NOPE_, i = p >> 1;
        float cc = g_cos[s * RH_ + i], sn = g_sin[s * RH_ + i];
        float x1 = sh[NOPE_ + (i << 1)], x2 = sh[NOPE_ + (i << 1) + 1];
        out = (p & 1) ? (x1 * sn + x2 * cc) : (x1 * cc - x2 * sn);
    }
    row[d] = f2tf_f(out);
}

__global__ __launch_bounds__(256) void transpose_kv() {
    __shared__ float t[32][33];
    int x = threadIdx.x & 31, y = threadIdx.x >> 5;
    #pragma unroll
    for (int i = 0; i < 4; i++) {
        int trow = blockIdx.x * 32 + y + i * 8;
        t[y + i * 8][x] = g_kv[(size_t)trow * D_ + blockIdx.y * 32 + x];
    }
    __syncthreads();
    #pragma unroll
    for (int i = 0; i < 4; i++) {
        int drow = blockIdx.y * 32 + y + i * 8;
        g_kvT[(size_t)drow * S_ + blockIdx.x * 32 + x] = t[x][y + i * 8];
    }
}

__global__ __launch_bounds__(256) void o_post() {
    int s = blockIdx.x, h = blockIdx.y;
    float* row = g_o + (size_t)s * (H_ * D_) + (size_t)h * D_;
    int d = threadIdx.x;
    __shared__ float sh[R_];
    float v = row[d];
    if (d >= NOPE_) sh[d - NOPE_] = v;
    __syncthreads();
    float out;
    if (d < NOPE_) out = v;
    else {
        int p = d - NOPE_, i = p >> 1;
        float cc = g_cos[s * RH_ + i], sn = g_sin[s * RH_ + i];
        float x1 = sh[i << 1], x2 = sh[(i << 1) + 1];
        out = (p & 1) ? (x2 * cc - x1 * sn) : (x1 * cc + x2 * sn);
    }
    row[d] = f2tf_f(out);
}

// ---------------- launch ----------------
extern "C" void kernel_launch(void* const* d_in, const int* in_sizes, int n_in,
                              void* d_out, int out_size) {
    const float* x        = (const float*)d_in[0];
    const float* freqs    = (const float*)d_in[1];
    const float* wq_a     = (const float*)d_in[2];
    const float* q_norm_w = (const float*)d_in[3];
    const float* wq_b     = (const float*)d_in[4];
    const float* wkv      = (const float*)d_in[5];
    const float* kv_norm_w= (const float*)d_in[6];
    const float* wo_a_w   = (const float*)d_in[7];
    const float* wo_b     = (const float*)d_in[8];
    const float* sink     = (const float*)d_in[9];
    float* out = (float*)d_out;

    float *p_x, *p_wqa, *p_wqb, *p_wkv, *p_woa, *p_wob;
    float *p_qa, *p_q, *p_kv, *p_o, *p_or, *p_part;
    cudaGetSymbolAddress((void**)&p_x,   g_x);
    cudaGetSymbolAddress((void**)&p_wqa, g_wqa);
    cudaGetSymbolAddress((void**)&p_wqb, g_wqb);
    cudaGetSymbolAddress((void**)&p_wkv, g_wkv);
    cudaGetSymbolAddress((void**)&p_woa, g_woa);
    cudaGetSymbolAddress((void**)&p_wob, g_wob);
    cudaGetSymbolAddress((void**)&p_qa,  g_qa);
    cudaGetSymbolAddress((void**)&p_q,   g_q);
    cudaGetSymbolAddress((void**)&p_kv,  g_kv);
    cudaGetSymbolAddress((void**)&p_o,   g_o);
    cudaGetSymbolAddress((void**)&p_or,  g_or);
    cudaGetSymbolAddress((void**)&p_part, g_part);

    cudaFuncSetAttribute(gemm_tn_tc, cudaFuncAttributeMaxDynamicSharedMemorySize, GEMM_SMEM);
    cudaFuncSetAttribute(flash_attn, cudaFuncAttributeMaxDynamicSharedMemorySize, FLASH_SMEM);

    cos_sin_k<<<(S_ * RH_ + 255) / 256, 256>>>(freqs);

    round_tf32_k<<<(S_ * HID_ / 4 + 255) / 256, 256>>>(x, p_x, S_ * HID_ / 4);
    round_tf32_k<<<(QL_ * HID_ / 4 + 255) / 256, 256>>>(wq_a, p_wqa, QL_ * HID_ / 4);
    round_tf32_k<<<(H_ * D_ * QL_ / 4 + 255) / 256, 256>>>(wq_b, p_wqb, H_ * D_ * QL_ / 4);
    round_tf32_k<<<(D_ * HID_ / 4 + 255) / 256, 256>>>(wkv, p_wkv, D_ * HID_ / 4);
    round_tf32_k<<<(G_ * OR_ * 1024 / 4 + 255) / 256, 256>>>(wo_a_w, p_woa, G_ * OR_ * 1024 / 4);
    round_tf32_k<<<(HID_ * G_ * OR_ / 4 + 255) / 256, 256>>>(wo_b, p_wob, HID_ * G_ * OR_ / 4);

    // q_a = x @ wq_a^T   — split-K x4: Kc=512
    gemm_tn_tc<<<dim3(QL_ / BN, S_ / BM, 4), 256, GEMM_SMEM>>>(p_x, p_wqa, p_part,
        512, HID_, HID_, QL_, 512, 512, (long)S_ * QL_, 0);
    reduce_parts_k<<<(S_ * QL_ / 4 + 255) / 256, 256>>>(p_part, p_qa,
        S_ * QL_ / 4, (long)S_ * QL_ / 4, 4);
    rms_qa<<<S_, 256>>>(q_norm_w);

    // q = qa @ wq_b^T
    gemm_tn_tc<<<dim3((H_ * D_) / BN, S_ / BM, 1), 256, GEMM_SMEM>>>(p_qa, p_wqb, p_q,
        QL_, QL_, QL_, H_ * D_, 0, 0, 0, 0);
    q_post<<<dim3(S_, H_), 256>>>();

    // kv = x @ wkv^T     — split-K x8: Kc=256
    gemm_tn_tc<<<dim3(D_ / BN, S_ / BM, 8), 256, GEMM_SMEM>>>(p_x, p_wkv, p_part,
        256, HID_, HID_, D_, 256, 256, (long)S_ * D_, 0);
    reduce_parts_k<<<(S_ * D_ / 4 + 255) / 256, 256>>>(p_part, p_kv,
        S_ * D_ / 4, (long)S_ * D_ / 4, 8);
    kv_post<<<S_, 256>>>(kv_norm_w);
    transpose_kv<<<dim3(S_ / 32, D_ / 32), 256>>>();

    // fused attention
    flash_attn<<<512, 256, FLASH_SMEM>>>(sink);

    o_post<<<dim3(S_, H_), 256>>>();

    // grouped wo_a (tf32-rounded output in epilogue)
    gemm_tn_tc<<<dim3(OR_ / BN, S_ / BM, G_), 256, GEMM_SMEM>>>(p_o, p_woa, p_or,
        (H_ / G_) * D_, H_ * D_, (H_ / G_) * D_, G_ * OR_,
        (long)(H_ / G_) * D_, (long)OR_ * (H_ / G_) * D_, (long)OR_, 1);

    // out = o_r @ wo_b^T — split-K x2: Kc=1024
    gemm_tn_tc<<<dim3(HID_ / BN, S_ / BM, 2), 256, GEMM_SMEM>>>(p_or, p_wob, p_part,
        1024, G_ * OR_, G_ * OR_, HID_, 1024, 1024, (long)S_ * HID_, 0);
    reduce_parts_k<<<(S_ * HID_ / 4 + 255) / 256, 256>>>(p_part, out,
        S_ * HID_ / 4, (long)S_ * HID_ / 4, 2);
}

// round 12
// speedup vs baseline: 2.2967x; 1.0144x over previous
#include <cuda_runtime.h>
#include <cstdint>

#define S_    2048
#define HID_  2048
#define H_    16
#define D_    256
#define R_    64
#define RH_   32          // R/2
#define NOPE_ 192
#define QL_   1024
#define OR_   512
#define G_    4
#define EPS_  1e-6f
#define SCALE_ 0.0625f    // 256^-0.5

#define BM 128
#define BN 64
#define BK 32
#define STAGE_BYTES 24576            // A 16KB + B 8KB per stage
#define GEMM_SMEM (3 * STAGE_BYTES)  // 72 KB -> 3 CTAs/SM

// flash smem (floats): Q 16384 | KV 16384 | KVT 16384 | P 4096 | RED 512
#define F_Q   0
#define F_KV  16384
#define F_KVT 32768
#define F_P   49152
#define F_RED 53248
#define FLASH_SMEM ((53248 + 512) * 4)

// ---------------- scratch ----------------
__device__ float g_cos[S_ * RH_];
__device__ float g_sin[S_ * RH_];
__device__ float g_x[(size_t)S_ * HID_];
__device__ float g_wqa[(size_t)QL_ * HID_];
__device__ float g_wqb[(size_t)H_ * D_ * QL_];
__device__ float g_wkv[(size_t)D_ * HID_];
__device__ float g_woa[(size_t)G_ * OR_ * 1024];
__device__ float g_wob[(size_t)HID_ * G_ * OR_];
__device__ float g_qa[(size_t)S_ * QL_];
__device__ float g_q[(size_t)S_ * H_ * D_];
__device__ float g_kv[(size_t)S_ * D_];
__device__ float g_kvT[(size_t)D_ * S_];
__device__ float g_o[(size_t)S_ * H_ * D_];
__device__ float g_or[(size_t)S_ * G_ * OR_];
__device__ float g_part[(size_t)8 * 1024 * 1024];   // 32 MB split-K partials

// ---------------- helpers ----------------
__device__ __forceinline__ uint32_t f2tf(float x) {
    uint32_t r;
    asm("cvt.rna.tf32.f32 %0, %1;" : "=r"(r) : "f"(x));
    return r;
}
__device__ __forceinline__ float f2tf_f(float x) { return __uint_as_float(f2tf(x)); }

__device__ __forceinline__ void mma_tf32(float4& c, const uint32_t a[4], const uint32_t b[2]) {
    asm volatile(
        "mma.sync.aligned.m16n8k8.row.col.f32.tf32.tf32.f32 "
        "{%0,%1,%2,%3}, {%4,%5,%6,%7}, {%8,%9}, {%0,%1,%2,%3};\n"
        : "+f"(c.x), "+f"(c.y), "+f"(c.z), "+f"(c.w)
        : "r"(a[0]), "r"(a[1]), "r"(a[2]), "r"(a[3]), "r"(b[0]), "r"(b[1]));
}
__device__ __forceinline__ void ldsm4(uint32_t* d, uint32_t addr) {
    asm volatile("ldmatrix.sync.aligned.m8n8.x4.shared.b16 {%0,%1,%2,%3}, [%4];"
        : "=r"(d[0]), "=r"(d[1]), "=r"(d[2]), "=r"(d[3]) : "r"(addr));
}
#define CP16(dst, src) \
    asm volatile("cp.async.cg.shared.global [%0], [%1], 16;\n" :: "r"(dst), "l"(src))
#define CP_COMMIT() asm volatile("cp.async.commit_group;\n")
#define CP_WAIT1()  asm volatile("cp.async.wait_group 1;\n")

__device__ __forceinline__ float block_reduce(float v, bool is_max) {
    __shared__ float warp_res[8];
    __shared__ float result;
    __syncthreads();
    #pragma unroll
    for (int o = 16; o; o >>= 1) {
        float other = __shfl_xor_sync(0xffffffffu, v, o);
        v = is_max ? fmaxf(v, other) : (v + other);
    }
    if ((threadIdx.x & 31) == 0) warp_res[threadIdx.x >> 5] = v;
    __syncthreads();
    if (threadIdx.x == 0) {
        int nw = (blockDim.x + 31) >> 5;
        float r = warp_res[0];
        for (int i = 1; i < nw; i++) r = is_max ? fmaxf(r, warp_res[i]) : (r + warp_res[i]);
        result = r;
    }
    __syncthreads();
    return result;
}

__global__ __launch_bounds__(256) void round_tf32_k(const float* __restrict__ src,
                                                    float* __restrict__ dst, int n4) {
    int i = blockIdx.x * 256 + threadIdx.x;
    if (i < n4) {
        float4 v = ((const float4*)src)[i];
        v.x = f2tf_f(v.x); v.y = f2tf_f(v.y); v.z = f2tf_f(v.z); v.w = f2tf_f(v.w);
        ((float4*)dst)[i] = v;
    }
}

// deterministic fixed-order split-K reduction (final output only)
__global__ __launch_bounds__(256) void reduce_parts_k(const float* __restrict__ src,
                                                      float* __restrict__ dst,
                                                      int n4, long stride4, int parts) {
    int i = blockIdx.x * 256 + threadIdx.x;
    if (i >= n4) return;
    float4 a = ((const float4*)src)[i];
    for (int p = 1; p < parts; p++) {
        float4 b = ((const float4*)src)[i + (size_t)p * stride4];
        a.x += b.x; a.y += b.y; a.z += b.z; a.w += b.w;
    }
    ((float4*)dst)[i] = a;
}

// fused: qa = rms(sum of 4 split-K partials) * w, tf32-rounded. One block per row.
__global__ __launch_bounds__(256) void reduce_rms_qa(const float* __restrict__ part,
                                                     const float* __restrict__ w) {
    int s = blockIdx.x;
    const float* p0 = part + (long)s * QL_;
    float v[4];
    float ss = 0.f;
    #pragma unroll
    for (int i = 0; i < 4; i++) {
        int idx = threadIdx.x + i * 256;
        float a = p0[idx] + p0[idx + (long)S_ * QL_] +
                  p0[idx + 2L * S_ * QL_] + p0[idx + 3L * S_ * QL_];
        v[i] = a;
        ss += a * a;
    }
    ss = block_reduce(ss, false);
    float sc = rsqrtf(ss / QL_ + EPS_);
    #pragma unroll
    for (int i = 0; i < 4; i++) {
        int idx = threadIdx.x + i * 256;
        g_qa[(long)s * QL_ + idx] = f2tf_f(v[i] * sc * w[idx]);
    }
}

// fused: kv = rope(rms(sum of 8 split-K partials) * w), tf32-rounded. One block per row.
__global__ __launch_bounds__(256) void reduce_kv_post(const float* __restrict__ part,
                                                      const float* __restrict__ w) {
    int s = blockIdx.x;
    int d = threadIdx.x;
    const float* p0 = part + (long)s * D_ + d;
    float v = 0.f;
    #pragma unroll
    for (int p = 0; p < 8; p++) v += p0[(long)p * S_ * D_];
    float ss = block_reduce(v * v, false);
    float sc = rsqrtf(ss / D_ + EPS_);
    __shared__ float sh[D_];
    sh[d] = v * sc * w[d];
    __syncthreads();
    float out;
    if (d < NOPE_) out = sh[d];
    else {
        int p = d - NOPE_, i = p >> 1;
        float cc = g_cos[s * RH_ + i], sn = g_sin[s * RH_ + i];
        float x1 = sh[NOPE_ + (i << 1)], x2 = sh[NOPE_ + (i << 1) + 1];
        out = (p & 1) ? (x1 * sn + x2 * cc) : (x1 * cc - x2 * sn);
    }
    g_kv[(long)s * D_ + d] = f2tf_f(out);
}

// ============================================================================
// TF32 GEMM TN: C[M,N] = A[M,K] @ B[N,K]^T. Inputs pre-rounded tf32.
// 128x64x32 CTA tile, 256 threads (8 warps 4x2, 32x32 warp tile),
// 3-stage cp.async pipeline (72 KB -> 3 CTAs/SM), ldmatrix.x4, XOR swizzle.
// ============================================================================
__global__ __launch_bounds__(256, 3) void gemm_tn_tc(
    const float* __restrict__ A, const float* __restrict__ B, float* __restrict__ C,
    int K, int lda, int ldb, int ldc,
    long sA, long sB, long sC, int rnd)
{
    int row0 = blockIdx.y * BM, col0 = blockIdx.x * BN;
    A += (long)blockIdx.z * sA;
    B += (long)blockIdx.z * sB;
    C += (long)blockIdx.z * sC;
    int niter = K / BK;

    extern __shared__ uint32_t smem[];
    uint32_t smem_b = (uint32_t)__cvta_generic_to_shared(smem);

    int tid = threadIdx.x, lane = tid & 31, warp = tid >> 5;
    int wm = warp >> 1, wn = warp & 1;   // 4 x 2 warps

    int ldr = tid >> 3;
    int ldk = tid & 7;
    uint32_t dstA[4], dstB[2];
    const float* srcA[4];
    const float* srcB[2];
    #pragma unroll
    for (int i = 0; i < 4; i++) {
        int r = ldr + i * 32;
        dstA[i] = smem_b + ((((r << 3) + (ldk ^ (r & 7)))) << 4);
        srcA[i] = A + (long)(row0 + r) * lda + (ldk << 2);
    }
    #pragma unroll
    for (int i = 0; i < 2; i++) {
        int r = ldr + i * 32;
        dstB[i] = smem_b + 16384 + ((((r << 3) + (ldk ^ (r & 7)))) << 4);
        srcB[i] = B + (long)(col0 + r) * ldb + (ldk << 2);
    }

    int jr = ((lane >> 3) & 1) << 3;
    int jk = lane >> 4;
    int rr = lane & 7;
    uint32_t a_ad[2], b_ad[2];
    #pragma unroll
    for (int mt = 0; mt < 2; mt++) {
        int ar = wm * 32 + mt * 16 + jr + rr;
        a_ad[mt] = smem_b + (((ar << 3) + (jk ^ (ar & 7))) << 4);
    }
    #pragma unroll
    for (int ntp = 0; ntp < 2; ntp++) {
        int br = wn * 32 + ntp * 16 + jr + rr;
        b_ad[ntp] = smem_b + 16384 + (((br << 3) + (jk ^ (br & 7))) << 4);
    }

    float4 c[2][4];
    #pragma unroll
    for (int i = 0; i < 2; i++)
        #pragma unroll
        for (int j = 0; j < 4; j++) c[i][j] = make_float4(0.f, 0.f, 0.f, 0.f);

    #pragma unroll
    for (int i = 0; i < 4; i++) CP16(dstA[i], srcA[i]);
    #pragma unroll
    for (int i = 0; i < 2; i++) CP16(dstB[i], srcB[i]);
    CP_COMMIT();
    if (niter > 1) {
        #pragma unroll
        for (int i = 0; i < 4; i++) CP16(dstA[i] + STAGE_BYTES, srcA[i] + BK);
        #pragma unroll
        for (int i = 0; i < 2; i++) CP16(dstB[i] + STAGE_BYTES, srcB[i] + BK);
    }
    CP_COMMIT();
    #pragma unroll
    for (int i = 0; i < 4; i++) srcA[i] += 2 * BK;
    #pragma unroll
    for (int i = 0; i < 2; i++) srcB[i] += 2 * BK;

    int stage = 0;
    for (int k = 0; k < niter; k++) {
        CP_WAIT1();
        __syncthreads();

        if (k + 2 < niter) {
            int s2 = stage + 2; if (s2 >= 3) s2 -= 3;
            uint32_t so2 = (uint32_t)s2 * STAGE_BYTES;
            #pragma unroll
            for (int i = 0; i < 4; i++) CP16(dstA[i] + so2, srcA[i]);
            #pragma unroll
            for (int i = 0; i < 2; i++) CP16(dstB[i] + so2, srcB[i]);
        }
        CP_COMMIT();
        #pragma unroll
        for (int i = 0; i < 4; i++) srcA[i] += BK;
        #pragma unroll
        for (int i = 0; i < 2; i++) srcB[i] += BK;

        uint32_t so = (uint32_t)stage * STAGE_BYTES;
        uint32_t aa[2], bb[2];
        #pragma unroll
        for (int mt = 0; mt < 2; mt++) aa[mt] = a_ad[mt] + so;
        #pragma unroll
        for (int ntp = 0; ntp < 2; ntp++) bb[ntp] = b_ad[ntp] + so;

        #pragma unroll
        for (int ks = 0; ks < 4; ks++) {
            uint32_t af[2][4];
            #pragma unroll
            for (int mt = 0; mt < 2; mt++) ldsm4(af[mt], aa[mt] ^ (ks << 5));
            uint32_t bf[4][2];
            #pragma unroll
            for (int ntp = 0; ntp < 2; ntp++) {
                uint32_t t[4];
                ldsm4(t, bb[ntp] ^ (ks << 5));
                bf[ntp * 2][0]     = t[0];
                bf[ntp * 2 + 1][0] = t[1];
                bf[ntp * 2][1]     = t[2];
                bf[ntp * 2 + 1][1] = t[3];
            }
            #pragma unroll
            for (int mt = 0; mt < 2; mt++)
                #pragma unroll
                for (int nt = 0; nt < 4; nt++)
                    mma_tf32(c[mt][nt], af[mt], bf[nt]);
        }
        stage++; if (stage >= 3) stage -= 3;
    }

    #pragma unroll
    for (int mt = 0; mt < 2; mt++) {
        int m = row0 + wm * 32 + mt * 16 + (lane >> 2);
        #pragma unroll
        for (int nt = 0; nt < 4; nt++) {
            int n = col0 + wn * 32 + nt * 8 + ((lane & 3) << 1);
            float4 v = c[mt][nt];
            if (rnd) { v.x = f2tf_f(v.x); v.y = f2tf_f(v.y); v.z = f2tf_f(v.z); v.w = f2tf_f(v.w); }
            *(float2*)(C + (long)m * ldc + n)       = make_float2(v.x, v.y);
            *(float2*)(C + (long)(m + 8) * ldc + n) = make_float2(v.z, v.w);
        }
    }
}

// ============================================================================
// Fused flash attention: per CTA = (head h, 64-row q tile qi), online softmax.
// ============================================================================
__global__ __launch_bounds__(256, 1) void flash_attn(const float* __restrict__ sink) {
    int bx = blockIdx.x;
    int h  = bx & 15;
    int qi = 31 - (bx >> 4);          // heavy tiles first
    int q0 = qi * 64;
    int jn = qi + 1;

    extern __shared__ float smf[];
    uint32_t smb = (uint32_t)__cvta_generic_to_shared(smf);
    uint32_t smQ = smb, smKV = smb + F_KV * 4, smKVT = smb + F_KVT * 4, smP = smb + F_P * 4;

    int tid = threadIdx.x, lane = tid & 31, warp = tid >> 5;
    int wm = warp >> 2, wn = warp & 3;
    int jr = ((lane >> 3) & 1) << 3;
    int jk = lane >> 4;
    int rr = lane & 7;
    int g  = lane >> 2;
    int e2 = (lane & 3) << 1;

    const float4* q4   = (const float4*)g_q + (size_t)q0 * 1024 + (size_t)h * 64;
    const float4* kv4  = (const float4*)g_kv;
    const float4* kvT4 = (const float4*)g_kvT;

    #pragma unroll
    for (int i = 0; i < 16; i++) {
        int id = tid + i * 256, row = id >> 6, k4 = id & 63;
        uint32_t dst = smQ + (uint32_t)((row << 6) + (k4 & 56) + ((k4 ^ row) & 7)) * 16;
        CP16(dst, q4 + (size_t)row * 1024 + k4);
    }
    #pragma unroll
    for (int i = 0; i < 16; i++) {
        int id = tid + i * 256, row = id >> 6, k4 = id & 63;
        uint32_t dst = smKV + (uint32_t)((row << 6) + (k4 & 56) + ((k4 ^ row) & 7)) * 16;
        CP16(dst, kv4 + (size_t)row * 64 + k4);
    }
    CP_COMMIT();
    #pragma unroll
    for (int i = 0; i < 16; i++) {
        int id = tid + i * 256, rd = id >> 4, k4 = id & 15;
        uint32_t dst = smKVT + (uint32_t)((rd << 4) + (k4 & 8) + ((k4 ^ rd) & 7)) * 16;
        CP16(dst, kvT4 + (size_t)rd * 512 + k4);
    }
    CP_COMMIT();

    uint32_t aSb[2], bSb, aPb[2], bPVb[4];
    #pragma unroll
    for (int mt = 0; mt < 2; mt++) {
        int ar = wm * 32 + mt * 16 + jr + rr;
        aSb[mt] = smQ + (uint32_t)((ar << 6) + (jk ^ (ar & 7))) * 16;
        aPb[mt] = smP + (uint32_t)((ar << 4) + (jk ^ (ar & 7))) * 16;
    }
    {
        int br = wn * 16 + jr + rr;
        bSb = smKV + (uint32_t)((br << 6) + (jk ^ (br & 7))) * 16;
    }
    #pragma unroll
    for (int ntp = 0; ntp < 4; ntp++) {
        int br = wn * 64 + ntp * 16 + jr + rr;
        bPVb[ntp] = smKVT + (uint32_t)((br << 4) + (jk ^ (br & 7))) * 16;
    }

    float4 cO[2][8];
    #pragma unroll
    for (int mt = 0; mt < 2; mt++)
        #pragma unroll
        for (int nt = 0; nt < 8; nt++) cO[mt][nt] = make_float4(0.f, 0.f, 0.f, 0.f);
    float mrow[4] = {-3.0e38f, -3.0e38f, -3.0e38f, -3.0e38f};
    float lrow[4] = {0.f, 0.f, 0.f, 0.f};

    for (int j = 0; j < jn; j++) {
        CP_WAIT1();
        __syncthreads();

        float4 sS[2][2];
        #pragma unroll
        for (int mt = 0; mt < 2; mt++)
            #pragma unroll
            for (int nt = 0; nt < 2; nt++) sS[mt][nt] = make_float4(0.f, 0.f, 0.f, 0.f);

        #pragma unroll
        for (int cc = 0; cc < 8; cc++) {
            uint32_t ao = (uint32_t)cc * 128;
            #pragma unroll
            for (int ks = 0; ks < 4; ks++) {
                uint32_t af[2][4];
                #pragma unroll
                for (int mt = 0; mt < 2; mt++) ldsm4(af[mt], (aSb[mt] + ao) ^ (ks << 5));
                uint32_t tb[4];
                ldsm4(tb, (bSb + ao) ^ (ks << 5));
                uint32_t b0[2] = {tb[0], tb[2]}, b1[2] = {tb[1], tb[3]};
                #pragma unroll
                for (int mt = 0; mt < 2; mt++) {
                    mma_tf32(sS[mt][0], af[mt], b0);
                    mma_tf32(sS[mt][1], af[mt], b1);
                }
            }
        }

        #pragma unroll
        for (int mt = 0; mt < 2; mt++)
            #pragma unroll
            for (int nt = 0; nt < 2; nt++) {
                sS[mt][nt].x *= SCALE_; sS[mt][nt].y *= SCALE_;
                sS[mt][nt].z *= SCALE_; sS[mt][nt].w *= SCALE_;
            }
        if (j == qi) {
            #pragma unroll
            for (int mt = 0; mt < 2; mt++) {
                int r0 = wm * 32 + mt * 16 + g;
                #pragma unroll
                for (int nt = 0; nt < 2; nt++) {
                    int c0 = wn * 16 + nt * 8 + e2;
                    if (c0 > r0)     sS[mt][nt].x = -3.0e38f;
                    if (c0 + 1 > r0) sS[mt][nt].y = -3.0e38f;
                    if (c0 > r0 + 8)     sS[mt][nt].z = -3.0e38f;
                    if (c0 + 1 > r0 + 8) sS[mt][nt].w = -3.0e38f;
                }
            }
        }

        float rm[4];
        #pragma unroll
        for (int mt = 0; mt < 2; mt++) {
            rm[mt * 2 + 0] = fmaxf(fmaxf(sS[mt][0].x, sS[mt][0].y), fmaxf(sS[mt][1].x, sS[mt][1].y));
            rm[mt * 2 + 1] = fmaxf(fmaxf(sS[mt][0].z, sS[mt][0].w), fmaxf(sS[mt][1].z, sS[mt][1].w));
        }
        #pragma unroll
        for (int i = 0; i < 4; i++) {
            rm[i] = fmaxf(rm[i], __shfl_xor_sync(0xffffffffu, rm[i], 1));
            rm[i] = fmaxf(rm[i], __shfl_xor_sync(0xffffffffu, rm[i], 2));
        }
        #pragma unroll
        for (int i = 0; i < 4; i++) {
            int row = wm * 32 + (i >> 1) * 16 + g + (i & 1) * 8;
            smf[F_RED + wn * 64 + row] = rm[i];
        }
        __syncthreads();   // (A)

        if (j + 1 < jn) {
            const float4* kvs = kv4 + (size_t)(j + 1) * 64 * 64;
            #pragma unroll
            for (int i = 0; i < 16; i++) {
                int id = tid + i * 256, row = id >> 6, k4 = id & 63;
                uint32_t dst = smKV + (uint32_t)((row << 6) + (k4 & 56) + ((k4 ^ row) & 7)) * 16;
                CP16(dst, kvs + (size_t)row * 64 + k4);
            }
        }
        CP_COMMIT();

        float mnew[4], alpha[4];
        #pragma unroll
        for (int i = 0; i < 4; i++) {
            int row = wm * 32 + (i >> 1) * 16 + g + (i & 1) * 8;
            float tm = fmaxf(fmaxf(smf[F_RED + row], smf[F_RED + 64 + row]),
                             fmaxf(smf[F_RED + 128 + row], smf[F_RED + 192 + row]));
            mnew[i] = fmaxf(mrow[i], tm);
            alpha[i] = __expf(mrow[i] - mnew[i]);
            mrow[i] = mnew[i];
        }

        float ls[4];
        #pragma unroll
        for (int mt = 0; mt < 2; mt++) {
            #pragma unroll
            for (int nt = 0; nt < 2; nt++) {
                sS[mt][nt].x = __expf(sS[mt][nt].x - mnew[mt * 2 + 0]);
                sS[mt][nt].y = __expf(sS[mt][nt].y - mnew[mt * 2 + 0]);
                sS[mt][nt].z = __expf(sS[mt][nt].z - mnew[mt * 2 + 1]);
                sS[mt][nt].w = __expf(sS[mt][nt].w - mnew[mt * 2 + 1]);
            }
            ls[mt * 2 + 0] = sS[mt][0].x + sS[mt][0].y + sS[mt][1].x + sS[mt][1].y;
            ls[mt * 2 + 1] = sS[mt][0].z + sS[mt][0].w + sS[mt][1].z + sS[mt][1].w;
        }
        #pragma unroll
        for (int i = 0; i < 4; i++) {
            ls[i] += __shfl_xor_sync(0xffffffffu, ls[i], 1);
            ls[i] += __shfl_xor_sync(0xffffffffu, ls[i], 2);
        }
        #pragma unroll
        for (int i = 0; i < 4; i++) {
            int row = wm * 32 + (i >> 1) * 16 + g + (i & 1) * 8;
            smf[F_RED + 256 + wn * 64 + row] = ls[i];
        }
        __syncthreads();   // (B)
        #pragma unroll
        for (int i = 0; i < 4; i++) {
            int row = wm * 32 + (i >> 1) * 16 + g + (i & 1) * 8;
            float tl = smf[F_RED + 256 + row] + smf[F_RED + 256 + 64 + row] +
                       smf[F_RED + 256 + 128 + row] + smf[F_RED + 256 + 192 + row];
            lrow[i] = lrow[i] * alpha[i] + tl;
        }

        #pragma unroll
        for (int mt = 0; mt < 2; mt++)
            #pragma unroll
            for (int nt = 0; nt < 8; nt++) {
                cO[mt][nt].x *= alpha[mt * 2 + 0];
                cO[mt][nt].y *= alpha[mt * 2 + 0];
                cO[mt][nt].z *= alpha[mt * 2 + 1];
                cO[mt][nt].w *= alpha[mt * 2 + 1];
            }

        #pragma unroll
        for (int mt = 0; mt < 2; mt++)
            #pragma unroll
            for (int nt = 0; nt < 2; nt++) {
                int c = wn * 16 + nt * 8 + e2;
                int k4 = c >> 2;
                {
                    int row = wm * 32 + mt * 16 + g;
                    int fi = F_P + (((row << 4) + (k4 & 8) + ((k4 ^ row) & 7)) << 2) + (c & 2);
                    *(float2*)(smf + fi) = make_float2(f2tf_f(sS[mt][nt].x), f2tf_f(sS[mt][nt].y));
                }
                {
                    int row = wm * 32 + mt * 16 + g + 8;
                    int fi = F_P + (((row << 4) + (k4 & 8) + ((k4 ^ row) & 7)) << 2) + (c & 2);
                    *(float2*)(smf + fi) = make_float2(f2tf_f(sS[mt][nt].z), f2tf_f(sS[mt][nt].w));
                }
            }

        CP_WAIT1();
        __syncthreads();   // (C)

        #pragma unroll
        for (int kk = 0; kk < 8; kk++) {
            uint32_t xo = (uint32_t)((kk & 3) << 5);
            uint32_t ad = (uint32_t)((kk >> 2) << 7);
            uint32_t af[2][4];
            #pragma unroll
            for (int mt = 0; mt < 2; mt++) ldsm4(af[mt], (aPb[mt] + ad) ^ xo);
            #pragma unroll
            for (int ntp = 0; ntp < 4; ntp++) {
                uint32_t tb[4];
                ldsm4(tb, (bPVb[ntp] + ad) ^ xo);
                uint32_t b0[2] = {tb[0], tb[2]}, b1[2] = {tb[1], tb[3]};
                #pragma unroll
                for (int mt = 0; mt < 2; mt++) {
                    mma_tf32(cO[mt][ntp * 2 + 0], af[mt], b0);
                    mma_tf32(cO[mt][ntp * 2 + 1], af[mt], b1);
                }
            }
        }
        __syncthreads();   // (D)

        if (j + 1 < jn) {
            const float4* kvts = kvT4 + (size_t)(j + 1) * 16;
            #pragma unroll
            for (int i = 0; i < 16; i++) {
                int id = tid + i * 256, rd = id >> 4, k4 = id & 15;
                uint32_t dst = smKVT + (uint32_t)((rd << 4) + (k4 & 8) + ((k4 ^ rd) & 7)) * 16;
                CP16(dst, kvts + (size_t)rd * 512 + k4);
            }
        }
        CP_COMMIT();
    }

    float snk = sink[h];
    float fac[4];
    #pragma unroll
    for (int i = 0; i < 4; i++) {
        float mf = fmaxf(mrow[i], snk);
        float af = __expf(mrow[i] - mf);
        float lf = lrow[i] * af + __expf(snk - mf);
        fac[i] = af / lf;
    }
    #pragma unroll
    for (int mt = 0; mt < 2; mt++) {
        int r = q0 + wm * 32 + mt * 16 + g;
        #pragma unroll
        for (int nt = 0; nt < 8; nt++) {
            int c = wn * 64 + nt * 8 + e2;
            float* p0 = g_o + (size_t)r * (H_ * D_) + (size_t)h * D_ + c;
            *(float2*)p0 = make_float2(cO[mt][nt].x * fac[mt * 2 + 0], cO[mt][nt].y * fac[mt * 2 + 0]);
            *(float2*)(p0 + (size_t)8 * (H_ * D_)) =
                make_float2(cO[mt][nt].z * fac[mt * 2 + 1], cO[mt][nt].w * fac[mt * 2 + 1]);
        }
    }
}

// ---------------- elementwise / norm kernels ----------------
__global__ void cos_sin_k(const float* __restrict__ freqs) {
    int i = blockIdx.x * blockDim.x + threadIdx.x;
    if (i < S_ * RH_) {
        float f = freqs[i];
        g_cos[i] = cosf(f);
        g_sin[i] = sinf(f);
    }
}

__global__ __launch_bounds__(256) void q_post() {
    int s = blockIdx.x, h = blockIdx.y;
    float* row = g_q + (size_t)s * (H_ * D_) + (size_t)h * D_;
    int d = threadIdx.x;
    float v = row[d];
    float ss = block_reduce(v * v, false);
    float sc = rsqrtf(ss / D_ + EPS_);
    __shared__ float sh[D_];
    sh[d] = v * sc;
    __syncthreads();
    float out;
    if (d < NOPE_) out = sh[d];
    else {
        int p = d - NOPE_, i = p >> 1;
        float cc = g_cos[s * RH_ + i], sn = g_sin[s * RH_ + i];
        float x1 = sh[NOPE_ + (i << 1)], x2 = sh[NOPE_ + (i << 1) + 1];
        out = (p & 1) ? (x1 * sn + x2 * cc) : (x1 * cc - x2 * sn);
    }
    row[d] = f2tf_f(out);
}

__global__ __launch_bounds__(256) void transpose_kv() {
    __shared__ float t[32][33];
    int x = threadIdx.x & 31, y = threadIdx.x >> 5;
    #pragma unroll
    for (int i = 0; i < 4; i++) {
        int trow = blockIdx.x * 32 + y + i * 8;
        t[y + i * 8][x] = g_kv[(size_t)trow * D_ + blockIdx.y * 32 + x];
    }
    __syncthreads();
    #pragma unroll
    for (int i = 0; i < 4; i++) {
        int drow = blockIdx.y * 32 + y + i * 8;
        g_kvT[(size_t)drow * S_ + blockIdx.x * 32 + x] = t[x][y + i * 8];
    }
}

__global__ __launch_bounds__(256) void o_post() {
    int s = blockIdx.x, h = blockIdx.y;
    float* row = g_o + (size_t)s * (H_ * D_) + (size_t)h * D_;
    int d = threadIdx.x;
    __shared__ float sh[R_];
    float v = row[d];
    if (d >= NOPE_) sh[d - NOPE_] = v;
    __syncthreads();
    float out;
    if (d < NOPE_) out = v;
    else {
        int p = d - NOPE_, i = p >> 1;
        float cc = g_cos[s * RH_ + i], sn = g_sin[s * RH_ + i];
        float x1 = sh[i << 1], x2 = sh[(i << 1) + 1];
        out = (p & 1) ? (x2 * cc - x1 * sn) : (x1 * cc + x2 * sn);
    }
    row[d] = f2tf_f(out);
}

// ---------------- launch ----------------
extern "C" void kernel_launch(void* const* d_in, const int* in_sizes, int n_in,
                              void* d_out, int out_size) {
    const float* x        = (const float*)d_in[0];
    const float* freqs    = (const float*)d_in[1];
    const float* wq_a     = (const float*)d_in[2];
    const float* q_norm_w = (const float*)d_in[3];
    const float* wq_b     = (const float*)d_in[4];
    const float* wkv      = (const float*)d_in[5];
    const float* kv_norm_w= (const float*)d_in[6];
    const float* wo_a_w   = (const float*)d_in[7];
    const float* wo_b     = (const float*)d_in[8];
    const float* sink     = (const float*)d_in[9];
    float* out = (float*)d_out;

    float *p_x, *p_wqa, *p_wqb, *p_wkv, *p_woa, *p_wob;
    float *p_qa, *p_q, *p_kv, *p_o, *p_or, *p_part;
    cudaGetSymbolAddress((void**)&p_x,   g_x);
    cudaGetSymbolAddress((void**)&p_wqa, g_wqa);
    cudaGetSymbolAddress((void**)&p_wqb, g_wqb);
    cudaGetSymbolAddress((void**)&p_wkv, g_wkv);
    cudaGetSymbolAddress((void**)&p_woa, g_woa);
    cudaGetSymbolAddress((void**)&p_wob, g_wob);
    cudaGetSymbolAddress((void**)&p_qa,  g_qa);
    cudaGetSymbolAddress((void**)&p_q,   g_q);
    cudaGetSymbolAddress((void**)&p_kv,  g_kv);
    cudaGetSymbolAddress((void**)&p_o,   g_o);
    cudaGetSymbolAddress((void**)&p_or,  g_or);
    cudaGetSymbolAddress((void**)&p_part, g_part);

    cudaFuncSetAttribute(gemm_tn_tc, cudaFuncAttributeMaxDynamicSharedMemorySize, GEMM_SMEM);
    cudaFuncSetAttribute(flash_attn, cudaFuncAttributeMaxDynamicSharedMemorySize, FLASH_SMEM);

    // launches 1-5 (so launch #6 = qa GEMM gets captured by ncu -s 5 -c 1)
    cos_sin_k<<<(S_ * RH_ + 255) / 256, 256>>>(freqs);
    round_tf32_k<<<(S_ * HID_ / 4 + 255) / 256, 256>>>(x, p_x, S_ * HID_ / 4);
    round_tf32_k<<<(QL_ * HID_ / 4 + 255) / 256, 256>>>(wq_a, p_wqa, QL_ * HID_ / 4);
    round_tf32_k<<<(D_ * HID_ / 4 + 255) / 256, 256>>>(wkv, p_wkv, D_ * HID_ / 4);
    round_tf32_k<<<(H_ * D_ * QL_ / 4 + 255) / 256, 256>>>(wq_b, p_wqb, H_ * D_ * QL_ / 4);

    // launch #6: q_a = x @ wq_a^T — split-K x4 (ncu target)
    gemm_tn_tc<<<dim3(QL_ / BN, S_ / BM, 4), 256, GEMM_SMEM>>>(p_x, p_wqa, p_part,
        512, HID_, HID_, QL_, 512, 512, (long)S_ * QL_, 0);
    reduce_rms_qa<<<S_, 256>>>(p_part, q_norm_w);

    // q = qa @ wq_b^T
    gemm_tn_tc<<<dim3((H_ * D_) / BN, S_ / BM, 1), 256, GEMM_SMEM>>>(p_qa, p_wqb, p_q,
        QL_, QL_, QL_, H_ * D_, 0, 0, 0, 0);
    q_post<<<dim3(S_, H_), 256>>>();

    // kv = x @ wkv^T — split-K x8
    gemm_tn_tc<<<dim3(D_ / BN, S_ / BM, 8), 256, GEMM_SMEM>>>(p_x, p_wkv, p_part,
        256, HID_, HID_, D_, 256, 256, (long)S_ * D_, 0);
    reduce_kv_post<<<S_, 256>>>(p_part, kv_norm_w);
    transpose_kv<<<dim3(S_ / 32, D_ / 32), 256>>>();

    // fused attention
    flash_attn<<<512, 256, FLASH_SMEM>>>(sink);

    o_post<<<dim3(S_, H_), 256>>>();

    // round wo weights (first use is below)
    round_tf32_k<<<(G_ * OR_ * 1024 / 4 + 255) / 256, 256>>>(wo_a_w, p_woa, G_ * OR_ * 1024 / 4);
    round_tf32_k<<<(HID_ * G_ * OR_ / 4 + 255) / 256, 256>>>(wo_b, p_wob, HID_ * G_ * OR_ / 4);

    // grouped wo_a (tf32-rounded output in epilogue)
    gemm_tn_tc<<<dim3(OR_ / BN, S_ / BM, G_), 256, GEMM_SMEM>>>(p_o, p_woa, p_or,
        (H_ / G_) * D_, H_ * D_, (H_ / G_) * D_, G_ * OR_,
        (long)(H_ / G_) * D_, (long)OR_ * (H_ / G_) * D_, (long)OR_, 1);

    // out = o_r @ wo_b^T — split-K x2
    gemm_tn_tc<<<dim3(HID_ / BN, S_ / BM, 2), 256, GEMM_SMEM>>>(p_or, p_wob, p_part,
        1024, G_ * OR_, G_ * OR_, HID_, 1024, 1024, (long)S_ * HID_, 0);
    reduce_parts_k<<<(S_ * HID_ / 4 + 255) / 256, 256>>>(p_part, out,
        S_ * HID_ / 4, (long)S_ * HID_ / 4, 2);
}

// round 14
// speedup vs baseline: 2.3590x; 1.0271x over previous
#include <cuda_runtime.h>
#include <cstdint>

#define S_    2048
#define HID_  2048
#define H_    16
#define D_    256
#define R_    64
#define RH_   32          // R/2
#define NOPE_ 192
#define QL_   1024
#define OR_   512
#define G_    4
#define EPS_  1e-6f
#define SCALE_ 0.0625f    // 256^-0.5

#define BM 128
#define BN 64
#define BK 32
#define STAGE_BYTES 24576            // A 16KB + B 8KB per stage
#define GEMM_SMEM (3 * STAGE_BYTES)  // 72 KB -> 3 CTAs/SM

// flash smem (floats): Q 16384 | KV 16384 | KVT 16384 | P 4096 | RED 512
#define F_Q   0
#define F_KV  16384
#define F_KVT 32768
#define F_P   49152
#define F_RED 53248
#define FLASH_SMEM ((53248 + 512) * 4)

// ---------------- scratch ----------------
__device__ float g_cos[S_ * RH_];
__device__ float g_sin[S_ * RH_];
__device__ float g_x[(size_t)S_ * HID_];
__device__ float g_wqa[(size_t)QL_ * HID_];
__device__ float g_wqb[(size_t)H_ * D_ * QL_];
__device__ float g_wkv[(size_t)D_ * HID_];
__device__ float g_woa[(size_t)G_ * OR_ * 1024];
__device__ float g_wob[(size_t)HID_ * G_ * OR_];
__device__ float g_qa[(size_t)S_ * QL_];
__device__ float g_q[(size_t)S_ * H_ * D_];
__device__ float g_kv[(size_t)S_ * D_];
__device__ float g_kvT[(size_t)D_ * S_];
__device__ float g_o[(size_t)S_ * H_ * D_];
__device__ float g_or[(size_t)S_ * G_ * OR_];
__device__ float g_part[(size_t)8 * 1024 * 1024];    // 32 MB qa split-K partials
__device__ float g_part2[(size_t)4 * 1024 * 1024];   // 16 MB kv split-K partials

// ---------------- helpers ----------------
__device__ __forceinline__ uint32_t f2tf(float x) {
    uint32_t r;
    asm("cvt.rna.tf32.f32 %0, %1;" : "=r"(r) : "f"(x));
    return r;
}
__device__ __forceinline__ float f2tf_f(float x) { return __uint_as_float(f2tf(x)); }

__device__ __forceinline__ void mma_tf32(float4& c, const uint32_t a[4], const uint32_t b[2]) {
    asm volatile(
        "mma.sync.aligned.m16n8k8.row.col.f32.tf32.tf32.f32 "
        "{%0,%1,%2,%3}, {%4,%5,%6,%7}, {%8,%9}, {%0,%1,%2,%3};\n"
        : "+f"(c.x), "+f"(c.y), "+f"(c.z), "+f"(c.w)
        : "r"(a[0]), "r"(a[1]), "r"(a[2]), "r"(a[3]), "r"(b[0]), "r"(b[1]));
}
__device__ __forceinline__ void ldsm4(uint32_t* d, uint32_t addr) {
    asm volatile("ldmatrix.sync.aligned.m8n8.x4.shared.b16 {%0,%1,%2,%3}, [%4];"
        : "=r"(d[0]), "=r"(d[1]), "=r"(d[2]), "=r"(d[3]) : "r"(addr));
}
#define CP16(dst, src) \
    asm volatile("cp.async.cg.shared.global [%0], [%1], 16;\n" :: "r"(dst), "l"(src))
#define CP_COMMIT() asm volatile("cp.async.commit_group;\n")
#define CP_WAIT1()  asm volatile("cp.async.wait_group 1;\n")

__device__ __forceinline__ float block_reduce(float v, bool is_max) {
    __shared__ float warp_res[8];
    __shared__ float result;
    __syncthreads();
    #pragma unroll
    for (int o = 16; o; o >>= 1) {
        float other = __shfl_xor_sync(0xffffffffu, v, o);
        v = is_max ? fmaxf(v, other) : (v + other);
    }
    if ((threadIdx.x & 31) == 0) warp_res[threadIdx.x >> 5] = v;
    __syncthreads();
    if (threadIdx.x == 0) {
        int nw = (blockDim.x + 31) >> 5;
        float r = warp_res[0];
        for (int i = 1; i < nw; i++) r = is_max ? fmaxf(r, warp_res[i]) : (r + warp_res[i]);
        result = r;
    }
    __syncthreads();
    return result;
}

__global__ __launch_bounds__(256) void round_tf32_k(const float* __restrict__ src,
                                                    float* __restrict__ dst, int n4) {
    int i = blockIdx.x * 256 + threadIdx.x;
    if (i < n4) {
        float4 v = ((const float4*)src)[i];
        v.x = f2tf_f(v.x); v.y = f2tf_f(v.y); v.z = f2tf_f(v.z); v.w = f2tf_f(v.w);
        ((float4*)dst)[i] = v;
    }
}

// deterministic fixed-order split-K reduction (final output only)
__global__ __launch_bounds__(256) void reduce_parts_k(const float* __restrict__ src,
                                                      float* __restrict__ dst,
                                                      int n4, long stride4, int parts) {
    int i = blockIdx.x * 256 + threadIdx.x;
    if (i >= n4) return;
    float4 a = ((const float4*)src)[i];
    for (int p = 1; p < parts; p++) {
        float4 b = ((const float4*)src)[i + (size_t)p * stride4];
        a.x += b.x; a.y += b.y; a.z += b.z; a.w += b.w;
    }
    ((float4*)dst)[i] = a;
}

// fused: qa = rms(sum of 4 split-K partials) * w, tf32-rounded
__global__ __launch_bounds__(256) void reduce_rms_qa(const float* __restrict__ part,
                                                     const float* __restrict__ w) {
    int s = blockIdx.x;
    const float* p0 = part + (long)s * QL_;
    float v[4];
    float ss = 0.f;
    #pragma unroll
    for (int i = 0; i < 4; i++) {
        int idx = threadIdx.x + i * 256;
        float a = p0[idx] + p0[idx + (long)S_ * QL_] +
                  p0[idx + 2L * S_ * QL_] + p0[idx + 3L * S_ * QL_];
        v[i] = a;
        ss += a * a;
    }
    ss = block_reduce(ss, false);
    float sc = rsqrtf(ss / QL_ + EPS_);
    #pragma unroll
    for (int i = 0; i < 4; i++) {
        int idx = threadIdx.x + i * 256;
        g_qa[(long)s * QL_ + idx] = f2tf_f(v[i] * sc * w[idx]);
    }
}

// fused: kv = rope(rms(sum of 8 split-K partials) * w), tf32-rounded
__global__ __launch_bounds__(256) void reduce_kv_post(const float* __restrict__ part,
                                                      const float* __restrict__ w) {
    int s = blockIdx.x;
    int d = threadIdx.x;
    const float* p0 = part + (long)s * D_ + d;
    float v = 0.f;
    #pragma unroll
    for (int p = 0; p < 8; p++) v += p0[(long)p * S_ * D_];
    float ss = block_reduce(v * v, false);
    float sc = rsqrtf(ss / D_ + EPS_);
    __shared__ float sh[D_];
    sh[d] = v * sc * w[d];
    __syncthreads();
    float out;
    if (d < NOPE_) out = sh[d];
    else {
        int p = d - NOPE_, i = p >> 1;
        float cc = g_cos[s * RH_ + i], sn = g_sin[s * RH_ + i];
        float x1 = sh[NOPE_ + (i << 1)], x2 = sh[NOPE_ + (i << 1) + 1];
        out = (p & 1) ? (x1 * sn + x2 * cc) : (x1 * cc - x2 * sn);
    }
    g_kv[(long)s * D_ + d] = f2tf_f(out);
}

// ============================================================================
// TF32 GEMM TN body: C[M,N] = A[M,K] @ B[N,K]^T. Inputs pre-rounded tf32.
// 128x64x32 CTA tile, 256 threads (8 warps 4x2, 32x32 warp tile),
// 3-stage cp.async pipeline (72 KB -> 3 CTAs/SM), ldmatrix.x4, XOR swizzle.
// ============================================================================
__device__ __forceinline__ void gemm_body(
    const float* __restrict__ A, const float* __restrict__ B, float* __restrict__ C,
    int K, int lda, int ldb, int ldc, int rnd)
{
    int row0 = blockIdx.y * BM, col0 = blockIdx.x * BN;
    int niter = K / BK;

    extern __shared__ uint32_t smem[];
    uint32_t smem_b = (uint32_t)__cvta_generic_to_shared(smem);

    int tid = threadIdx.x, lane = tid & 31, warp = tid >> 5;
    int wm = warp >> 1, wn = warp & 1;   // 4 x 2 warps

    int ldr = tid >> 3;
    int ldk = tid & 7;
    uint32_t dstA[4], dstB[2];
    const float* srcA[4];
    const float* srcB[2];
    #pragma unroll
    for (int i = 0; i < 4; i++) {
        int r = ldr + i * 32;
        dstA[i] = smem_b + ((((r << 3) + (ldk ^ (r & 7)))) << 4);
        srcA[i] = A + (long)(row0 + r) * lda + (ldk << 2);
    }
    #pragma unroll
    for (int i = 0; i < 2; i++) {
        int r = ldr + i * 32;
        dstB[i] = smem_b + 16384 + ((((r << 3) + (ldk ^ (r & 7)))) << 4);
        srcB[i] = B + (long)(col0 + r) * ldb + (ldk << 2);
    }

    int jr = ((lane >> 3) & 1) << 3;
    int jk = lane >> 4;
    int rr = lane & 7;
    uint32_t a_ad[2], b_ad[2];
    #pragma unroll
    for (int mt = 0; mt < 2; mt++) {
        int ar = wm * 32 + mt * 16 + jr + rr;
        a_ad[mt] = smem_b + (((ar << 3) + (jk ^ (ar & 7))) << 4);
    }
    #pragma unroll
    for (int ntp = 0; ntp < 2; ntp++) {
        int br = wn * 32 + ntp * 16 + jr + rr;
        b_ad[ntp] = smem_b + 16384 + (((br << 3) + (jk ^ (br & 7))) << 4);
    }

    float4 c[2][4];
    #pragma unroll
    for (int i = 0; i < 2; i++)
        #pragma unroll
        for (int j = 0; j < 4; j++) c[i][j] = make_float4(0.f, 0.f, 0.f, 0.f);

    #pragma unroll
    for (int i = 0; i < 4; i++) CP16(dstA[i], srcA[i]);
    #pragma unroll
    for (int i = 0; i < 2; i++) CP16(dstB[i], srcB[i]);
    CP_COMMIT();
    if (niter > 1) {
        #pragma unroll
        for (int i = 0; i < 4; i++) CP16(dstA[i] + STAGE_BYTES, srcA[i] + BK);
        #pragma unroll
        for (int i = 0; i < 2; i++) CP16(dstB[i] + STAGE_BYTES, srcB[i] + BK);
    }
    CP_COMMIT();
    #pragma unroll
    for (int i = 0; i < 4; i++) srcA[i] += 2 * BK;
    #pragma unroll
    for (int i = 0; i < 2; i++) srcB[i] += 2 * BK;

    int stage = 0;
    for (int k = 0; k < niter; k++) {
        CP_WAIT1();
        __syncthreads();

        if (k + 2 < niter) {
            int s2 = stage + 2; if (s2 >= 3) s2 -= 3;
            uint32_t so2 = (uint32_t)s2 * STAGE_BYTES;
            #pragma unroll
            for (int i = 0; i < 4; i++) CP16(dstA[i] + so2, srcA[i]);
            #pragma unroll
            for (int i = 0; i < 2; i++) CP16(dstB[i] + so2, srcB[i]);
        }
        CP_COMMIT();
        #pragma unroll
        for (int i = 0; i < 4; i++) srcA[i] += BK;
        #pragma unroll
        for (int i = 0; i < 2; i++) srcB[i] += BK;

        uint32_t so = (uint32_t)stage * STAGE_BYTES;
        uint32_t aa[2], bb[2];
        #pragma unroll
        for (int mt = 0; mt < 2; mt++) aa[mt] = a_ad[mt] + so;
        #pragma unroll
        for (int ntp = 0; ntp < 2; ntp++) bb[ntp] = b_ad[ntp] + so;

        #pragma unroll
        for (int ks = 0; ks < 4; ks++) {
            uint32_t af[2][4];
            #pragma unroll
            for (int mt = 0; mt < 2; mt++) ldsm4(af[mt], aa[mt] ^ (ks << 5));
            uint32_t bf[4][2];
            #pragma unroll
            for (int ntp = 0; ntp < 2; ntp++) {
                uint32_t t[4];
                ldsm4(t, bb[ntp] ^ (ks << 5));
                bf[ntp * 2][0]     = t[0];
                bf[ntp * 2 + 1][0] = t[1];
                bf[ntp * 2][1]     = t[2];
                bf[ntp * 2 + 1][1] = t[3];
            }
            #pragma unroll
            for (int mt = 0; mt < 2; mt++)
                #pragma unroll
                for (int nt = 0; nt < 4; nt++)
                    mma_tf32(c[mt][nt], af[mt], bf[nt]);
        }
        stage++; if (stage >= 3) stage -= 3;
    }

    #pragma unroll
    for (int mt = 0; mt < 2; mt++) {
        int m = row0 + wm * 32 + mt * 16 + (lane >> 2);
        #pragma unroll
        for (int nt = 0; nt < 4; nt++) {
            int n = col0 + wn * 32 + nt * 8 + ((lane & 3) << 1);
            float4 v = c[mt][nt];
            if (rnd) { v.x = f2tf_f(v.x); v.y = f2tf_f(v.y); v.z = f2tf_f(v.z); v.w = f2tf_f(v.w); }
            *(float2*)(C + (long)m * ldc + n)       = make_float2(v.x, v.y);
            *(float2*)(C + (long)(m + 8) * ldc + n) = make_float2(v.z, v.w);
        }
    }
}

__global__ __launch_bounds__(256, 3) void gemm_tn_tc(
    const float* __restrict__ A, const float* __restrict__ B, float* __restrict__ C,
    int K, int lda, int ldb, int ldc,
    long sA, long sB, long sC, int rnd)
{
    gemm_body(A + (long)blockIdx.z * sA, B + (long)blockIdx.z * sB,
              C + (long)blockIdx.z * sC, K, lda, ldb, ldc, rnd);
}

// combined qa + kv launch: z < zsplit -> set 1; else set 2 (x must be < xmax2)
__global__ __launch_bounds__(256, 3) void gemm_dual(
    const float* __restrict__ A,
    const float* __restrict__ B1, float* __restrict__ C1, int K1, int ldb1, int ldc1,
    long sA1, long sB1, long sC1,
    const float* __restrict__ B2, float* __restrict__ C2, int K2, int ldb2, int ldc2,
    long sA2, long sB2, long sC2,
    int lda, int zsplit, int xmax2)
{
    int z = blockIdx.z;
    if (z < zsplit) {
        gemm_body(A + (long)z * sA1, B1 + (long)z * sB1, C1 + (long)z * sC1,
                  K1, lda, ldb1, ldc1, 0);
    } else {
        if ((int)blockIdx.x >= xmax2) return;
        z -= zsplit;
        gemm_body(A + (long)z * sA2, B2 + (long)z * sB2, C2 + (long)z * sC2,
                  K2, lda, ldb2, ldc2, 0);
    }
}

// ============================================================================
// Fused flash attention + o_post: per CTA = (head h, 64-row q tile qi).
// Inverse RoPE on cols 192..255 (owned by wn==3 warps) + tf32 round in epilogue.
// ============================================================================
__global__ __launch_bounds__(256, 1) void flash_attn(const float* __restrict__ sink) {
    int bx = blockIdx.x;
    int h  = bx & 15;
    int qi = 31 - (bx >> 4);          // heavy tiles first
    int q0 = qi * 64;
    int jn = qi + 1;

    extern __shared__ float smf[];
    uint32_t smb = (uint32_t)__cvta_generic_to_shared(smf);
    uint32_t smQ = smb, smKV = smb + F_KV * 4, smKVT = smb + F_KVT * 4, smP = smb + F_P * 4;

    int tid = threadIdx.x, lane = tid & 31, warp = tid >> 5;
    int wm = warp >> 2, wn = warp & 3;
    int jr = ((lane >> 3) & 1) << 3;
    int jk = lane >> 4;
    int rr = lane & 7;
    int g  = lane >> 2;
    int e2 = (lane & 3) << 1;

    const float4* q4   = (const float4*)g_q + (size_t)q0 * 1024 + (size_t)h * 64;
    const float4* kv4  = (const float4*)g_kv;
    const float4* kvT4 = (const float4*)g_kvT;

    #pragma unroll
    for (int i = 0; i < 16; i++) {
        int id = tid + i * 256, row = id >> 6, k4 = id & 63;
        uint32_t dst = smQ + (uint32_t)((row << 6) + (k4 & 56) + ((k4 ^ row) & 7)) * 16;
        CP16(dst, q4 + (size_t)row * 1024 + k4);
    }
    #pragma unroll
    for (int i = 0; i < 16; i++) {
        int id = tid + i * 256, row = id >> 6, k4 = id & 63;
        uint32_t dst = smKV + (uint32_t)((row << 6) + (k4 & 56) + ((k4 ^ row) & 7)) * 16;
        CP16(dst, kv4 + (size_t)row * 64 + k4);
    }
    CP_COMMIT();
    #pragma unroll
    for (int i = 0; i < 16; i++) {
        int id = tid + i * 256, rd = id >> 4, k4 = id & 15;
        uint32_t dst = smKVT + (uint32_t)((rd << 4) + (k4 & 8) + ((k4 ^ rd) & 7)) * 16;
        CP16(dst, kvT4 + (size_t)rd * 512 + k4);
    }
    CP_COMMIT();

    uint32_t aSb[2], bSb, aPb[2], bPVb[4];
    #pragma unroll
    for (int mt = 0; mt < 2; mt++) {
        int ar = wm * 32 + mt * 16 + jr + rr;
        aSb[mt] = smQ + (uint32_t)((ar << 6) + (jk ^ (ar & 7))) * 16;
        aPb[mt] = smP + (uint32_t)((ar << 4) + (jk ^ (ar & 7))) * 16;
    }
    {
        int br = wn * 16 + jr + rr;
        bSb = smKV + (uint32_t)((br << 6) + (jk ^ (br & 7))) * 16;
    }
    #pragma unroll
    for (int ntp = 0; ntp < 4; ntp++) {
        int br = wn * 64 + ntp * 16 + jr + rr;
        bPVb[ntp] = smKVT + (uint32_t)((br << 4) + (jk ^ (br & 7))) * 16;
    }

    float4 cO[2][8];
    #pragma unroll
    for (int mt = 0; mt < 2; mt++)
        #pragma unroll
        for (int nt = 0; nt < 8; nt++) cO[mt][nt] = make_float4(0.f, 0.f, 0.f, 0.f);
    float mrow[4] = {-3.0e38f, -3.0e38f, -3.0e38f, -3.0e38f};
    float lrow[4] = {0.f, 0.f, 0.f, 0.f};

    for (int j = 0; j < jn; j++) {
        CP_WAIT1();
        __syncthreads();

        float4 sS[2][2];
        #pragma unroll
        for (int mt = 0; mt < 2; mt++)
            #pragma unroll
            for (int nt = 0; nt < 2; nt++) sS[mt][nt] = make_float4(0.f, 0.f, 0.f, 0.f);

        #pragma unroll
        for (int cc = 0; cc < 8; cc++) {
            uint32_t ao = (uint32_t)cc * 128;
            #pragma unroll
            for (int ks = 0; ks < 4; ks++) {
                uint32_t af[2][4];
                #pragma unroll
                for (int mt = 0; mt < 2; mt++) ldsm4(af[mt], (aSb[mt] + ao) ^ (ks << 5));
                uint32_t tb[4];
                ldsm4(tb, (bSb + ao) ^ (ks << 5));
                uint32_t b0[2] = {tb[0], tb[2]}, b1[2] = {tb[1], tb[3]};
                #pragma unroll
                for (int mt = 0; mt < 2; mt++) {
                    mma_tf32(sS[mt][0], af[mt], b0);
                    mma_tf32(sS[mt][1], af[mt], b1);
                }
            }
        }

        #pragma unroll
        for (int mt = 0; mt < 2; mt++)
            #pragma unroll
            for (int nt = 0; nt < 2; nt++) {
                sS[mt][nt].x *= SCALE_; sS[mt][nt].y *= SCALE_;
                sS[mt][nt].z *= SCALE_; sS[mt][nt].w *= SCALE_;
            }
        if (j == qi) {
            #pragma unroll
            for (int mt = 0; mt < 2; mt++) {
                int r0 = wm * 32 + mt * 16 + g;
                #pragma unroll
                for (int nt = 0; nt < 2; nt++) {
                    int c0 = wn * 16 + nt * 8 + e2;
                    if (c0 > r0)     sS[mt][nt].x = -3.0e38f;
                    if (c0 + 1 > r0) sS[mt][nt].y = -3.0e38f;
                    if (c0 > r0 + 8)     sS[mt][nt].z = -3.0e38f;
                    if (c0 + 1 > r0 + 8) sS[mt][nt].w = -3.0e38f;
                }
            }
        }

        float rm[4];
        #pragma unroll
        for (int mt = 0; mt < 2; mt++) {
            rm[mt * 2 + 0] = fmaxf(fmaxf(sS[mt][0].x, sS[mt][0].y), fmaxf(sS[mt][1].x, sS[mt][1].y));
            rm[mt * 2 + 1] = fmaxf(fmaxf(sS[mt][0].z, sS[mt][0].w), fmaxf(sS[mt][1].z, sS[mt][1].w));
        }
        #pragma unroll
        for (int i = 0; i < 4; i++) {
            rm[i] = fmaxf(rm[i], __shfl_xor_sync(0xffffffffu, rm[i], 1));
            rm[i] = fmaxf(rm[i], __shfl_xor_sync(0xffffffffu, rm[i], 2));
        }
        #pragma unroll
        for (int i = 0; i < 4; i++) {
            int row = wm * 32 + (i >> 1) * 16 + g + (i & 1) * 8;
            smf[F_RED + wn * 64 + row] = rm[i];
        }
        __syncthreads();   // (A)

        if (j + 1 < jn) {
            const float4* kvs = kv4 + (size_t)(j + 1) * 64 * 64;
            #pragma unroll
            for (int i = 0; i < 16; i++) {
                int id = tid + i * 256, row = id >> 6, k4 = id & 63;
                uint32_t dst = smKV + (uint32_t)((row << 6) + (k4 & 56) + ((k4 ^ row) & 7)) * 16;
                CP16(dst, kvs + (size_t)row * 64 + k4);
            }
        }
        CP_COMMIT();

        float mnew[4], alpha[4];
        #pragma unroll
        for (int i = 0; i < 4; i++) {
            int row = wm * 32 + (i >> 1) * 16 + g + (i & 1) * 8;
            float tm = fmaxf(fmaxf(smf[F_RED + row], smf[F_RED + 64 + row]),
                             fmaxf(smf[F_RED + 128 + row], smf[F_RED + 192 + row]));
            mnew[i] = fmaxf(mrow[i], tm);
            alpha[i] = __expf(mrow[i] - mnew[i]);
            mrow[i] = mnew[i];
        }

        float ls[4];
        #pragma unroll
        for (int mt = 0; mt < 2; mt++) {
            #pragma unroll
            for (int nt = 0; nt < 2; nt++) {
                sS[mt][nt].x = __expf(sS[mt][nt].x - mnew[mt * 2 + 0]);
                sS[mt][nt].y = __expf(sS[mt][nt].y - mnew[mt * 2 + 0]);
                sS[mt][nt].z = __expf(sS[mt][nt].z - mnew[mt * 2 + 1]);
                sS[mt][nt].w = __expf(sS[mt][nt].w - mnew[mt * 2 + 1]);
            }
            ls[mt * 2 + 0] = sS[mt][0].x + sS[mt][0].y + sS[mt][1].x + sS[mt][1].y;
            ls[mt * 2 + 1] = sS[mt][0].z + sS[mt][0].w + sS[mt][1].z + sS[mt][1].w;
        }
        #pragma unroll
        for (int i = 0; i < 4; i++) {
            ls[i] += __shfl_xor_sync(0xffffffffu, ls[i], 1);
            ls[i] += __shfl_xor_sync(0xffffffffu, ls[i], 2);
        }
        #pragma unroll
        for (int i = 0; i < 4; i++) {
            int row = wm * 32 + (i >> 1) * 16 + g + (i & 1) * 8;
            smf[F_RED + 256 + wn * 64 + row] = ls[i];
        }
        __syncthreads();   // (B)
        #pragma unroll
        for (int i = 0; i < 4; i++) {
            int row = wm * 32 + (i >> 1) * 16 + g + (i & 1) * 8;
            float tl = smf[F_RED + 256 + row] + smf[F_RED + 256 + 64 + row] +
                       smf[F_RED + 256 + 128 + row] + smf[F_RED + 256 + 192 + row];
            lrow[i] = lrow[i] * alpha[i] + tl;
        }

        #pragma unroll
        for (int mt = 0; mt < 2; mt++)
            #pragma unroll
            for (int nt = 0; nt < 8; nt++) {
                cO[mt][nt].x *= alpha[mt * 2 + 0];
                cO[mt][nt].y *= alpha[mt * 2 + 0];
                cO[mt][nt].z *= alpha[mt * 2 + 1];
                cO[mt][nt].w *= alpha[mt * 2 + 1];
            }

        #pragma unroll
        for (int mt = 0; mt < 2; mt++)
            #pragma unroll
            for (int nt = 0; nt < 2; nt++) {
                int c = wn * 16 + nt * 8 + e2;
                int k4 = c >> 2;
                {
                    int row = wm * 32 + mt * 16 + g;
                    int fi = F_P + (((row << 4) + (k4 & 8) + ((k4 ^ row) & 7)) << 2) + (c & 2);
                    *(float2*)(smf + fi) = make_float2(f2tf_f(sS[mt][nt].x), f2tf_f(sS[mt][nt].y));
                }
                {
                    int row = wm * 32 + mt * 16 + g + 8;
                    int fi = F_P + (((row << 4) + (k4 & 8) + ((k4 ^ row) & 7)) << 2) + (c & 2);
                    *(float2*)(smf + fi) = make_float2(f2tf_f(sS[mt][nt].z), f2tf_f(sS[mt][nt].w));
                }
            }

        CP_WAIT1();
        __syncthreads();   // (C)

        #pragma unroll
        for (int kk = 0; kk < 8; kk++) {
            uint32_t xo = (uint32_t)((kk & 3) << 5);
            uint32_t ad = (uint32_t)((kk >> 2) << 7);
            uint32_t af[2][4];
            #pragma unroll
            for (int mt = 0; mt < 2; mt++) ldsm4(af[mt], (aPb[mt] + ad) ^ xo);
            #pragma unroll
            for (int ntp = 0; ntp < 4; ntp++) {
                uint32_t tb[4];
                ldsm4(tb, (bPVb[ntp] + ad) ^ xo);
                uint32_t b0[2] = {tb[0], tb[2]}, b1[2] = {tb[1], tb[3]};
                #pragma unroll
                for (int mt = 0; mt < 2; mt++) {
                    mma_tf32(cO[mt][ntp * 2 + 0], af[mt], b0);
                    mma_tf32(cO[mt][ntp * 2 + 1], af[mt], b1);
                }
            }
        }
        __syncthreads();   // (D)

        if (j + 1 < jn) {
            const float4* kvts = kvT4 + (size_t)(j + 1) * 16;
            #pragma unroll
            for (int i = 0; i < 16; i++) {
                int id = tid + i * 256, rd = id >> 4, k4 = id & 15;
                uint32_t dst = smKVT + (uint32_t)((rd << 4) + (k4 & 8) + ((k4 ^ rd) & 7)) * 16;
                CP16(dst, kvts + (size_t)rd * 512 + k4);
            }
        }
        CP_COMMIT();
    }

    // ---- finalize: sink + normalize + fused inverse RoPE (wn==3) + tf32 round ----
    float snk = sink[h];
    float fac[4];
    #pragma unroll
    for (int i = 0; i < 4; i++) {
        float mf = fmaxf(mrow[i], snk);
        float af = __expf(mrow[i] - mf);
        float lf = lrow[i] * af + __expf(snk - mf);
        fac[i] = af / lf;
    }
    #pragma unroll
    for (int mt = 0; mt < 2; mt++) {
        int r = q0 + wm * 32 + mt * 16 + g;
        #pragma unroll
        for (int nt = 0; nt < 8; nt++) {
            int c = wn * 64 + nt * 8 + e2;
            float v0 = cO[mt][nt].x * fac[mt * 2 + 0];
            float v1 = cO[mt][nt].y * fac[mt * 2 + 0];
            float v2 = cO[mt][nt].z * fac[mt * 2 + 1];
            float v3 = cO[mt][nt].w * fac[mt * 2 + 1];
            if (wn == 3) {
                int i = (c & 63) >> 1;
                float c1 = g_cos[r * RH_ + i],       s1 = g_sin[r * RH_ + i];
                float c2 = g_cos[(r + 8) * RH_ + i], s2 = g_sin[(r + 8) * RH_ + i];
                float t0 = v0 * c1 + v1 * s1, t1 = v1 * c1 - v0 * s1;
                float t2 = v2 * c2 + v3 * s2, t3 = v3 * c2 - v2 * s2;
                v0 = t0; v1 = t1; v2 = t2; v3 = t3;
            }
            float* p0 = g_o + (size_t)r * (H_ * D_) + (size_t)h * D_ + c;
            *(float2*)p0 = make_float2(f2tf_f(v0), f2tf_f(v1));
            *(float2*)(p0 + (size_t)8 * (H_ * D_)) = make_float2(f2tf_f(v2), f2tf_f(v3));
        }
    }
}

// ---------------- elementwise / norm kernels ----------------
__global__ void cos_sin_k(const float* __restrict__ freqs) {
    int i = blockIdx.x * blockDim.x + threadIdx.x;
    if (i < S_ * RH_) {
        float f = freqs[i];
        g_cos[i] = cosf(f);
        g_sin[i] = sinf(f);
    }
}

__global__ __launch_bounds__(256) void q_post() {
    int s = blockIdx.x, h = blockIdx.y;
    float* row = g_q + (size_t)s * (H_ * D_) + (size_t)h * D_;
    int d = threadIdx.x;
    float v = row[d];
    float ss = block_reduce(v * v, false);
    float sc = rsqrtf(ss / D_ + EPS_);
    __shared__ float sh[D_];
    sh[d] = v * sc;
    __syncthreads();
    float out;
    if (d < NOPE_) out = sh[d];
    else {
        int p = d - NOPE_, i = p >> 1;
        float cc = g_cos[s * RH_ + i], sn = g_sin[s * RH_ + i];
        float x1 = sh[NOPE_ + (i << 1)], x2 = sh[NOPE_ + (i << 1) + 1];
        out = (p & 1) ? (x1 * sn + x2 * cc) : (x1 * cc - x2 * sn);
    }
    row[d] = f2tf_f(out);
}

__global__ __launch_bounds__(256) void transpose_kv() {
    __shared__ float t[32][33];
    int x = threadIdx.x & 31, y = threadIdx.x >> 5;
    #pragma unroll
    for (int i = 0; i < 4; i++) {
        int trow = blockIdx.x * 32 + y + i * 8;
        t[y + i * 8][x] = g_kv[(size_t)trow * D_ + blockIdx.y * 32 + x];
    }
    __syncthreads();
    #pragma unroll
    for (int i = 0; i < 4; i++) {
        int drow = blockIdx.y * 32 + y + i * 8;
        g_kvT[(size_t)drow * S_ + blockIdx.x * 32 + x] = t[x][y + i * 8];
    }
}

// ---------------- launch ----------------
extern "C" void kernel_launch(void* const* d_in, const int* in_sizes, int n_in,
                              void* d_out, int out_size) {
    const float* x        = (const float*)d_in[0];
    const float* freqs    = (const float*)d_in[1];
    const float* wq_a     = (const float*)d_in[2];
    const float* q_norm_w = (const float*)d_in[3];
    const float* wq_b     = (const float*)d_in[4];
    const float* wkv      = (const float*)d_in[5];
    const float* kv_norm_w= (const float*)d_in[6];
    const float* wo_a_w   = (const float*)d_in[7];
    const float* wo_b     = (const float*)d_in[8];
    const float* sink     = (const float*)d_in[9];
    float* out = (float*)d_out;

    float *p_x, *p_wqa, *p_wqb, *p_wkv, *p_woa, *p_wob;
    float *p_qa, *p_q, *p_kv, *p_o, *p_or, *p_part, *p_part2;
    cudaGetSymbolAddress((void**)&p_x,   g_x);
    cudaGetSymbolAddress((void**)&p_wqa, g_wqa);
    cudaGetSymbolAddress((void**)&p_wqb, g_wqb);
    cudaGetSymbolAddress((void**)&p_wkv, g_wkv);
    cudaGetSymbolAddress((void**)&p_woa, g_woa);
    cudaGetSymbolAddress((void**)&p_wob, g_wob);
    cudaGetSymbolAddress((void**)&p_qa,  g_qa);
    cudaGetSymbolAddress((void**)&p_q,   g_q);
    cudaGetSymbolAddress((void**)&p_kv,  g_kv);
    cudaGetSymbolAddress((void**)&p_o,   g_o);
    cudaGetSymbolAddress((void**)&p_or,  g_or);
    cudaGetSymbolAddress((void**)&p_part, g_part);
    cudaGetSymbolAddress((void**)&p_part2, g_part2);

    cudaFuncSetAttribute(gemm_tn_tc, cudaFuncAttributeMaxDynamicSharedMemorySize, GEMM_SMEM);
    cudaFuncSetAttribute(gemm_dual,  cudaFuncAttributeMaxDynamicSharedMemorySize, GEMM_SMEM);
    cudaFuncSetAttribute(flash_attn, cudaFuncAttributeMaxDynamicSharedMemorySize, FLASH_SMEM);

    cos_sin_k<<<(S_ * RH_ + 255) / 256, 256>>>(freqs);
    round_tf32_k<<<(S_ * HID_ / 4 + 255) / 256, 256>>>(x, p_x, S_ * HID_ / 4);
    round_tf32_k<<<(QL_ * HID_ / 4 + 255) / 256, 256>>>(wq_a, p_wqa, QL_ * HID_ / 4);
    round_tf32_k<<<(D_ * HID_ / 4 + 255) / 256, 256>>>(wkv, p_wkv, D_ * HID_ / 4);
    round_tf32_k<<<(H_ * D_ * QL_ / 4 + 255) / 256, 256>>>(wq_b, p_wqb, H_ * D_ * QL_ / 4);

    // combined: qa = x@wqa^T (split-K x4, z 0..3) + kv = x@wkv^T (split-K x8, z 4..11)
    gemm_dual<<<dim3(QL_ / BN, S_ / BM, 12), 256, GEMM_SMEM>>>(
        p_x,
        p_wqa, p_part, 512, HID_, QL_, 512, 512, (long)S_ * QL_,
        p_wkv, p_part2, 256, HID_, D_, 256, 256, (long)S_ * D_,
        HID_, 4, D_ / BN);
    reduce_rms_qa<<<S_, 256>>>(p_part, q_norm_w);
    reduce_kv_post<<<S_, 256>>>(p_part2, kv_norm_w);
    transpose_kv<<<dim3(S_ / 32, D_ / 32), 256>>>();

    // q = qa @ wq_b^T
    gemm_tn_tc<<<dim3((H_ * D_) / BN, S_ / BM, 1), 256, GEMM_SMEM>>>(p_qa, p_wqb, p_q,
        QL_, QL_, QL_, H_ * D_, 0, 0, 0, 0);
    q_post<<<dim3(S_, H_), 256>>>();

    // fused attention (incl. o_post)
    flash_attn<<<512, 256, FLASH_SMEM>>>(sink);

    round_tf32_k<<<(G_ * OR_ * 1024 / 4 + 255) / 256, 256>>>(wo_a_w, p_woa, G_ * OR_ * 1024 / 4);
    round_tf32_k<<<(HID_ * G_ * OR_ / 4 + 255) / 256, 256>>>(wo_b, p_wob, HID_ * G_ * OR_ / 4);

    // grouped wo_a (tf32-rounded output in epilogue)
    gemm_tn_tc<<<dim3(OR_ / BN, S_ / BM, G_), 256, GEMM_SMEM>>>(p_o, p_woa, p_or,
        (H_ / G_) * D_, H_ * D_, (H_ / G_) * D_, G_ * OR_,
        (long)(H_ / G_) * D_, (long)OR_ * (H_ / G_) * D_, (long)OR_, 1);

    // out = o_r @ wo_b^T — split-K x2
    gemm_tn_tc<<<dim3(HID_ / BN, S_ / BM, 2), 256, GEMM_SMEM>>>(p_or, p_wob, p_part,
        1024, G_ * OR_, G_ * OR_, HID_, 1024, 1024, (long)S_ * HID_, 0);
    reduce_parts_k<<<(S_ * HID_ / 4 + 255) / 256, 256>>>(p_part, out,
        S_ * HID_ / 4, (long)S_ * HID_ / 4, 2);
}

// round 15
// speedup vs baseline: 2.4053x; 1.0196x over previous
#include <cuda_runtime.h>
#include <cstdint>

#define S_    2048
#define HID_  2048
#define H_    16
#define D_    256
#define R_    64
#define RH_   32          // R/2
#define NOPE_ 192
#define QL_   1024
#define OR_   512
#define G_    4
#define EPS_  1e-6f
#define SCALE_ 0.0625f    // 256^-0.5

#define BM 128
#define BN 64
#define BK 32
#define STAGE_BYTES 24576            // A 16KB + B 8KB per stage
#define GEMM_SMEM (3 * STAGE_BYTES)  // 72 KB -> 3 CTAs/SM

// flash smem (floats): Q 16384 | KV 16384 | KVT 16384 | P 4096 | RED 512
#define F_Q   0
#define F_KV  16384
#define F_KVT 32768
#define F_P   49152
#define F_RED 53248
#define FLASH_SMEM ((53248 + 512) * 4)

// ---------------- scratch ----------------
__device__ float g_cos[S_ * RH_];
__device__ float g_sin[S_ * RH_];
__device__ float g_x[(size_t)S_ * HID_];
__device__ float g_wqa[(size_t)QL_ * HID_];
__device__ float g_wqb[(size_t)H_ * D_ * QL_];
__device__ float g_wkv[(size_t)D_ * HID_];
__device__ float g_woa[(size_t)G_ * OR_ * 1024];
__device__ float g_wob[(size_t)HID_ * G_ * OR_];
__device__ float g_qa[(size_t)S_ * QL_];
__device__ float g_q[(size_t)S_ * H_ * D_];
__device__ float g_kv[(size_t)S_ * D_];
__device__ float g_kvT[(size_t)D_ * S_];
__device__ float g_o[(size_t)S_ * H_ * D_];
__device__ float g_or[(size_t)S_ * G_ * OR_];
__device__ float g_part[(size_t)8 * 1024 * 1024];    // 32 MB qa split-K partials
__device__ float g_part2[(size_t)4 * 1024 * 1024];   // 16 MB kv split-K partials

// ---------------- helpers ----------------
__device__ __forceinline__ uint32_t f2tf(float x) {
    uint32_t r;
    asm("cvt.rna.tf32.f32 %0, %1;" : "=r"(r) : "f"(x));
    return r;
}
__device__ __forceinline__ float f2tf_f(float x) { return __uint_as_float(f2tf(x)); }

__device__ __forceinline__ void mma_tf32(float4& c, const uint32_t a[4], const uint32_t b[2]) {
    asm volatile(
        "mma.sync.aligned.m16n8k8.row.col.f32.tf32.tf32.f32 "
        "{%0,%1,%2,%3}, {%4,%5,%6,%7}, {%8,%9}, {%0,%1,%2,%3};\n"
        : "+f"(c.x), "+f"(c.y), "+f"(c.z), "+f"(c.w)
        : "r"(a[0]), "r"(a[1]), "r"(a[2]), "r"(a[3]), "r"(b[0]), "r"(b[1]));
}
__device__ __forceinline__ void ldsm4(uint32_t* d, uint32_t addr) {
    asm volatile("ldmatrix.sync.aligned.m8n8.x4.shared.b16 {%0,%1,%2,%3}, [%4];"
        : "=r"(d[0]), "=r"(d[1]), "=r"(d[2]), "=r"(d[3]) : "r"(addr));
}
#define CP16(dst, src) \
    asm volatile("cp.async.cg.shared.global [%0], [%1], 16;\n" :: "r"(dst), "l"(src))
#define CP_COMMIT() asm volatile("cp.async.commit_group;\n")
#define CP_WAIT1()  asm volatile("cp.async.wait_group 1;\n")
#define CP_WAIT2()  asm volatile("cp.async.wait_group 2;\n")

__device__ __forceinline__ float block_reduce(float v, bool is_max) {
    __shared__ float warp_res[8];
    __shared__ float result;
    __syncthreads();
    #pragma unroll
    for (int o = 16; o; o >>= 1) {
        float other = __shfl_xor_sync(0xffffffffu, v, o);
        v = is_max ? fmaxf(v, other) : (v + other);
    }
    if ((threadIdx.x & 31) == 0) warp_res[threadIdx.x >> 5] = v;
    __syncthreads();
    if (threadIdx.x == 0) {
        int nw = (blockDim.x + 31) >> 5;
        float r = warp_res[0];
        for (int i = 1; i < nw; i++) r = is_max ? fmaxf(r, warp_res[i]) : (r + warp_res[i]);
        result = r;
    }
    __syncthreads();
    return result;
}

// single-launch tf32 rounding of all GEMM operands (compile-time segment table)
__global__ __launch_bounds__(256) void round_all(
    const float* __restrict__ x, const float* __restrict__ wqa,
    const float* __restrict__ wkv, const float* __restrict__ wqb,
    const float* __restrict__ woa, const float* __restrict__ wob)
{
    long i = (long)blockIdx.x * 256 + threadIdx.x;
    const float* src; float* dst; long off;
    if      (i < 1048576L) { src = x;   dst = g_x;   off = 0; }
    else if (i < 1572864L) { src = wqa; dst = g_wqa; off = 1048576L; }
    else if (i < 1703936L) { src = wkv; dst = g_wkv; off = 1572864L; }
    else if (i < 2752512L) { src = wqb; dst = g_wqb; off = 1703936L; }
    else if (i < 3276800L) { src = woa; dst = g_woa; off = 2752512L; }
    else                   { src = wob; dst = g_wob; off = 3276800L; }
    long k = i - off;
    float4 v = ((const float4*)src)[k];
    v.x = f2tf_f(v.x); v.y = f2tf_f(v.y); v.z = f2tf_f(v.z); v.w = f2tf_f(v.w);
    ((float4*)dst)[k] = v;
}

// deterministic fixed-order split-K reduction (final output only)
__global__ __launch_bounds__(256) void reduce_parts_k(const float* __restrict__ src,
                                                      float* __restrict__ dst,
                                                      int n4, long stride4, int parts) {
    int i = blockIdx.x * 256 + threadIdx.x;
    if (i >= n4) return;
    float4 a = ((const float4*)src)[i];
    for (int p = 1; p < parts; p++) {
        float4 b = ((const float4*)src)[i + (size_t)p * stride4];
        a.x += b.x; a.y += b.y; a.z += b.z; a.w += b.w;
    }
    ((float4*)dst)[i] = a;
}

// fused: qa = rms(sum of 4 split-K partials) * w, tf32-rounded
__global__ __launch_bounds__(256) void reduce_rms_qa(const float* __restrict__ part,
                                                     const float* __restrict__ w) {
    int s = blockIdx.x;
    const float* p0 = part + (long)s * QL_;
    float v[4];
    float ss = 0.f;
    #pragma unroll
    for (int i = 0; i < 4; i++) {
        int idx = threadIdx.x + i * 256;
        float a = p0[idx] + p0[idx + (long)S_ * QL_] +
                  p0[idx + 2L * S_ * QL_] + p0[idx + 3L * S_ * QL_];
        v[i] = a;
        ss += a * a;
    }
    ss = block_reduce(ss, false);
    float sc = rsqrtf(ss / QL_ + EPS_);
    #pragma unroll
    for (int i = 0; i < 4; i++) {
        int idx = threadIdx.x + i * 256;
        g_qa[(long)s * QL_ + idx] = f2tf_f(v[i] * sc * w[idx]);
    }
}

// fused: kv = rope(rms(sum of 8 split-K partials) * w), tf32-rounded
__global__ __launch_bounds__(256) void reduce_kv_post(const float* __restrict__ part,
                                                      const float* __restrict__ w) {
    int s = blockIdx.x;
    int d = threadIdx.x;
    const float* p0 = part + (long)s * D_ + d;
    float v = 0.f;
    #pragma unroll
    for (int p = 0; p < 8; p++) v += p0[(long)p * S_ * D_];
    float ss = block_reduce(v * v, false);
    float sc = rsqrtf(ss / D_ + EPS_);
    __shared__ float sh[D_];
    sh[d] = v * sc * w[d];
    __syncthreads();
    float out;
    if (d < NOPE_) out = sh[d];
    else {
        int p = d - NOPE_, i = p >> 1;
        float cc = g_cos[s * RH_ + i], sn = g_sin[s * RH_ + i];
        float x1 = sh[NOPE_ + (i << 1)], x2 = sh[NOPE_ + (i << 1) + 1];
        out = (p & 1) ? (x1 * sn + x2 * cc) : (x1 * cc - x2 * sn);
    }
    g_kv[(long)s * D_ + d] = f2tf_f(out);
}

// ============================================================================
// TF32 GEMM TN body: 128x64x32 tile, 256 threads, 3-stage cp.async, 3 CTAs/SM.
// ============================================================================
__device__ __forceinline__ void gemm_body(
    const float* __restrict__ A, const float* __restrict__ B, float* __restrict__ C,
    int K, int lda, int ldb, int ldc, int rnd)
{
    int row0 = blockIdx.y * BM, col0 = blockIdx.x * BN;
    int niter = K / BK;

    extern __shared__ uint32_t smem[];
    uint32_t smem_b = (uint32_t)__cvta_generic_to_shared(smem);

    int tid = threadIdx.x, lane = tid & 31, warp = tid >> 5;
    int wm = warp >> 1, wn = warp & 1;   // 4 x 2 warps

    int ldr = tid >> 3;
    int ldk = tid & 7;
    uint32_t dstA[4], dstB[2];
    const float* srcA[4];
    const float* srcB[2];
    #pragma unroll
    for (int i = 0; i < 4; i++) {
        int r = ldr + i * 32;
        dstA[i] = smem_b + ((((r << 3) + (ldk ^ (r & 7)))) << 4);
        srcA[i] = A + (long)(row0 + r) * lda + (ldk << 2);
    }
    #pragma unroll
    for (int i = 0; i < 2; i++) {
        int r = ldr + i * 32;
        dstB[i] = smem_b + 16384 + ((((r << 3) + (ldk ^ (r & 7)))) << 4);
        srcB[i] = B + (long)(col0 + r) * ldb + (ldk << 2);
    }

    int jr = ((lane >> 3) & 1) << 3;
    int jk = lane >> 4;
    int rr = lane & 7;
    uint32_t a_ad[2], b_ad[2];
    #pragma unroll
    for (int mt = 0; mt < 2; mt++) {
        int ar = wm * 32 + mt * 16 + jr + rr;
        a_ad[mt] = smem_b + (((ar << 3) + (jk ^ (ar & 7))) << 4);
    }
    #pragma unroll
    for (int ntp = 0; ntp < 2; ntp++) {
        int br = wn * 32 + ntp * 16 + jr + rr;
        b_ad[ntp] = smem_b + 16384 + (((br << 3) + (jk ^ (br & 7))) << 4);
    }

    float4 c[2][4];
    #pragma unroll
    for (int i = 0; i < 2; i++)
        #pragma unroll
        for (int j = 0; j < 4; j++) c[i][j] = make_float4(0.f, 0.f, 0.f, 0.f);

    #pragma unroll
    for (int i = 0; i < 4; i++) CP16(dstA[i], srcA[i]);
    #pragma unroll
    for (int i = 0; i < 2; i++) CP16(dstB[i], srcB[i]);
    CP_COMMIT();
    if (niter > 1) {
        #pragma unroll
        for (int i = 0; i < 4; i++) CP16(dstA[i] + STAGE_BYTES, srcA[i] + BK);
        #pragma unroll
        for (int i = 0; i < 2; i++) CP16(dstB[i] + STAGE_BYTES, srcB[i] + BK);
    }
    CP_COMMIT();
    #pragma unroll
    for (int i = 0; i < 4; i++) srcA[i] += 2 * BK;
    #pragma unroll
    for (int i = 0; i < 2; i++) srcB[i] += 2 * BK;

    int stage = 0;
    for (int k = 0; k < niter; k++) {
        CP_WAIT1();
        __syncthreads();

        if (k + 2 < niter) {
            int s2 = stage + 2; if (s2 >= 3) s2 -= 3;
            uint32_t so2 = (uint32_t)s2 * STAGE_BYTES;
            #pragma unroll
            for (int i = 0; i < 4; i++) CP16(dstA[i] + so2, srcA[i]);
            #pragma unroll
            for (int i = 0; i < 2; i++) CP16(dstB[i] + so2, srcB[i]);
        }
        CP_COMMIT();
        #pragma unroll
        for (int i = 0; i < 4; i++) srcA[i] += BK;
        #pragma unroll
        for (int i = 0; i < 2; i++) srcB[i] += BK;

        uint32_t so = (uint32_t)stage * STAGE_BYTES;
        uint32_t aa[2], bb[2];
        #pragma unroll
        for (int mt = 0; mt < 2; mt++) aa[mt] = a_ad[mt] + so;
        #pragma unroll
        for (int ntp = 0; ntp < 2; ntp++) bb[ntp] = b_ad[ntp] + so;

        #pragma unroll
        for (int ks = 0; ks < 4; ks++) {
            uint32_t af[2][4];
            #pragma unroll
            for (int mt = 0; mt < 2; mt++) ldsm4(af[mt], aa[mt] ^ (ks << 5));
            uint32_t bf[4][2];
            #pragma unroll
            for (int ntp = 0; ntp < 2; ntp++) {
                uint32_t t[4];
                ldsm4(t, bb[ntp] ^ (ks << 5));
                bf[ntp * 2][0]     = t[0];
                bf[ntp * 2 + 1][0] = t[1];
                bf[ntp * 2][1]     = t[2];
                bf[ntp * 2 + 1][1] = t[3];
            }
            #pragma unroll
            for (int mt = 0; mt < 2; mt++)
                #pragma unroll
                for (int nt = 0; nt < 4; nt++)
                    mma_tf32(c[mt][nt], af[mt], bf[nt]);
        }
        stage++; if (stage >= 3) stage -= 3;
    }

    #pragma unroll
    for (int mt = 0; mt < 2; mt++) {
        int m = row0 + wm * 32 + mt * 16 + (lane >> 2);
        #pragma unroll
        for (int nt = 0; nt < 4; nt++) {
            int n = col0 + wn * 32 + nt * 8 + ((lane & 3) << 1);
            float4 v = c[mt][nt];
            if (rnd) { v.x = f2tf_f(v.x); v.y = f2tf_f(v.y); v.z = f2tf_f(v.z); v.w = f2tf_f(v.w); }
            *(float2*)(C + (long)m * ldc + n)       = make_float2(v.x, v.y);
            *(float2*)(C + (long)(m + 8) * ldc + n) = make_float2(v.z, v.w);
        }
    }
}

__global__ __launch_bounds__(256, 3) void gemm_tn_tc(
    const float* __restrict__ A, const float* __restrict__ B, float* __restrict__ C,
    int K, int lda, int ldb, int ldc,
    long sA, long sB, long sC, int rnd)
{
    gemm_body(A + (long)blockIdx.z * sA, B + (long)blockIdx.z * sB,
              C + (long)blockIdx.z * sC, K, lda, ldb, ldc, rnd);
}

// combined qa + kv launch: z < zsplit -> set 1; else set 2 (x must be < xmax2)
__global__ __launch_bounds__(256, 3) void gemm_dual(
    const float* __restrict__ A,
    const float* __restrict__ B1, float* __restrict__ C1, int K1, int ldb1, int ldc1,
    long sA1, long sB1, long sC1,
    const float* __restrict__ B2, float* __restrict__ C2, int K2, int ldb2, int ldc2,
    long sA2, long sB2, long sC2,
    int lda, int zsplit, int xmax2)
{
    int z = blockIdx.z;
    if (z < zsplit) {
        gemm_body(A + (long)z * sA1, B1 + (long)z * sB1, C1 + (long)z * sC1,
                  K1, lda, ldb1, ldc1, 0);
    } else {
        if ((int)blockIdx.x >= xmax2) return;
        z -= zsplit;
        gemm_body(A + (long)z * sA2, B2 + (long)z * sB2, C2 + (long)z * sC2,
                  K2, lda, ldb2, ldc2, 0);
    }
}

// ============================================================================
// Fused flash attention + q_post (prologue) + o_post (epilogue).
// Per CTA = (head h, 64-row q tile qi). Single-barrier online softmax.
// ============================================================================
__global__ __launch_bounds__(256, 1) void flash_attn(const float* __restrict__ sink) {
    int bx = blockIdx.x;
    int h  = bx & 15;
    int qi = 31 - (bx >> 4);          // heavy tiles first
    int q0 = qi * 64;
    int jn = qi + 1;

    extern __shared__ float smf[];
    uint32_t smb = (uint32_t)__cvta_generic_to_shared(smf);
    uint32_t smQ = smb, smKV = smb + F_KV * 4, smKVT = smb + F_KVT * 4, smP = smb + F_P * 4;

    int tid = threadIdx.x, lane = tid & 31, warp = tid >> 5;
    int wm = warp >> 2, wn = warp & 3;
    int jr = ((lane >> 3) & 1) << 3;
    int jk = lane >> 4;
    int rr = lane & 7;
    int g  = lane >> 2;
    int e2 = (lane & 3) << 1;

    const float4* q4   = (const float4*)g_q + (size_t)q0 * 1024 + (size_t)h * 64;
    const float4* kv4  = (const float4*)g_kv;
    const float4* kvT4 = (const float4*)g_kvT;

    // group 1: Q (raw fp32 from wq_b GEMM)
    #pragma unroll
    for (int i = 0; i < 16; i++) {
        int id = tid + i * 256, row = id >> 6, k4 = id & 63;
        uint32_t dst = smQ + (uint32_t)((row << 6) + (k4 & 56) + ((k4 ^ row) & 7)) * 16;
        CP16(dst, q4 + (size_t)row * 1024 + k4);
    }
    CP_COMMIT();
    // group 2: KV_0
    #pragma unroll
    for (int i = 0; i < 16; i++) {
        int id = tid + i * 256, row = id >> 6, k4 = id & 63;
        uint32_t dst = smKV + (uint32_t)((row << 6) + (k4 & 56) + ((k4 ^ row) & 7)) * 16;
        CP16(dst, kv4 + (size_t)row * 64 + k4);
    }
    CP_COMMIT();
    // group 3: KVT_0
    #pragma unroll
    for (int i = 0; i < 16; i++) {
        int id = tid + i * 256, rd = id >> 4, k4 = id & 15;
        uint32_t dst = smKVT + (uint32_t)((rd << 4) + (k4 & 8) + ((k4 ^ rd) & 7)) * 16;
        CP16(dst, kvT4 + (size_t)rd * 512 + k4);
    }
    CP_COMMIT();

    // ---- fused q_post: normalize rows over D, rope cols 192..255, tf32-round ----
    CP_WAIT2();          // Q landed (KV_0, KVT_0 may still be in flight)
    __syncthreads();
    {
        int r = tid >> 2, qr = tid & 3;       // 4 threads per row, 16 float4 each
        float ssq = 0.f;
        #pragma unroll
        for (int t = 0; t < 16; t++) {
            int k4 = qr * 16 + t;
            int fo = ((r << 6) + (k4 & 56) + ((k4 ^ r) & 7)) << 2;
            float4 v = *(float4*)(smf + fo);
            ssq += v.x * v.x + v.y * v.y + v.z * v.z + v.w * v.w;
        }
        ssq += __shfl_xor_sync(0xffffffffu, ssq, 1);
        ssq += __shfl_xor_sync(0xffffffffu, ssq, 2);
        float sc = rsqrtf(ssq / 256.f + EPS_);
        int sg = q0 + r;
        #pragma unroll
        for (int t = 0; t < 16; t++) {
            int k4 = qr * 16 + t;
            int fo = ((r << 6) + (k4 & 56) + ((k4 ^ r) & 7)) << 2;
            float4 v = *(float4*)(smf + fo);
            v.x *= sc; v.y *= sc; v.z *= sc; v.w *= sc;
            if (qr == 3) {
                int i0 = 2 * k4 - 96;
                float c0 = g_cos[sg * RH_ + i0],     s0 = g_sin[sg * RH_ + i0];
                float c1 = g_cos[sg * RH_ + i0 + 1], s1 = g_sin[sg * RH_ + i0 + 1];
                float nx = v.x * c0 - v.y * s0, ny = v.x * s0 + v.y * c0;
                float nz = v.z * c1 - v.w * s1, nw = v.z * s1 + v.w * c1;
                v = make_float4(nx, ny, nz, nw);
            }
            *(float4*)(smf + fo) = make_float4(f2tf_f(v.x), f2tf_f(v.y), f2tf_f(v.z), f2tf_f(v.w));
        }
    }
    __syncthreads();

    uint32_t aSb[2], bSb, aPb[2], bPVb[4];
    #pragma unroll
    for (int mt = 0; mt < 2; mt++) {
        int ar = wm * 32 + mt * 16 + jr + rr;
        aSb[mt] = smQ + (uint32_t)((ar << 6) + (jk ^ (ar & 7))) * 16;
        aPb[mt] = smP + (uint32_t)((ar << 4) + (jk ^ (ar & 7))) * 16;
    }
    {
        int br = wn * 16 + jr + rr;
        bSb = smKV + (uint32_t)((br << 6) + (jk ^ (br & 7))) * 16;
    }
    #pragma unroll
    for (int ntp = 0; ntp < 4; ntp++) {
        int br = wn * 64 + ntp * 16 + jr + rr;
        bPVb[ntp] = smKVT + (uint32_t)((br << 4) + (jk ^ (br & 7))) * 16;
    }

    float4 cO[2][8];
    #pragma unroll
    for (int mt = 0; mt < 2; mt++)
        #pragma unroll
        for (int nt = 0; nt < 8; nt++) cO[mt][nt] = make_float4(0.f, 0.f, 0.f, 0.f);
    float mrow[4] = {-3.0e38f, -3.0e38f, -3.0e38f, -3.0e38f};
    float lrow[4] = {0.f, 0.f, 0.f, 0.f};

    for (int j = 0; j < jn; j++) {
        CP_WAIT1();
        __syncthreads();

        float4 sS[2][2];
        #pragma unroll
        for (int mt = 0; mt < 2; mt++)
            #pragma unroll
            for (int nt = 0; nt < 2; nt++) sS[mt][nt] = make_float4(0.f, 0.f, 0.f, 0.f);

        #pragma unroll
        for (int cc = 0; cc < 8; cc++) {
            uint32_t ao = (uint32_t)cc * 128;
            #pragma unroll
            for (int ks = 0; ks < 4; ks++) {
                uint32_t af[2][4];
                #pragma unroll
                for (int mt = 0; mt < 2; mt++) ldsm4(af[mt], (aSb[mt] + ao) ^ (ks << 5));
                uint32_t tb[4];
                ldsm4(tb, (bSb + ao) ^ (ks << 5));
                uint32_t b0[2] = {tb[0], tb[2]}, b1[2] = {tb[1], tb[3]};
                #pragma unroll
                for (int mt = 0; mt < 2; mt++) {
                    mma_tf32(sS[mt][0], af[mt], b0);
                    mma_tf32(sS[mt][1], af[mt], b1);
                }
            }
        }

        #pragma unroll
        for (int mt = 0; mt < 2; mt++)
            #pragma unroll
            for (int nt = 0; nt < 2; nt++) {
                sS[mt][nt].x *= SCALE_; sS[mt][nt].y *= SCALE_;
                sS[mt][nt].z *= SCALE_; sS[mt][nt].w *= SCALE_;
            }
        if (j == qi) {
            #pragma unroll
            for (int mt = 0; mt < 2; mt++) {
                int r0 = wm * 32 + mt * 16 + g;
                #pragma unroll
                for (int nt = 0; nt < 2; nt++) {
                    int c0 = wn * 16 + nt * 8 + e2;
                    if (c0 > r0)     sS[mt][nt].x = -3.0e38f;
                    if (c0 + 1 > r0) sS[mt][nt].y = -3.0e38f;
                    if (c0 > r0 + 8)     sS[mt][nt].z = -3.0e38f;
                    if (c0 + 1 > r0 + 8) sS[mt][nt].w = -3.0e38f;
                }
            }
        }

        // ---- warp-local row max over this warp's 16 cols ----
        float rm[4];
        #pragma unroll
        for (int mt = 0; mt < 2; mt++) {
            rm[mt * 2 + 0] = fmaxf(fmaxf(sS[mt][0].x, sS[mt][0].y), fmaxf(sS[mt][1].x, sS[mt][1].y));
            rm[mt * 2 + 1] = fmaxf(fmaxf(sS[mt][0].z, sS[mt][0].w), fmaxf(sS[mt][1].z, sS[mt][1].w));
        }
        #pragma unroll
        for (int i = 0; i < 4; i++) {
            rm[i] = fmaxf(rm[i], __shfl_xor_sync(0xffffffffu, rm[i], 1));
            rm[i] = fmaxf(rm[i], __shfl_xor_sync(0xffffffffu, rm[i], 2));
        }

        // ---- exp against warp-local max; warp-local sums ----
        float ls[4];
        #pragma unroll
        for (int mt = 0; mt < 2; mt++) {
            #pragma unroll
            for (int nt = 0; nt < 2; nt++) {
                sS[mt][nt].x = __expf(sS[mt][nt].x - rm[mt * 2 + 0]);
                sS[mt][nt].y = __expf(sS[mt][nt].y - rm[mt * 2 + 0]);
                sS[mt][nt].z = __expf(sS[mt][nt].z - rm[mt * 2 + 1]);
                sS[mt][nt].w = __expf(sS[mt][nt].w - rm[mt * 2 + 1]);
            }
            ls[mt * 2 + 0] = sS[mt][0].x + sS[mt][0].y + sS[mt][1].x + sS[mt][1].y;
            ls[mt * 2 + 1] = sS[mt][0].z + sS[mt][0].w + sS[mt][1].z + sS[mt][1].w;
        }
        #pragma unroll
        for (int i = 0; i < 4; i++) {
            ls[i] += __shfl_xor_sync(0xffffffffu, ls[i], 1);
            ls[i] += __shfl_xor_sync(0xffffffffu, ls[i], 2);
        }

        // ---- publish (m_w, l_w); ONE barrier ----
        #pragma unroll
        for (int i = 0; i < 4; i++) {
            int row = wm * 32 + (i >> 1) * 16 + g + (i & 1) * 8;
            smf[F_RED + wn * 64 + row] = rm[i];
            smf[F_RED + 256 + wn * 64 + row] = ls[i];
        }
        __syncthreads();   // (A)

        if (j + 1 < jn) {
            const float4* kvs = kv4 + (size_t)(j + 1) * 64 * 64;
            #pragma unroll
            for (int i = 0; i < 16; i++) {
                int id = tid + i * 256, row = id >> 6, k4 = id & 63;
                uint32_t dst = smKV + (uint32_t)((row << 6) + (k4 & 56) + ((k4 ^ row) & 7)) * 16;
                CP16(dst, kvs + (size_t)row * 64 + k4);
            }
        }
        CP_COMMIT();

        // ---- combine across warps; correction factors ----
        float alpha[4], cf[4];
        #pragma unroll
        for (int i = 0; i < 4; i++) {
            int row = wm * 32 + (i >> 1) * 16 + g + (i & 1) * 8;
            float m0 = smf[F_RED + row],        m1 = smf[F_RED + 64 + row];
            float m2 = smf[F_RED + 128 + row],  m3 = smf[F_RED + 192 + row];
            float mnew = fmaxf(mrow[i], fmaxf(fmaxf(m0, m1), fmaxf(m2, m3)));
            alpha[i] = __expf(mrow[i] - mnew);
            float l0 = smf[F_RED + 256 + row],       l1 = smf[F_RED + 256 + 64 + row];
            float l2 = smf[F_RED + 256 + 128 + row], l3 = smf[F_RED + 256 + 192 + row];
            lrow[i] = lrow[i] * alpha[i] +
                      l0 * __expf(m0 - mnew) + l1 * __expf(m1 - mnew) +
                      l2 * __expf(m2 - mnew) + l3 * __expf(m3 - mnew);
            cf[i] = __expf(rm[i] - mnew);
            mrow[i] = mnew;
        }

        #pragma unroll
        for (int mt = 0; mt < 2; mt++)
            #pragma unroll
            for (int nt = 0; nt < 8; nt++) {
                cO[mt][nt].x *= alpha[mt * 2 + 0];
                cO[mt][nt].y *= alpha[mt * 2 + 0];
                cO[mt][nt].z *= alpha[mt * 2 + 1];
                cO[mt][nt].w *= alpha[mt * 2 + 1];
            }

        // ---- store P (corrected + tf32) ----
        #pragma unroll
        for (int mt = 0; mt < 2; mt++)
            #pragma unroll
            for (int nt = 0; nt < 2; nt++) {
                int c = wn * 16 + nt * 8 + e2;
                int k4 = c >> 2;
                float cf0 = cf[mt * 2 + 0], cf1 = cf[mt * 2 + 1];
                {
                    int row = wm * 32 + mt * 16 + g;
                    int fi = F_P + (((row << 4) + (k4 & 8) + ((k4 ^ row) & 7)) << 2) + (c & 2);
                    *(float2*)(smf + fi) = make_float2(f2tf_f(sS[mt][nt].x * cf0),
                                                       f2tf_f(sS[mt][nt].y * cf0));
                }
                {
                    int row = wm * 32 + mt * 16 + g + 8;
                    int fi = F_P + (((row << 4) + (k4 & 8) + ((k4 ^ row) & 7)) << 2) + (c & 2);
                    *(float2*)(smf + fi) = make_float2(f2tf_f(sS[mt][nt].z * cf1),
                                                       f2tf_f(sS[mt][nt].w * cf1));
                }
            }

        CP_WAIT1();
        __syncthreads();   // (C)

        #pragma unroll
        for (int kk = 0; kk < 8; kk++) {
            uint32_t xo = (uint32_t)((kk & 3) << 5);
            uint32_t ad = (uint32_t)((kk >> 2) << 7);
            uint32_t af[2][4];
            #pragma unroll
            for (int mt = 0; mt < 2; mt++) ldsm4(af[mt], (aPb[mt] + ad) ^ xo);
            #pragma unroll
            for (int ntp = 0; ntp < 4; ntp++) {
                uint32_t tb[4];
                ldsm4(tb, (bPVb[ntp] + ad) ^ xo);
                uint32_t b0[2] = {tb[0], tb[2]}, b1[2] = {tb[1], tb[3]};
                #pragma unroll
                for (int mt = 0; mt < 2; mt++) {
                    mma_tf32(cO[mt][ntp * 2 + 0], af[mt], b0);
                    mma_tf32(cO[mt][ntp * 2 + 1], af[mt], b1);
                }
            }
        }
        __syncthreads();   // (D)

        if (j + 1 < jn) {
            const float4* kvts = kvT4 + (size_t)(j + 1) * 16;
            #pragma unroll
            for (int i = 0; i < 16; i++) {
                int id = tid + i * 256, rd = id >> 4, k4 = id & 15;
                uint32_t dst = smKVT + (uint32_t)((rd << 4) + (k4 & 8) + ((k4 ^ rd) & 7)) * 16;
                CP16(dst, kvts + (size_t)rd * 512 + k4);
            }
        }
        CP_COMMIT();
    }

    // ---- finalize: sink + normalize + fused inverse RoPE (wn==3) + tf32 round ----
    float snk = sink[h];
    float fac[4];
    #pragma unroll
    for (int i = 0; i < 4; i++) {
        float mf = fmaxf(mrow[i], snk);
        float af = __expf(mrow[i] - mf);
        float lf = lrow[i] * af + __expf(snk - mf);
        fac[i] = af / lf;
    }
    #pragma unroll
    for (int mt = 0; mt < 2; mt++) {
        int r = q0 + wm * 32 + mt * 16 + g;
        #pragma unroll
        for (int nt = 0; nt < 8; nt++) {
            int c = wn * 64 + nt * 8 + e2;
            float v0 = cO[mt][nt].x * fac[mt * 2 + 0];
            float v1 = cO[mt][nt].y * fac[mt * 2 + 0];
            float v2 = cO[mt][nt].z * fac[mt * 2 + 1];
            float v3 = cO[mt][nt].w * fac[mt * 2 + 1];
            if (wn == 3) {
                int i = (c & 63) >> 1;
                float c1 = g_cos[r * RH_ + i],       s1 = g_sin[r * RH_ + i];
                float c2 = g_cos[(r + 8) * RH_ + i], s2 = g_sin[(r + 8) * RH_ + i];
                float t0 = v0 * c1 + v1 * s1, t1 = v1 * c1 - v0 * s1;
                float t2 = v2 * c2 + v3 * s2, t3 = v3 * c2 - v2 * s2;
                v0 = t0; v1 = t1; v2 = t2; v3 = t3;
            }
            float* p0 = g_o + (size_t)r * (H_ * D_) + (size_t)h * D_ + c;
            *(float2*)p0 = make_float2(f2tf_f(v0), f2tf_f(v1));
            *(float2*)(p0 + (size_t)8 * (H_ * D_)) = make_float2(f2tf_f(v2), f2tf_f(v3));
        }
    }
}

// ---------------- elementwise ----------------
__global__ void cos_sin_k(const float* __restrict__ freqs) {
    int i = blockIdx.x * blockDim.x + threadIdx.x;
    if (i < S_ * RH_) {
        float f = freqs[i];
        g_cos[i] = cosf(f);
        g_sin[i] = sinf(f);
    }
}

__global__ __launch_bounds__(256) void transpose_kv() {
    __shared__ float t[32][33];
    int x = threadIdx.x & 31, y = threadIdx.x >> 5;
    #pragma unroll
    for (int i = 0; i < 4; i++) {
        int trow = blockIdx.x * 32 + y + i * 8;
        t[y + i * 8][x] = g_kv[(size_t)trow * D_ + blockIdx.y * 32 + x];
    }
    __syncthreads();
    #pragma unroll
    for (int i = 0; i < 4; i++) {
        int drow = blockIdx.y * 32 + y + i * 8;
        g_kvT[(size_t)drow * S_ + blockIdx.x * 32 + x] = t[x][y + i * 8];
    }
}

// ---------------- launch ----------------
extern "C" void kernel_launch(void* const* d_in, const int* in_sizes, int n_in,
                              void* d_out, int out_size) {
    const float* x        = (const float*)d_in[0];
    const float* freqs    = (const float*)d_in[1];
    const float* wq_a     = (const float*)d_in[2];
    const float* q_norm_w = (const float*)d_in[3];
    const float* wq_b     = (const float*)d_in[4];
    const float* wkv      = (const float*)d_in[5];
    const float* kv_norm_w= (const float*)d_in[6];
    const float* wo_a_w   = (const float*)d_in[7];
    const float* wo_b     = (const float*)d_in[8];
    const float* sink     = (const float*)d_in[9];
    float* out = (float*)d_out;

    float *p_x, *p_wqa, *p_wqb, *p_wkv, *p_woa, *p_wob;
    float *p_qa, *p_q, *p_o, *p_or, *p_part, *p_part2;
    cudaGetSymbolAddress((void**)&p_x,   g_x);
    cudaGetSymbolAddress((void**)&p_wqa, g_wqa);
    cudaGetSymbolAddress((void**)&p_wqb, g_wqb);
    cudaGetSymbolAddress((void**)&p_wkv, g_wkv);
    cudaGetSymbolAddress((void**)&p_woa, g_woa);
    cudaGetSymbolAddress((void**)&p_wob, g_wob);
    cudaGetSymbolAddress((void**)&p_qa,  g_qa);
    cudaGetSymbolAddress((void**)&p_q,   g_q);
    cudaGetSymbolAddress((void**)&p_o,   g_o);
    cudaGetSymbolAddress((void**)&p_or,  g_or);
    cudaGetSymbolAddress((void**)&p_part, g_part);
    cudaGetSymbolAddress((void**)&p_part2, g_part2);

    cudaFuncSetAttribute(gemm_tn_tc, cudaFuncAttributeMaxDynamicSharedMemorySize, GEMM_SMEM);
    cudaFuncSetAttribute(gemm_dual,  cudaFuncAttributeMaxDynamicSharedMemorySize, GEMM_SMEM);
    cudaFuncSetAttribute(flash_attn, cudaFuncAttributeMaxDynamicSharedMemorySize, FLASH_SMEM);

    cos_sin_k<<<(S_ * RH_ + 255) / 256, 256>>>(freqs);
    round_all<<<16896, 256>>>(x, wq_a, wkv, wq_b, wo_a_w, wo_b);

    // combined: qa = x@wqa^T (split-K x4, z 0..3) + kv = x@wkv^T (split-K x8, z 4..11)
    gemm_dual<<<dim3(QL_ / BN, S_ / BM, 12), 256, GEMM_SMEM>>>(
        p_x,
        p_wqa, p_part, 512, HID_, QL_, 512, 512, (long)S_ * QL_,
        p_wkv, p_part2, 256, HID_, D_, 256, 256, (long)S_ * D_,
        HID_, 4, D_ / BN);
    reduce_rms_qa<<<S_, 256>>>(p_part, q_norm_w);
    reduce_kv_post<<<S_, 256>>>(p_part2, kv_norm_w);
    transpose_kv<<<dim3(S_ / 32, D_ / 32), 256>>>();

    // q = qa @ wq_b^T (raw fp32; flash normalizes/ropes/rounds in its prologue)
    gemm_tn_tc<<<dim3((H_ * D_) / BN, S_ / BM, 1), 256, GEMM_SMEM>>>(p_qa, p_wqb, p_q,
        QL_, QL_, QL_, H_ * D_, 0, 0, 0, 0);

    // fused attention (q_post + attention + o_post)
    flash_attn<<<512, 256, FLASH_SMEM>>>(sink);

    // grouped wo_a (tf32-rounded output in epilogue)
    gemm_tn_tc<<<dim3(OR_ / BN, S_ / BM, G_), 256, GEMM_SMEM>>>(p_o, p_woa, p_or,
        (H_ / G_) * D_, H_ * D_, (H_ / G_) * D_, G_ * OR_,
        (long)(H_ / G_) * D_, (long)OR_ * (H_ / G_) * D_, (long)OR_, 1);

    // out = o_r @ wo_b^T — split-K x2
    gemm_tn_tc<<<dim3(HID_ / BN, S_ / BM, 2), 256, GEMM_SMEM>>>(p_or, p_wob, p_part,
        1024, G_ * OR_, G_ * OR_, HID_, 1024, 1024, (long)S_ * HID_, 0);
    reduce_parts_k<<<(S_ * HID_ / 4 + 255) / 256, 256>>>(p_part, out,
        S_ * HID_ / 4, (long)S_ * HID_ / 4, 2);
}

// round 16
// speedup vs baseline: 2.4223x; 1.0071x over previous
#include <cuda_runtime.h>
#include <cstdint>

#define S_    2048
#define HID_  2048
#define H_    16
#define D_    256
#define R_    64
#define RH_   32          // R/2
#define NOPE_ 192
#define QL_   1024
#define OR_   512
#define G_    4
#define EPS_  1e-6f
#define SCALE_ 0.0625f    // 256^-0.5

#define BM 128
#define BN 64
#define BK 32
#define STAGE_BYTES 24576            // A 16KB + B 8KB per stage
#define GEMM_SMEM (3 * STAGE_BYTES)  // 72 KB -> 3 CTAs/SM

// flash smem (floats): Q 16384 | KV 16384 | KVT 16384 | P 4096 | RED 512
#define F_Q   0
#define F_KV  16384
#define F_KVT 32768
#define F_P   49152
#define F_RED 53248
#define FLASH_SMEM ((53248 + 512) * 4)

// ---------------- scratch ----------------
__device__ float g_cos[S_ * RH_];
__device__ float g_sin[S_ * RH_];
__device__ float g_x[(size_t)S_ * HID_];
__device__ float g_wqa[(size_t)QL_ * HID_];
__device__ float g_wqb[(size_t)H_ * D_ * QL_];
__device__ float g_wkv[(size_t)D_ * HID_];
__device__ float g_woa[(size_t)G_ * OR_ * 1024];
__device__ float g_wob[(size_t)HID_ * G_ * OR_];
__device__ float g_qa[(size_t)S_ * QL_];
__device__ float g_q[(size_t)S_ * H_ * D_];
__device__ float g_kv[(size_t)S_ * D_];
__device__ float g_kvT[(size_t)D_ * S_];
__device__ float g_o[(size_t)S_ * H_ * D_];
__device__ float g_or[(size_t)S_ * G_ * OR_];
__device__ float g_part[(size_t)8 * 1024 * 1024];    // 32 MB qa split-K partials
__device__ float g_part2[(size_t)4 * 1024 * 1024];   // 16 MB kv split-K partials

// ---------------- helpers ----------------
__device__ __forceinline__ uint32_t f2tf(float x) {
    uint32_t r;
    asm("cvt.rna.tf32.f32 %0, %1;" : "=r"(r) : "f"(x));
    return r;
}
__device__ __forceinline__ float f2tf_f(float x) { return __uint_as_float(f2tf(x)); }

__device__ __forceinline__ void mma_tf32(float4& c, const uint32_t a[4], const uint32_t b[2]) {
    asm volatile(
        "mma.sync.aligned.m16n8k8.row.col.f32.tf32.tf32.f32 "
        "{%0,%1,%2,%3}, {%4,%5,%6,%7}, {%8,%9}, {%0,%1,%2,%3};\n"
        : "+f"(c.x), "+f"(c.y), "+f"(c.z), "+f"(c.w)
        : "r"(a[0]), "r"(a[1]), "r"(a[2]), "r"(a[3]), "r"(b[0]), "r"(b[1]));
}
__device__ __forceinline__ void ldsm4(uint32_t* d, uint32_t addr) {
    asm volatile("ldmatrix.sync.aligned.m8n8.x4.shared.b16 {%0,%1,%2,%3}, [%4];"
        : "=r"(d[0]), "=r"(d[1]), "=r"(d[2]), "=r"(d[3]) : "r"(addr));
}
#define CP16(dst, src) \
    asm volatile("cp.async.cg.shared.global [%0], [%1], 16;\n" :: "r"(dst), "l"(src))
#define CP_COMMIT() asm volatile("cp.async.commit_group;\n")
#define CP_WAIT1()  asm volatile("cp.async.wait_group 1;\n")
#define CP_WAIT2()  asm volatile("cp.async.wait_group 2;\n")

__device__ __forceinline__ float block_reduce(float v, bool is_max) {
    __shared__ float warp_res[8];
    __shared__ float result;
    __syncthreads();
    #pragma unroll
    for (int o = 16; o; o >>= 1) {
        float other = __shfl_xor_sync(0xffffffffu, v, o);
        v = is_max ? fmaxf(v, other) : (v + other);
    }
    if ((threadIdx.x & 31) == 0) warp_res[threadIdx.x >> 5] = v;
    __syncthreads();
    if (threadIdx.x == 0) {
        int nw = (blockDim.x + 31) >> 5;
        float r = warp_res[0];
        for (int i = 1; i < nw; i++) r = is_max ? fmaxf(r, warp_res[i]) : (r + warp_res[i]);
        result = r;
    }
    __syncthreads();
    return result;
}

// single prep launch: cos/sin of freqs (segment 0) + tf32 rounding of operands
__global__ __launch_bounds__(256) void prep_k(
    const float* __restrict__ freqs,
    const float* __restrict__ x, const float* __restrict__ wqa,
    const float* __restrict__ wkv, const float* __restrict__ wqb,
    const float* __restrict__ woa, const float* __restrict__ wob)
{
    long i = (long)blockIdx.x * 256 + threadIdx.x;
    if (i < 16384L) {
        float4 f = ((const float4*)freqs)[i];
        ((float4*)g_cos)[i] = make_float4(cosf(f.x), cosf(f.y), cosf(f.z), cosf(f.w));
        ((float4*)g_sin)[i] = make_float4(sinf(f.x), sinf(f.y), sinf(f.z), sinf(f.w));
        return;
    }
    i -= 16384L;
    const float* src; float* dst; long off;
    if      (i < 1048576L) { src = x;   dst = g_x;   off = 0; }
    else if (i < 1572864L) { src = wqa; dst = g_wqa; off = 1048576L; }
    else if (i < 1703936L) { src = wkv; dst = g_wkv; off = 1572864L; }
    else if (i < 2752512L) { src = wqb; dst = g_wqb; off = 1703936L; }
    else if (i < 3276800L) { src = woa; dst = g_woa; off = 2752512L; }
    else                   { src = wob; dst = g_wob; off = 3276800L; }
    long k = i - off;
    float4 v = ((const float4*)src)[k];
    v.x = f2tf_f(v.x); v.y = f2tf_f(v.y); v.z = f2tf_f(v.z); v.w = f2tf_f(v.w);
    ((float4*)dst)[k] = v;
}

// deterministic fixed-order split-K reduction (final output only)
__global__ __launch_bounds__(256) void reduce_parts_k(const float* __restrict__ src,
                                                      float* __restrict__ dst,
                                                      int n4, long stride4, int parts) {
    int i = blockIdx.x * 256 + threadIdx.x;
    if (i >= n4) return;
    float4 a = ((const float4*)src)[i];
    for (int p = 1; p < parts; p++) {
        float4 b = ((const float4*)src)[i + (size_t)p * stride4];
        a.x += b.x; a.y += b.y; a.z += b.z; a.w += b.w;
    }
    ((float4*)dst)[i] = a;
}

// merged post-processing: y==0 -> qa = rms(sum4 partials)*w; y==1 -> kv+kvT
__global__ __launch_bounds__(256) void reduce_post(
    const float* __restrict__ partq, const float* __restrict__ wq,
    const float* __restrict__ partk, const float* __restrict__ wk)
{
    int s = blockIdx.x;
    if (blockIdx.y == 0) {
        const float* p0 = partq + (long)s * QL_;
        float v[4];
        float ss = 0.f;
        #pragma unroll
        for (int i = 0; i < 4; i++) {
            int idx = threadIdx.x + i * 256;
            float a = p0[idx] + p0[idx + (long)S_ * QL_] +
                      p0[idx + 2L * S_ * QL_] + p0[idx + 3L * S_ * QL_];
            v[i] = a;
            ss += a * a;
        }
        ss = block_reduce(ss, false);
        float sc = rsqrtf(ss / QL_ + EPS_);
        #pragma unroll
        for (int i = 0; i < 4; i++) {
            int idx = threadIdx.x + i * 256;
            g_qa[(long)s * QL_ + idx] = f2tf_f(v[i] * sc * wq[idx]);
        }
    } else {
        int d = threadIdx.x;
        const float* p0 = partk + (long)s * D_ + d;
        float v = 0.f;
        #pragma unroll
        for (int p = 0; p < 8; p++) v += p0[(long)p * S_ * D_];
        float ss = block_reduce(v * v, false);
        float sc = rsqrtf(ss / D_ + EPS_);
        __shared__ float sh[D_];
        sh[d] = v * sc * wk[d];
        __syncthreads();
        float out;
        if (d < NOPE_) out = sh[d];
        else {
            int p = d - NOPE_, i = p >> 1;
            float cc = g_cos[s * RH_ + i], sn = g_sin[s * RH_ + i];
            float x1 = sh[NOPE_ + (i << 1)], x2 = sh[NOPE_ + (i << 1) + 1];
            out = (p & 1) ? (x1 * sn + x2 * cc) : (x1 * cc - x2 * sn);
        }
        float r = f2tf_f(out);
        g_kv[(long)s * D_ + d] = r;
        g_kvT[(long)d * S_ + s] = r;
    }
}

// ============================================================================
// TF32 GEMM TN body: 128x64x32 tile, 256 threads, 3-stage cp.async, 3 CTAs/SM.
// ============================================================================
__device__ __forceinline__ void gemm_body(
    const float* __restrict__ A, const float* __restrict__ B, float* __restrict__ C,
    int K, int lda, int ldb, int ldc, int rnd)
{
    int row0 = blockIdx.y * BM, col0 = blockIdx.x * BN;
    int niter = K / BK;

    extern __shared__ uint32_t smem[];
    uint32_t smem_b = (uint32_t)__cvta_generic_to_shared(smem);

    int tid = threadIdx.x, lane = tid & 31, warp = tid >> 5;
    int wm = warp >> 1, wn = warp & 1;   // 4 x 2 warps

    int ldr = tid >> 3;
    int ldk = tid & 7;
    uint32_t dstA[4], dstB[2];
    const float* srcA[4];
    const float* srcB[2];
    #pragma unroll
    for (int i = 0; i < 4; i++) {
        int r = ldr + i * 32;
        dstA[i] = smem_b + ((((r << 3) + (ldk ^ (r & 7)))) << 4);
        srcA[i] = A + (long)(row0 + r) * lda + (ldk << 2);
    }
    #pragma unroll
    for (int i = 0; i < 2; i++) {
        int r = ldr + i * 32;
        dstB[i] = smem_b + 16384 + ((((r << 3) + (ldk ^ (r & 7)))) << 4);
        srcB[i] = B + (long)(col0 + r) * ldb + (ldk << 2);
    }

    int jr = ((lane >> 3) & 1) << 3;
    int jk = lane >> 4;
    int rr = lane & 7;
    uint32_t a_ad[2], b_ad[2];
    #pragma unroll
    for (int mt = 0; mt < 2; mt++) {
        int ar = wm * 32 + mt * 16 + jr + rr;
        a_ad[mt] = smem_b + (((ar << 3) + (jk ^ (ar & 7))) << 4);
    }
    #pragma unroll
    for (int ntp = 0; ntp < 2; ntp++) {
        int br = wn * 32 + ntp * 16 + jr + rr;
        b_ad[ntp] = smem_b + 16384 + (((br << 3) + (jk ^ (br & 7))) << 4);
    }

    float4 c[2][4];
    #pragma unroll
    for (int i = 0; i < 2; i++)
        #pragma unroll
        for (int j = 0; j < 4; j++) c[i][j] = make_float4(0.f, 0.f, 0.f, 0.f);

    #pragma unroll
    for (int i = 0; i < 4; i++) CP16(dstA[i], srcA[i]);
    #pragma unroll
    for (int i = 0; i < 2; i++) CP16(dstB[i], srcB[i]);
    CP_COMMIT();
    if (niter > 1) {
        #pragma unroll
        for (int i = 0; i < 4; i++) CP16(dstA[i] + STAGE_BYTES, srcA[i] + BK);
        #pragma unroll
        for (int i = 0; i < 2; i++) CP16(dstB[i] + STAGE_BYTES, srcB[i] + BK);
    }
    CP_COMMIT();
    #pragma unroll
    for (int i = 0; i < 4; i++) srcA[i] += 2 * BK;
    #pragma unroll
    for (int i = 0; i < 2; i++) srcB[i] += 2 * BK;

    int stage = 0;
    for (int k = 0; k < niter; k++) {
        CP_WAIT1();
        __syncthreads();

        if (k + 2 < niter) {
            int s2 = stage + 2; if (s2 >= 3) s2 -= 3;
            uint32_t so2 = (uint32_t)s2 * STAGE_BYTES;
            #pragma unroll
            for (int i = 0; i < 4; i++) CP16(dstA[i] + so2, srcA[i]);
            #pragma unroll
            for (int i = 0; i < 2; i++) CP16(dstB[i] + so2, srcB[i]);
        }
        CP_COMMIT();
        #pragma unroll
        for (int i = 0; i < 4; i++) srcA[i] += BK;
        #pragma unroll
        for (int i = 0; i < 2; i++) srcB[i] += BK;

        uint32_t so = (uint32_t)stage * STAGE_BYTES;
        uint32_t aa[2], bb[2];
        #pragma unroll
        for (int mt = 0; mt < 2; mt++) aa[mt] = a_ad[mt] + so;
        #pragma unroll
        for (int ntp = 0; ntp < 2; ntp++) bb[ntp] = b_ad[ntp] + so;

        #pragma unroll
        for (int ks = 0; ks < 4; ks++) {
            uint32_t af[2][4];
            #pragma unroll
            for (int mt = 0; mt < 2; mt++) ldsm4(af[mt], aa[mt] ^ (ks << 5));
            uint32_t bf[4][2];
            #pragma unroll
            for (int ntp = 0; ntp < 2; ntp++) {
                uint32_t t[4];
                ldsm4(t, bb[ntp] ^ (ks << 5));
                bf[ntp * 2][0]     = t[0];
                bf[ntp * 2 + 1][0] = t[1];
                bf[ntp * 2][1]     = t[2];
                bf[ntp * 2 + 1][1] = t[3];
            }
            #pragma unroll
            for (int mt = 0; mt < 2; mt++)
                #pragma unroll
                for (int nt = 0; nt < 4; nt++)
                    mma_tf32(c[mt][nt], af[mt], bf[nt]);
        }
        stage++; if (stage >= 3) stage -= 3;
    }

    #pragma unroll
    for (int mt = 0; mt < 2; mt++) {
        int m = row0 + wm * 32 + mt * 16 + (lane >> 2);
        #pragma unroll
        for (int nt = 0; nt < 4; nt++) {
            int n = col0 + wn * 32 + nt * 8 + ((lane & 3) << 1);
            float4 v = c[mt][nt];
            if (rnd) { v.x = f2tf_f(v.x); v.y = f2tf_f(v.y); v.z = f2tf_f(v.z); v.w = f2tf_f(v.w); }
            *(float2*)(C + (long)m * ldc + n)       = make_float2(v.x, v.y);
            *(float2*)(C + (long)(m + 8) * ldc + n) = make_float2(v.z, v.w);
        }
    }
}

__global__ __launch_bounds__(256, 3) void gemm_tn_tc(
    const float* __restrict__ A, const float* __restrict__ B, float* __restrict__ C,
    int K, int lda, int ldb, int ldc,
    long sA, long sB, long sC, int rnd)
{
    gemm_body(A + (long)blockIdx.z * sA, B + (long)blockIdx.z * sB,
              C + (long)blockIdx.z * sC, K, lda, ldb, ldc, rnd);
}

// combined qa + kv launch: z < zsplit -> set 1; else set 2 (x must be < xmax2)
__global__ __launch_bounds__(256, 3) void gemm_dual(
    const float* __restrict__ A,
    const float* __restrict__ B1, float* __restrict__ C1, int K1, int ldb1, int ldc1,
    long sA1, long sB1, long sC1,
    const float* __restrict__ B2, float* __restrict__ C2, int K2, int ldb2, int ldc2,
    long sA2, long sB2, long sC2,
    int lda, int zsplit, int xmax2)
{
    int z = blockIdx.z;
    if (z < zsplit) {
        gemm_body(A + (long)z * sA1, B1 + (long)z * sB1, C1 + (long)z * sC1,
                  K1, lda, ldb1, ldc1, 0);
    } else {
        if ((int)blockIdx.x >= xmax2) return;
        z -= zsplit;
        gemm_body(A + (long)z * sA2, B2 + (long)z * sB2, C2 + (long)z * sC2,
                  K2, lda, ldb2, ldc2, 0);
    }
}

// ============================================================================
// Fused flash attention + q_post (prologue) + o_post (epilogue).
// Per CTA = (head h, 64-row q tile qi). Single-barrier online softmax.
// ============================================================================
__global__ __launch_bounds__(256, 1) void flash_attn(const float* __restrict__ sink) {
    int bx = blockIdx.x;
    int h  = bx & 15;
    int qi = 31 - (bx >> 4);          // heavy tiles first
    int q0 = qi * 64;
    int jn = qi + 1;

    extern __shared__ float smf[];
    uint32_t smb = (uint32_t)__cvta_generic_to_shared(smf);
    uint32_t smQ = smb, smKV = smb + F_KV * 4, smKVT = smb + F_KVT * 4, smP = smb + F_P * 4;

    int tid = threadIdx.x, lane = tid & 31, warp = tid >> 5;
    int wm = warp >> 2, wn = warp & 3;
    int jr = ((lane >> 3) & 1) << 3;
    int jk = lane >> 4;
    int rr = lane & 7;
    int g  = lane >> 2;
    int e2 = (lane & 3) << 1;

    const float4* q4   = (const float4*)g_q + (size_t)q0 * 1024 + (size_t)h * 64;
    const float4* kv4  = (const float4*)g_kv;
    const float4* kvT4 = (const float4*)g_kvT;

    #pragma unroll
    for (int i = 0; i < 16; i++) {
        int id = tid + i * 256, row = id >> 6, k4 = id & 63;
        uint32_t dst = smQ + (uint32_t)((row << 6) + (k4 & 56) + ((k4 ^ row) & 7)) * 16;
        CP16(dst, q4 + (size_t)row * 1024 + k4);
    }
    CP_COMMIT();
    #pragma unroll
    for (int i = 0; i < 16; i++) {
        int id = tid + i * 256, row = id >> 6, k4 = id & 63;
        uint32_t dst = smKV + (uint32_t)((row << 6) + (k4 & 56) + ((k4 ^ row) & 7)) * 16;
        CP16(dst, kv4 + (size_t)row * 64 + k4);
    }
    CP_COMMIT();
    #pragma unroll
    for (int i = 0; i < 16; i++) {
        int id = tid + i * 256, rd = id >> 4, k4 = id & 15;
        uint32_t dst = smKVT + (uint32_t)((rd << 4) + (k4 & 8) + ((k4 ^ rd) & 7)) * 16;
        CP16(dst, kvT4 + (size_t)rd * 512 + k4);
    }
    CP_COMMIT();

    // ---- fused q_post ----
    CP_WAIT2();
    __syncthreads();
    {
        int r = tid >> 2, qr = tid & 3;
        float ssq = 0.f;
        #pragma unroll
        for (int t = 0; t < 16; t++) {
            int k4 = qr * 16 + t;
            int fo = ((r << 6) + (k4 & 56) + ((k4 ^ r) & 7)) << 2;
            float4 v = *(float4*)(smf + fo);
            ssq += v.x * v.x + v.y * v.y + v.z * v.z + v.w * v.w;
        }
        ssq += __shfl_xor_sync(0xffffffffu, ssq, 1);
        ssq += __shfl_xor_sync(0xffffffffu, ssq, 2);
        float sc = rsqrtf(ssq / 256.f + EPS_);
        int sg = q0 + r;
        #pragma unroll
        for (int t = 0; t < 16; t++) {
            int k4 = qr * 16 + t;
            int fo = ((r << 6) + (k4 & 56) + ((k4 ^ r) & 7)) << 2;
            float4 v = *(float4*)(smf + fo);
            v.x *= sc; v.y *= sc; v.z *= sc; v.w *= sc;
            if (qr == 3) {
                int i0 = 2 * k4 - 96;
                float c0 = g_cos[sg * RH_ + i0],     s0 = g_sin[sg * RH_ + i0];
                float c1 = g_cos[sg * RH_ + i0 + 1], s1 = g_sin[sg * RH_ + i0 + 1];
                float nx = v.x * c0 - v.y * s0, ny = v.x * s0 + v.y * c0;
                float nz = v.z * c1 - v.w * s1, nw = v.z * s1 + v.w * c1;
                v = make_float4(nx, ny, nz, nw);
            }
            *(float4*)(smf + fo) = make_float4(f2tf_f(v.x), f2tf_f(v.y), f2tf_f(v.z), f2tf_f(v.w));
        }
    }
    __syncthreads();

    uint32_t aSb[2], bSb, aPb[2], bPVb[4];
    #pragma unroll
    for (int mt = 0; mt < 2; mt++) {
        int ar = wm * 32 + mt * 16 + jr + rr;
        aSb[mt] = smQ + (uint32_t)((ar << 6) + (jk ^ (ar & 7))) * 16;
        aPb[mt] = smP + (uint32_t)((ar << 4) + (jk ^ (ar & 7))) * 16;
    }
    {
        int br = wn * 16 + jr + rr;
        bSb = smKV + (uint32_t)((br << 6) + (jk ^ (br & 7))) * 16;
    }
    #pragma unroll
    for (int ntp = 0; ntp < 4; ntp++) {
        int br = wn * 64 + ntp * 16 + jr + rr;
        bPVb[ntp] = smKVT + (uint32_t)((br << 4) + (jk ^ (br & 7))) * 16;
    }

    float4 cO[2][8];
    #pragma unroll
    for (int mt = 0; mt < 2; mt++)
        #pragma unroll
        for (int nt = 0; nt < 8; nt++) cO[mt][nt] = make_float4(0.f, 0.f, 0.f, 0.f);
    float mrow[4] = {-3.0e38f, -3.0e38f, -3.0e38f, -3.0e38f};
    float lrow[4] = {0.f, 0.f, 0.f, 0.f};

    for (int j = 0; j < jn; j++) {
        CP_WAIT1();
        __syncthreads();

        float4 sS[2][2];
        #pragma unroll
        for (int mt = 0; mt < 2; mt++)
            #pragma unroll
            for (int nt = 0; nt < 2; nt++) sS[mt][nt] = make_float4(0.f, 0.f, 0.f, 0.f);

        #pragma unroll
        for (int cc = 0; cc < 8; cc++) {
            uint32_t ao = (uint32_t)cc * 128;
            #pragma unroll
            for (int ks = 0; ks < 4; ks++) {
                uint32_t af[2][4];
                #pragma unroll
                for (int mt = 0; mt < 2; mt++) ldsm4(af[mt], (aSb[mt] + ao) ^ (ks << 5));
                uint32_t tb[4];
                ldsm4(tb, (bSb + ao) ^ (ks << 5));
                uint32_t b0[2] = {tb[0], tb[2]}, b1[2] = {tb[1], tb[3]};
                #pragma unroll
                for (int mt = 0; mt < 2; mt++) {
                    mma_tf32(sS[mt][0], af[mt], b0);
                    mma_tf32(sS[mt][1], af[mt], b1);
                }
            }
        }

        #pragma unroll
        for (int mt = 0; mt < 2; mt++)
            #pragma unroll
            for (int nt = 0; nt < 2; nt++) {
                sS[mt][nt].x *= SCALE_; sS[mt][nt].y *= SCALE_;
                sS[mt][nt].z *= SCALE_; sS[mt][nt].w *= SCALE_;
            }
        if (j == qi) {
            #pragma unroll
            for (int mt = 0; mt < 2; mt++) {
                int r0 = wm * 32 + mt * 16 + g;
                #pragma unroll
                for (int nt = 0; nt < 2; nt++) {
                    int c0 = wn * 16 + nt * 8 + e2;
                    if (c0 > r0)     sS[mt][nt].x = -3.0e38f;
                    if (c0 + 1 > r0) sS[mt][nt].y = -3.0e38f;
                    if (c0 > r0 + 8)     sS[mt][nt].z = -3.0e38f;
                    if (c0 + 1 > r0 + 8) sS[mt][nt].w = -3.0e38f;
                }
            }
        }

        float rm[4];
        #pragma unroll
        for (int mt = 0; mt < 2; mt++) {
            rm[mt * 2 + 0] = fmaxf(fmaxf(sS[mt][0].x, sS[mt][0].y), fmaxf(sS[mt][1].x, sS[mt][1].y));
            rm[mt * 2 + 1] = fmaxf(fmaxf(sS[mt][0].z, sS[mt][0].w), fmaxf(sS[mt][1].z, sS[mt][1].w));
        }
        #pragma unroll
        for (int i = 0; i < 4; i++) {
            rm[i] = fmaxf(rm[i], __shfl_xor_sync(0xffffffffu, rm[i], 1));
            rm[i] = fmaxf(rm[i], __shfl_xor_sync(0xffffffffu, rm[i], 2));
        }

        float ls[4];
        #pragma unroll
        for (int mt = 0; mt < 2; mt++) {
            #pragma unroll
            for (int nt = 0; nt < 2; nt++) {
                sS[mt][nt].x = __expf(sS[mt][nt].x - rm[mt * 2 + 0]);
                sS[mt][nt].y = __expf(sS[mt][nt].y - rm[mt * 2 + 0]);
                sS[mt][nt].z = __expf(sS[mt][nt].z - rm[mt * 2 + 1]);
                sS[mt][nt].w = __expf(sS[mt][nt].w - rm[mt * 2 + 1]);
            }
            ls[mt * 2 + 0] = sS[mt][0].x + sS[mt][0].y + sS[mt][1].x + sS[mt][1].y;
            ls[mt * 2 + 1] = sS[mt][0].z + sS[mt][0].w + sS[mt][1].z + sS[mt][1].w;
        }
        #pragma unroll
        for (int i = 0; i < 4; i++) {
            ls[i] += __shfl_xor_sync(0xffffffffu, ls[i], 1);
            ls[i] += __shfl_xor_sync(0xffffffffu, ls[i], 2);
        }

        #pragma unroll
        for (int i = 0; i < 4; i++) {
            int row = wm * 32 + (i >> 1) * 16 + g + (i & 1) * 8;
            smf[F_RED + wn * 64 + row] = rm[i];
            smf[F_RED + 256 + wn * 64 + row] = ls[i];
        }
        __syncthreads();   // (A)

        if (j + 1 < jn) {
            const float4* kvs = kv4 + (size_t)(j + 1) * 64 * 64;
            #pragma unroll
            for (int i = 0; i < 16; i++) {
                int id = tid + i * 256, row = id >> 6, k4 = id & 63;
                uint32_t dst = smKV + (uint32_t)((row << 6) + (k4 & 56) + ((k4 ^ row) & 7)) * 16;
                CP16(dst, kvs + (size_t)row * 64 + k4);
            }
        }
        CP_COMMIT();

        float alpha[4], cf[4];
        #pragma unroll
        for (int i = 0; i < 4; i++) {
            int row = wm * 32 + (i >> 1) * 16 + g + (i & 1) * 8;
            float m0 = smf[F_RED + row],        m1 = smf[F_RED + 64 + row];
            float m2 = smf[F_RED + 128 + row],  m3 = smf[F_RED + 192 + row];
            float mnew = fmaxf(mrow[i], fmaxf(fmaxf(m0, m1), fmaxf(m2, m3)));
            alpha[i] = __expf(mrow[i] - mnew);
            float l0 = smf[F_RED + 256 + row],       l1 = smf[F_RED + 256 + 64 + row];
            float l2 = smf[F_RED + 256 + 128 + row], l3 = smf[F_RED + 256 + 192 + row];
            lrow[i] = lrow[i] * alpha[i] +
                      l0 * __expf(m0 - mnew) + l1 * __expf(m1 - mnew) +
                      l2 * __expf(m2 - mnew) + l3 * __expf(m3 - mnew);
            cf[i] = __expf(rm[i] - mnew);
            mrow[i] = mnew;
        }

        #pragma unroll
        for (int mt = 0; mt < 2; mt++)
            #pragma unroll
            for (int nt = 0; nt < 8; nt++) {
                cO[mt][nt].x *= alpha[mt * 2 + 0];
                cO[mt][nt].y *= alpha[mt * 2 + 0];
                cO[mt][nt].z *= alpha[mt * 2 + 1];
                cO[mt][nt].w *= alpha[mt * 2 + 1];
            }

        #pragma unroll
        for (int mt = 0; mt < 2; mt++)
            #pragma unroll
            for (int nt = 0; nt < 2; nt++) {
                int c = wn * 16 + nt * 8 + e2;
                int k4 = c >> 2;
                float cf0 = cf[mt * 2 + 0], cf1 = cf[mt * 2 + 1];
                {
                    int row = wm * 32 + mt * 16 + g;
                    int fi = F_P + (((row << 4) + (k4 & 8) + ((k4 ^ row) & 7)) << 2) + (c & 2);
                    *(float2*)(smf + fi) = make_float2(f2tf_f(sS[mt][nt].x * cf0),
                                                       f2tf_f(sS[mt][nt].y * cf0));
                }
                {
                    int row = wm * 32 + mt * 16 + g + 8;
                    int fi = F_P + (((row << 4) + (k4 & 8) + ((k4 ^ row) & 7)) << 2) + (c & 2);
                    *(float2*)(smf + fi) = make_float2(f2tf_f(sS[mt][nt].z * cf1),
                                                       f2tf_f(sS[mt][nt].w * cf1));
                }
            }

        CP_WAIT1();
        __syncthreads();   // (C)

        #pragma unroll
        for (int kk = 0; kk < 8; kk++) {
            uint32_t xo = (uint32_t)((kk & 3) << 5);
            uint32_t ad = (uint32_t)((kk >> 2) << 7);
            uint32_t af[2][4];
            #pragma unroll
            for (int mt = 0; mt < 2; mt++) ldsm4(af[mt], (aPb[mt] + ad) ^ xo);
            #pragma unroll
            for (int ntp = 0; ntp < 4; ntp++) {
                uint32_t tb[4];
                ldsm4(tb, (bPVb[ntp] + ad) ^ xo);
                uint32_t b0[2] = {tb[0], tb[2]}, b1[2] = {tb[1], tb[3]};
                #pragma unroll
                for (int mt = 0; mt < 2; mt++) {
                    mma_tf32(cO[mt][ntp * 2 + 0], af[mt], b0);
                    mma_tf32(cO[mt][ntp * 2 + 1], af[mt], b1);
                }
            }
        }
        __syncthreads();   // (D)

        if (j + 1 < jn) {
            const float4* kvts = kvT4 + (size_t)(j + 1) * 16;
            #pragma unroll
            for (int i = 0; i < 16; i++) {
                int id = tid + i * 256, rd = id >> 4, k4 = id & 15;
                uint32_t dst = smKVT + (uint32_t)((rd << 4) + (k4 & 8) + ((k4 ^ rd) & 7)) * 16;
                CP16(dst, kvts + (size_t)rd * 512 + k4);
            }
        }
        CP_COMMIT();
    }

    // ---- finalize: sink + normalize + fused inverse RoPE (wn==3) + tf32 round ----
    float snk = sink[h];
    float fac[4];
    #pragma unroll
    for (int i = 0; i < 4; i++) {
        float mf = fmaxf(mrow[i], snk);
        float af = __expf(mrow[i] - mf);
        float lf = lrow[i] * af + __expf(snk - mf);
        fac[i] = af / lf;
    }
    #pragma unroll
    for (int mt = 0; mt < 2; mt++) {
        int r = q0 + wm * 32 + mt * 16 + g;
        #pragma unroll
        for (int nt = 0; nt < 8; nt++) {
            int c = wn * 64 + nt * 8 + e2;
            float v0 = cO[mt][nt].x * fac[mt * 2 + 0];
            float v1 = cO[mt][nt].y * fac[mt * 2 + 0];
            float v2 = cO[mt][nt].z * fac[mt * 2 + 1];
            float v3 = cO[mt][nt].w * fac[mt * 2 + 1];
            if (wn == 3) {
                int i = (c & 63) >> 1;
                float c1 = g_cos[r * RH_ + i],       s1 = g_sin[r * RH_ + i];
                float c2 = g_cos[(r + 8) * RH_ + i], s2 = g_sin[(r + 8) * RH_ + i];
                float t0 = v0 * c1 + v1 * s1, t1 = v1 * c1 - v0 * s1;
                float t2 = v2 * c2 + v3 * s2, t3 = v3 * c2 - v2 * s2;
                v0 = t0; v1 = t1; v2 = t2; v3 = t3;
            }
            float* p0 = g_o + (size_t)r * (H_ * D_) + (size_t)h * D_ + c;
            *(float2*)p0 = make_float2(f2tf_f(v0), f2tf_f(v1));
            *(float2*)(p0 + (size_t)8 * (H_ * D_)) = make_float2(f2tf_f(v2), f2tf_f(v3));
        }
    }
}

// ---------------- launch ----------------
extern "C" void kernel_launch(void* const* d_in, const int* in_sizes, int n_in,
                              void* d_out, int out_size) {
    const float* x        = (const float*)d_in[0];
    const float* freqs    = (const float*)d_in[1];
    const float* wq_a     = (const float*)d_in[2];
    const float* q_norm_w = (const float*)d_in[3];
    const float* wq_b     = (const float*)d_in[4];
    const float* wkv      = (const float*)d_in[5];
    const float* kv_norm_w= (const float*)d_in[6];
    const float* wo_a_w   = (const float*)d_in[7];
    const float* wo_b     = (const float*)d_in[8];
    const float* sink     = (const float*)d_in[9];
    float* out = (float*)d_out;

    float *p_x, *p_wqa, *p_wqb, *p_wkv, *p_woa, *p_wob;
    float *p_qa, *p_q, *p_o, *p_or, *p_part, *p_part2;
    cudaGetSymbolAddress((void**)&p_x,   g_x);
    cudaGetSymbolAddress((void**)&p_wqa, g_wqa);
    cudaGetSymbolAddress((void**)&p_wqb, g_wqb);
    cudaGetSymbolAddress((void**)&p_wkv, g_wkv);
    cudaGetSymbolAddress((void**)&p_woa, g_woa);
    cudaGetSymbolAddress((void**)&p_wob, g_wob);
    cudaGetSymbolAddress((void**)&p_qa,  g_qa);
    cudaGetSymbolAddress((void**)&p_q,   g_q);
    cudaGetSymbolAddress((void**)&p_o,   g_o);
    cudaGetSymbolAddress((void**)&p_or,  g_or);
    cudaGetSymbolAddress((void**)&p_part, g_part);
    cudaGetSymbolAddress((void**)&p_part2, g_part2);

    cudaFuncSetAttribute(gemm_tn_tc, cudaFuncAttributeMaxDynamicSharedMemorySize, GEMM_SMEM);
    cudaFuncSetAttribute(gemm_dual,  cudaFuncAttributeMaxDynamicSharedMemorySize, GEMM_SMEM);
    cudaFuncSetAttribute(flash_attn, cudaFuncAttributeMaxDynamicSharedMemorySize, FLASH_SMEM);

    // prep: cos/sin + all tf32 pre-rounding in one launch
    prep_k<<<16960, 256>>>(freqs, x, wq_a, wkv, wq_b, wo_a_w, wo_b);

    // combined: qa = x@wqa^T (split-K x4, z 0..3) + kv = x@wkv^T (split-K x8, z 4..11)
    gemm_dual<<<dim3(QL_ / BN, S_ / BM, 12), 256, GEMM_SMEM>>>(
        p_x,
        p_wqa, p_part, 512, HID_, QL_, 512, 512, (long)S_ * QL_,
        p_wkv, p_part2, 256, HID_, D_, 256, 256, (long)S_ * D_,
        HID_, 4, D_ / BN);

    // merged qa-rms + kv-post(+transpose)
    reduce_post<<<dim3(S_, 2), 256>>>(p_part, q_norm_w, p_part2, kv_norm_w);

    // q = qa @ wq_b^T (raw fp32; flash normalizes/ropes/rounds in its prologue)
    gemm_tn_tc<<<dim3((H_ * D_) / BN, S_ / BM, 1), 256, GEMM_SMEM>>>(p_qa, p_wqb, p_q,
        QL_, QL_, QL_, H_ * D_, 0, 0, 0, 0);

    // fused attention (q_post + attention + o_post)
    flash_attn<<<512, 256, FLASH_SMEM>>>(sink);

    // grouped wo_a (tf32-rounded output in epilogue)
    gemm_tn_tc<<<dim3(OR_ / BN, S_ / BM, G_), 256, GEMM_SMEM>>>(p_o, p_woa, p_or,
        (H_ / G_) * D_, H_ * D_, (H_ / G_) * D_, G_ * OR_,
        (long)(H_ / G_) * D_, (long)OR_ * (H_ / G_) * D_, (long)OR_, 1);

    // out = o_r @ wo_b^T — split-K x2
    gemm_tn_tc<<<dim3(HID_ / BN, S_ / BM, 2), 256, GEMM_SMEM>>>(p_or, p_wob, p_part,
        1024, G_ * OR_, G_ * OR_, HID_, 1024, 1024, (long)S_ * HID_, 0);
    reduce_parts_k<<<(S_ * HID_ / 4 + 255) / 256, 256>>>(p_part, out,
        S_ * HID_ / 4, (long)S_ * HID_ / 4, 2);
}